// round 1
// baseline (speedup 1.0000x reference)
#include <cuda_runtime.h>

#define DIM 1024

// ---------------- scratch (static device globals; no allocation) ----------------
__device__ float g_B [DIM*DIM];   // B = (W - W^T)/2
__device__ float g_B2[DIM*DIM];   // B^2
__device__ float g_B3[DIM*DIM];   // B^3
__device__ float g_Cm[DIM*DIM];   // coefficient matrices / T
__device__ float g_P [DIM*DIM];   // PS intermediate
__device__ float g_R [DIM*DIM];   // rotation R = expm(A)

// ---------------- B = 0.5*(W - W^T) ----------------
__global__ void skew_half_kernel(const float* __restrict__ W, float* __restrict__ B) {
    int j = blockIdx.x * 32 + threadIdx.x;
    int i = blockIdx.y * 8  + threadIdx.y;
    B[i * DIM + j] = 0.5f * (W[i * DIM + j] - W[j * DIM + i]);
}

// ---------------- out = a*I + b*X + c*Y (elementwise) ----------------
__global__ void comb_kernel(float* __restrict__ out, const float* __restrict__ X,
                            const float* __restrict__ Y, float a, float b, float c) {
    int idx = blockIdx.x * 256 + threadIdx.x;
    int i = idx >> 10;          // / DIM
    int j = idx & (DIM - 1);    // % DIM
    float v = b * X[idx] + c * Y[idx];
    if (i == j) v += a;
    out[idx] = v;
}

// ---------------- tiled fp32 GEMM: C = A@B (+ D) ----------------
// Row-major A[M,K], B[K,N], C[M,N]. Dims must divide tile sizes (they do here).
template<int BM, int BN, int BK, int TM, int TN, bool HAS_D>
__global__ void gemm_kernel(const float* __restrict__ A, const float* __restrict__ Bm,
                            const float* __restrict__ D, float* __restrict__ C,
                            int M, int N, int K)
{
    constexpr int THREADS = (BM / TM) * (BN / TN);
    constexpr int BMP = BM + 4;                       // pad to soften store conflicts
    __shared__ __align__(16) float As[BK][BMP];
    __shared__ __align__(16) float Bs[BK][BN];

    const int tid  = threadIdx.x;
    const int row0 = blockIdx.y * BM;
    const int col0 = blockIdx.x * BN;
    const int tcol = tid % (BN / TN);
    const int trow = tid / (BN / TN);

    float acc[TM][TN];
    #pragma unroll
    for (int i = 0; i < TM; i++)
        #pragma unroll
        for (int j = 0; j < TN; j++) acc[i][j] = 0.f;

    constexpr int AVEC = (BM * BK / 4) / THREADS;     // float4 loads per thread (A tile)
    constexpr int BVEC = (BK * BN / 4) / THREADS;     // float4 loads per thread (B tile)

    for (int k0 = 0; k0 < K; k0 += BK) {
        // A tile: BM x BK, transpose into As[k][row]
        #pragma unroll
        for (int v = 0; v < AVEC; v++) {
            int vid = tid + v * THREADS;
            int r   = vid / (BK / 4);
            int kq  = vid % (BK / 4);
            float4 t = *reinterpret_cast<const float4*>(&A[(size_t)(row0 + r) * K + k0 + kq * 4]);
            As[kq * 4 + 0][r] = t.x;
            As[kq * 4 + 1][r] = t.y;
            As[kq * 4 + 2][r] = t.z;
            As[kq * 4 + 3][r] = t.w;
        }
        // B tile: BK x BN, direct float4
        #pragma unroll
        for (int v = 0; v < BVEC; v++) {
            int vid = tid + v * THREADS;
            int r   = vid / (BN / 4);
            int cq  = vid % (BN / 4);
            *reinterpret_cast<float4*>(&Bs[r][cq * 4]) =
                *reinterpret_cast<const float4*>(&Bm[(size_t)(k0 + r) * N + col0 + cq * 4]);
        }
        __syncthreads();

        #pragma unroll
        for (int k = 0; k < BK; k++) {
            float ra[TM], rb[TN];
            #pragma unroll
            for (int i = 0; i < TM; i += 4) {
                float4 t = *reinterpret_cast<const float4*>(&As[k][trow * TM + i]);
                ra[i] = t.x; ra[i+1] = t.y; ra[i+2] = t.z; ra[i+3] = t.w;
            }
            #pragma unroll
            for (int j = 0; j < TN; j += 4) {
                float4 t = *reinterpret_cast<const float4*>(&Bs[k][tcol * TN + j]);
                rb[j] = t.x; rb[j+1] = t.y; rb[j+2] = t.z; rb[j+3] = t.w;
            }
            #pragma unroll
            for (int i = 0; i < TM; i++)
                #pragma unroll
                for (int j = 0; j < TN; j++)
                    acc[i][j] += ra[i] * rb[j];
        }
        __syncthreads();
    }

    // epilogue (float4 stores; optional bias matrix D)
    #pragma unroll
    for (int i = 0; i < TM; i++) {
        size_t r = row0 + trow * TM + i;
        #pragma unroll
        for (int j = 0; j < TN; j += 4) {
            size_t c = col0 + tcol * TN + j;
            float4 v;
            v.x = acc[i][j]; v.y = acc[i][j+1]; v.z = acc[i][j+2]; v.w = acc[i][j+3];
            if (HAS_D) {
                float4 d = *reinterpret_cast<const float4*>(&D[r * N + c]);
                v.x += d.x; v.y += d.y; v.z += d.z; v.w += d.w;
            }
            *reinterpret_cast<float4*>(&C[r * N + c]) = v;
        }
    }
}

extern "C" void kernel_launch(void* const* d_in, const int* in_sizes, int n_in,
                              void* d_out, int out_size)
{
    const float* x = (const float*)d_in[0];        // [4*4096, 1024]
    const float* W = (const float*)d_in[1];        // [1024, 1024]
    float* out = (float*)d_out;
    const int M = in_sizes[0] / DIM;               // 16384

    float *B, *B2, *B3, *Cm, *P, *R;
    cudaGetSymbolAddress((void**)&B,  g_B);
    cudaGetSymbolAddress((void**)&B2, g_B2);
    cudaGetSymbolAddress((void**)&B3, g_B3);
    cudaGetSymbolAddress((void**)&Cm, g_Cm);
    cudaGetSymbolAddress((void**)&P,  g_P);
    cudaGetSymbolAddress((void**)&R,  g_R);

    // 1) B = (W - W^T) / 2      (scaling s=1 folded in)
    skew_half_kernel<<<dim3(DIM / 32, DIM / 8), dim3(32, 8)>>>(W, B);

    const dim3 g64(DIM / 64, DIM / 64);
    const int  cb = DIM * DIM / 256;

    // 2) B2 = B@B ; B3 = B2@B
    gemm_kernel<64, 64, 16, 4, 4, false><<<g64, 256>>>(B,  B, nullptr, B2, DIM, DIM, DIM);
    gemm_kernel<64, 64, 16, 4, 4, false><<<g64, 256>>>(B2, B, nullptr, B3, DIM, DIM, DIM);

    // 3) Paterson–Stockmeyer degree-8 Taylor of expm(B):
    //    T = (c6 I + c7 B + c8 B2)·B3·B3 + (c3 I + c4 B + c5 B2)·B3 + (I + B + B2/2)
    comb_kernel<<<cb, 256>>>(Cm, B, B2, 1.f/720.f, 1.f/5040.f, 1.f/40320.f);  // Cm = C2
    comb_kernel<<<cb, 256>>>(R,  B, B2, 1.f/6.f,   1.f/24.f,   1.f/120.f);    // R  = C1
    gemm_kernel<64, 64, 16, 4, 4, true ><<<g64, 256>>>(Cm, B3, R, P, DIM, DIM, DIM);   // P = C2@B3 + C1
    comb_kernel<<<cb, 256>>>(Cm, B, B2, 1.f,       1.f,        0.5f);         // Cm = C0
    gemm_kernel<64, 64, 16, 4, 4, true ><<<g64, 256>>>(P, B3, Cm, B, DIM, DIM, DIM);   // B = T = P@B3 + C0

    // 4) undo scaling: R = T@T = expm(2B) = expm(A)
    gemm_kernel<64, 64, 16, 4, 4, false><<<g64, 256>>>(B, B, nullptr, R, DIM, DIM, DIM);

    // 5) out = x @ R   (M=16384, N=K=1024)
    gemm_kernel<128, 128, 16, 8, 8, false><<<dim3(DIM / 128, M / 128), 256>>>(
        x, R, nullptr, out, M, DIM, DIM);
}

// round 4
// speedup vs baseline: 2.4189x; 2.4189x over previous
#include <cuda_runtime.h>
#include <cuda_bf16.h>
#include <cstdint>

typedef __nv_bfloat16 bf16;
#define DIM 1024
#define XROWS 16384

// ---------------- scratch (static device globals; no allocation) ----------------
__device__ float g_B [DIM*DIM];
__device__ float g_B2[DIM*DIM];
__device__ float g_B3[DIM*DIM];
__device__ float g_Cm[DIM*DIM];
__device__ float g_P [DIM*DIM];
__device__ float g_R [DIM*DIM];

__device__ bf16 s_Bh [DIM*DIM], s_Bl [DIM*DIM];
__device__ bf16 s_B2h[DIM*DIM], s_B2l[DIM*DIM];
__device__ bf16 s_B3h[DIM*DIM], s_B3l[DIM*DIM];
__device__ bf16 s_Ch [DIM*DIM], s_Cl [DIM*DIM];
__device__ bf16 s_Rh [DIM*DIM], s_Rl [DIM*DIM];
__device__ bf16 g_xh [XROWS*DIM], g_xl [XROWS*DIM];

// ---------------- B = 0.5*(W - W^T) ----------------
__global__ void skew_half_kernel(const float* __restrict__ W, float* __restrict__ B) {
    int j = blockIdx.x * 32 + threadIdx.x;
    int i = blockIdx.y * 8  + threadIdx.y;
    B[i * DIM + j] = 0.5f * (W[i * DIM + j] - W[j * DIM + i]);
}

// ---------------- out = a*I + b*X + c*Y ----------------
__global__ void comb_kernel(float* __restrict__ out, const float* __restrict__ X,
                            const float* __restrict__ Y, float a, float b, float c) {
    int idx = blockIdx.x * 256 + threadIdx.x;
    int i = idx >> 10;
    int j = idx & (DIM - 1);
    float v = b * X[idx] + c * Y[idx];
    if (i == j) v += a;
    out[idx] = v;
}

// ---------------- split fp32 -> bf16 hi + bf16 lo (4 elems/thread) ----------------
__global__ void split_kernel(const float* __restrict__ in, bf16* __restrict__ hi,
                             bf16* __restrict__ lo) {
    int i = blockIdx.x * 256 + threadIdx.x;
    float4 v = reinterpret_cast<const float4*>(in)[i];
    float f[4] = {v.x, v.y, v.z, v.w};
    union { bf16 b[4]; uint2 u; } H, L;
    #pragma unroll
    for (int j = 0; j < 4; j++) {
        bf16 h = __float2bfloat16(f[j]);
        H.b[j] = h;
        L.b[j] = __float2bfloat16(f[j] - __bfloat162float(h));
    }
    reinterpret_cast<uint2*>(hi)[i] = H.u;
    reinterpret_cast<uint2*>(lo)[i] = L.u;
}

// ---------------- helpers ----------------
__device__ __forceinline__ void cp16(void* dst, const void* src) {
    unsigned d = (unsigned)__cvta_generic_to_shared(dst);
    asm volatile("cp.async.cg.shared.global [%0], [%1], 16;" :: "r"(d), "l"(src));
}
__device__ __forceinline__ void cp_commit() { asm volatile("cp.async.commit_group;"); }
__device__ __forceinline__ void cp_wait_all() { asm volatile("cp.async.wait_group 0;"); }

__device__ __forceinline__ void ldsm_x4(uint32_t a[4], const bf16* p) {
    unsigned s = (unsigned)__cvta_generic_to_shared(p);
    asm volatile("ldmatrix.sync.aligned.m8n8.x4.shared.b16 {%0,%1,%2,%3}, [%4];"
                 : "=r"(a[0]), "=r"(a[1]), "=r"(a[2]), "=r"(a[3]) : "r"(s));
}
__device__ __forceinline__ void ldsm_x2t(uint32_t b[2], const bf16* p) {
    unsigned s = (unsigned)__cvta_generic_to_shared(p);
    asm volatile("ldmatrix.sync.aligned.m8n8.x2.trans.shared.b16 {%0,%1}, [%2];"
                 : "=r"(b[0]), "=r"(b[1]) : "r"(s));
}
__device__ __forceinline__ void mma_bf16(float d[4], const uint32_t a[4], const uint32_t b[2]) {
    asm volatile("mma.sync.aligned.m16n8k16.row.col.f32.bf16.bf16.f32 "
                 "{%0,%1,%2,%3}, {%4,%5,%6,%7}, {%8,%9}, {%0,%1,%2,%3};"
                 : "+f"(d[0]), "+f"(d[1]), "+f"(d[2]), "+f"(d[3])
                 : "r"(a[0]), "r"(a[1]), "r"(a[2]), "r"(a[3]), "r"(b[0]), "r"(b[1]));
}

// ---------------- split-bf16 tensor-core GEMM ----------------
// C[M,N] = (Ah+Al)@(Bh+Bl) (+D), dropping Al@Bl.  Row-major, dims divide tiles.
template<int BM, int BN, int WM, int WN, int THREADS, bool HAS_D>
__global__ __launch_bounds__(THREADS)
void mma_gemm(const bf16* __restrict__ Ah, const bf16* __restrict__ Al,
              const bf16* __restrict__ Bh, const bf16* __restrict__ Bl,
              const float* __restrict__ D, float* __restrict__ C,
              int M, int N, int K)
{
    constexpr int BK = 32;
    constexpr int AP = BK + 8;     // A row pitch (bf16): 80B -> LDSM conflict-free
    constexpr int BP = BN + 8;     // B row pitch: (BN+8)*2B, %128B = 16 -> conflict-free
    constexpr int ASZ = BM * AP;
    constexpr int BSZ = BK * BP;
    constexpr int MI = WM / 16, NI = WN / 8;
    constexpr int WNC = BN / WN;
    constexpr int AC = (BM * BK / 8) / THREADS;
    constexpr int BC = (BK * BN / 8) / THREADS;

    extern __shared__ bf16 smem[];
    bf16* sA = smem;               // [stage][split][BM][AP]
    bf16* sB = smem + 4 * ASZ;     // [stage][split][BK][BP]

    const int tid = threadIdx.x, lane = tid & 31, wid = tid >> 5;
    const int wm = wid / WNC, wn = wid % WNC;
    const int row0 = blockIdx.y * BM, col0 = blockIdx.x * BN;

    float acc[MI][NI][4];
    #pragma unroll
    for (int mi = 0; mi < MI; mi++)
        #pragma unroll
        for (int ni = 0; ni < NI; ni++)
            #pragma unroll
            for (int r = 0; r < 4; r++) acc[mi][ni][r] = 0.f;

    auto load_stage = [&](int st, int k0) {
        #pragma unroll
        for (int s = 0; s < 2; s++) {
            const bf16* gA = s ? Al : Ah;
            #pragma unroll
            for (int i = 0; i < AC; i++) {
                int c = tid + i * THREADS;
                int r = c / (BK / 8), cc = c % (BK / 8);
                cp16(&sA[(st * 2 + s) * ASZ + r * AP + cc * 8],
                     gA + (size_t)(row0 + r) * K + k0 + cc * 8);
            }
            const bf16* gB = s ? Bl : Bh;
            #pragma unroll
            for (int i = 0; i < BC; i++) {
                int c = tid + i * THREADS;
                int r = c / (BN / 8), cc = c % (BN / 8);
                cp16(&sB[(st * 2 + s) * BSZ + r * BP + cc * 8],
                     gB + (size_t)(k0 + r) * N + col0 + cc * 8);
            }
        }
        cp_commit();
    };

    load_stage(0, 0);
    int st = 0;
    const int NITER = K / BK;

    for (int it = 0; it < NITER; it++) {
        cp_wait_all();
        __syncthreads();
        if (it + 1 < NITER) load_stage(st ^ 1, (it + 1) * BK);

        const bf16* Ahs = &sA[(st * 2 + 0) * ASZ];
        const bf16* Als = &sA[(st * 2 + 1) * ASZ];
        const bf16* Bhs = &sB[(st * 2 + 0) * BSZ];
        const bf16* Bls = &sB[(st * 2 + 1) * BSZ];

        #pragma unroll
        for (int ks = 0; ks < 2; ks++) {
            const int k0 = ks * 16;
            uint32_t ah[MI][4], al[MI][4], bh[NI][2], bl[NI][2];
            #pragma unroll
            for (int mi = 0; mi < MI; mi++) {
                int r = wm * WM + mi * 16 + (lane & 15);
                int c = k0 + (lane >> 4) * 8;
                ldsm_x4(ah[mi], Ahs + r * AP + c);
                ldsm_x4(al[mi], Als + r * AP + c);
            }
            #pragma unroll
            for (int ni = 0; ni < NI; ni++) {
                int r = k0 + (lane & 15);
                int c = wn * WN + ni * 8;
                ldsm_x2t(bh[ni], Bhs + r * BP + c);
                ldsm_x2t(bl[ni], Bls + r * BP + c);
            }
            #pragma unroll
            for (int mi = 0; mi < MI; mi++)
                #pragma unroll
                for (int ni = 0; ni < NI; ni++) {
                    mma_bf16(acc[mi][ni], ah[mi], bh[ni]);
                    mma_bf16(acc[mi][ni], ah[mi], bl[ni]);
                    mma_bf16(acc[mi][ni], al[mi], bh[ni]);
                }
        }
        st ^= 1;
    }

    // epilogue
    #pragma unroll
    for (int mi = 0; mi < MI; mi++)
        #pragma unroll
        for (int ni = 0; ni < NI; ni++) {
            int r = row0 + wm * WM + mi * 16 + lane / 4;
            int c = col0 + wn * WN + ni * 8 + 2 * (lane % 4);
            float2 v0 = make_float2(acc[mi][ni][0], acc[mi][ni][1]);
            float2 v1 = make_float2(acc[mi][ni][2], acc[mi][ni][3]);
            if (HAS_D) {
                float2 d0 = *reinterpret_cast<const float2*>(&D[(size_t)r * N + c]);
                float2 d1 = *reinterpret_cast<const float2*>(&D[(size_t)(r + 8) * N + c]);
                v0.x += d0.x; v0.y += d0.y; v1.x += d1.x; v1.y += d1.y;
            }
            *reinterpret_cast<float2*>(&C[(size_t)r * N + c]) = v0;
            *reinterpret_cast<float2*>(&C[(size_t)(r + 8) * N + c]) = v1;
        }
}

// ---------------- launch ----------------
extern "C" void kernel_launch(void* const* d_in, const int* in_sizes, int n_in,
                              void* d_out, int out_size)
{
    const float* x = (const float*)d_in[0];
    const float* W = (const float*)d_in[1];
    float* out = (float*)d_out;
    const int M = in_sizes[0] / DIM;   // 16384

    float *B, *B2, *B3, *Cm, *P, *R;
    cudaGetSymbolAddress((void**)&B,  g_B);
    cudaGetSymbolAddress((void**)&B2, g_B2);
    cudaGetSymbolAddress((void**)&B3, g_B3);
    cudaGetSymbolAddress((void**)&Cm, g_Cm);
    cudaGetSymbolAddress((void**)&P,  g_P);
    cudaGetSymbolAddress((void**)&R,  g_R);
    bf16 *Bh, *Bl, *B2h, *B2l, *B3h, *B3l, *Ch, *Cl, *Rh, *Rl, *xh, *xl;
    cudaGetSymbolAddress((void**)&Bh,  s_Bh);  cudaGetSymbolAddress((void**)&Bl,  s_Bl);
    cudaGetSymbolAddress((void**)&B2h, s_B2h); cudaGetSymbolAddress((void**)&B2l, s_B2l);
    cudaGetSymbolAddress((void**)&B3h, s_B3h); cudaGetSymbolAddress((void**)&B3l, s_B3l);
    cudaGetSymbolAddress((void**)&Ch,  s_Ch);  cudaGetSymbolAddress((void**)&Cl,  s_Cl);
    cudaGetSymbolAddress((void**)&Rh,  s_Rh);  cudaGetSymbolAddress((void**)&Rl,  s_Rl);
    cudaGetSymbolAddress((void**)&xh,  g_xh);  cudaGetSymbolAddress((void**)&xl,  g_xl);

    constexpr int SMEM_MAIN  = (4 * 128 * 40 + 4 * 32 * 136) * 2;  // 75776
    constexpr int SMEM_SMALL = (4 * 64 * 40 + 4 * 32 * 72) * 2;    // 38912
    cudaFuncSetAttribute(mma_gemm<128,128,64,32,256,false>,
                         cudaFuncAttributeMaxDynamicSharedMemorySize, SMEM_MAIN);
    cudaFuncSetAttribute(mma_gemm<64,64,32,32,128,false>,
                         cudaFuncAttributeMaxDynamicSharedMemorySize, SMEM_SMALL);
    cudaFuncSetAttribute(mma_gemm<64,64,32,32,128,true>,
                         cudaFuncAttributeMaxDynamicSharedMemorySize, SMEM_SMALL);

    const dim3 g64(DIM / 64, DIM / 64);
    const int  cb  = DIM * DIM / 256;        // comb blocks
    const int  sb1 = DIM * DIM / 1024;       // split blocks (1024 elems/block)
    const int  sbx = M * DIM / 1024;

    // split x early (independent of expm chain)
    split_kernel<<<sbx, 256>>>(x, xh, xl);

    // 1) B = (W - W^T)/2 ; split
    skew_half_kernel<<<dim3(DIM / 32, DIM / 8), dim3(32, 8)>>>(W, B);
    split_kernel<<<sb1, 256>>>(B, Bh, Bl);

    // 2) B2 = B@B ; B3 = B2@B
    mma_gemm<64,64,32,32,128,false><<<g64, 128, SMEM_SMALL>>>(Bh, Bl, Bh, Bl, nullptr, B2, DIM, DIM, DIM);
    split_kernel<<<sb1, 256>>>(B2, B2h, B2l);
    mma_gemm<64,64,32,32,128,false><<<g64, 128, SMEM_SMALL>>>(B2h, B2l, Bh, Bl, nullptr, B3, DIM, DIM, DIM);
    split_kernel<<<sb1, 256>>>(B3, B3h, B3l);

    // 3) Paterson–Stockmeyer degree-8 Taylor
    comb_kernel<<<cb, 256>>>(Cm, B, B2, 1.f/720.f, 1.f/5040.f, 1.f/40320.f);  // C2
    split_kernel<<<sb1, 256>>>(Cm, Ch, Cl);
    comb_kernel<<<cb, 256>>>(R, B, B2, 1.f/6.f, 1.f/24.f, 1.f/120.f);         // C1 (D)
    mma_gemm<64,64,32,32,128,true><<<g64, 128, SMEM_SMALL>>>(Ch, Cl, B3h, B3l, R, P, DIM, DIM, DIM);
    split_kernel<<<sb1, 256>>>(P, Ch, Cl);
    comb_kernel<<<cb, 256>>>(Cm, B, B2, 1.f, 1.f, 0.5f);                      // C0 (D)
    mma_gemm<64,64,32,32,128,true><<<g64, 128, SMEM_SMALL>>>(Ch, Cl, B3h, B3l, Cm, B, DIM, DIM, DIM); // T
    split_kernel<<<sb1, 256>>>(B, Ch, Cl);

    // 4) R = T@T ; split
    mma_gemm<64,64,32,32,128,false><<<g64, 128, SMEM_SMALL>>>(Ch, Cl, Ch, Cl, nullptr, R, DIM, DIM, DIM);
    split_kernel<<<sb1, 256>>>(R, Rh, Rl);

    // 5) out = x @ R
    mma_gemm<128,128,64,32,256,false><<<dim3(DIM / 128, M / 128), 256, SMEM_MAIN>>>(
        xh, xl, Rh, Rl, nullptr, out, M, DIM, DIM);
}

// round 5
// speedup vs baseline: 2.7675x; 1.1441x over previous
#include <cuda_runtime.h>
#include <cuda_bf16.h>
#include <cstdint>

typedef __nv_bfloat16 bf16;
#define DIM 1024
#define XROWS 16384
#define SPLITK 4

// ---------------- scratch (static device globals; no allocation) ----------------
__device__ float g_B   [DIM*DIM];
__device__ float g_B2  [DIM*DIM];
__device__ float g_part[SPLITK*DIM*DIM];

__device__ bf16 s_Bh [DIM*DIM], s_Bl [DIM*DIM];
__device__ bf16 s_B2h[DIM*DIM], s_B2l[DIM*DIM];
__device__ bf16 s_B3h[DIM*DIM], s_B3l[DIM*DIM];
__device__ bf16 s_Ch [DIM*DIM], s_Cl [DIM*DIM];
__device__ bf16 s_Ph [DIM*DIM], s_Pl [DIM*DIM];
__device__ bf16 s_Th [DIM*DIM], s_Tl [DIM*DIM];
__device__ bf16 s_Rh [DIM*DIM], s_Rl [DIM*DIM];
__device__ bf16 g_xh [XROWS*DIM], g_xl [XROWS*DIM];

// ---------------- fused skew + split: B = 0.5(W - W^T) -> fp32 + hi/lo ----------------
__global__ void skew_split_kernel(const float* __restrict__ W, float* __restrict__ B,
                                  bf16* __restrict__ hi, bf16* __restrict__ lo) {
    int j = blockIdx.x * 32 + threadIdx.x;
    int i = blockIdx.y * 8  + threadIdx.y;
    float v = 0.5f * (W[i * DIM + j] - W[j * DIM + i]);
    B[i * DIM + j] = v;
    bf16 h = __float2bfloat16(v);
    hi[i * DIM + j] = h;
    lo[i * DIM + j] = __float2bfloat16(v - __bfloat162float(h));
}

// ---------------- split fp32 -> bf16 hi + lo (float4 per thread) ----------------
__global__ void split_kernel(const float* __restrict__ in, bf16* __restrict__ hi,
                             bf16* __restrict__ lo) {
    int i = blockIdx.x * 256 + threadIdx.x;
    float4 v = reinterpret_cast<const float4*>(in)[i];
    float f[4] = {v.x, v.y, v.z, v.w};
    union { bf16 b[4]; uint2 u; } H, L;
    #pragma unroll
    for (int j = 0; j < 4; j++) {
        bf16 h = __float2bfloat16(f[j]);
        H.b[j] = h;
        L.b[j] = __float2bfloat16(f[j] - __bfloat162float(h));
    }
    reinterpret_cast<uint2*>(hi)[i] = H.u;
    reinterpret_cast<uint2*>(lo)[i] = L.u;
}

// ---------------- fused reduce(+comb)(+split) ----------------
// v = sum_{p<NPART} part[p] (+ a*I + b*Bm + c*B2m if COMB); write split(v), opt fp32.
template<int NPART, bool COMB, bool WF32>
__global__ void reduce_split(const float* __restrict__ part, float* __restrict__ f32out,
                             bf16* __restrict__ hi, bf16* __restrict__ lo,
                             const float* __restrict__ Bm, const float* __restrict__ B2m,
                             float a, float b, float c)
{
    constexpr int SZ4 = DIM * DIM / 4;
    int i = blockIdx.x * 256 + threadIdx.x;       // float4 index
    float f[4] = {0.f, 0.f, 0.f, 0.f};
    #pragma unroll
    for (int p = 0; p < NPART; p++) {
        float4 t = reinterpret_cast<const float4*>(part)[p * SZ4 + i];
        f[0] += t.x; f[1] += t.y; f[2] += t.z; f[3] += t.w;
    }
    if (COMB) {
        float4 bm = reinterpret_cast<const float4*>(Bm)[i];
        float4 b2 = reinterpret_cast<const float4*>(B2m)[i];
        f[0] += b * bm.x + c * b2.x;
        f[1] += b * bm.y + c * b2.y;
        f[2] += b * bm.z + c * b2.z;
        f[3] += b * bm.w + c * b2.w;
        int e0 = i * 4;
        int d = (e0 >> 10) - (e0 & (DIM - 1));    // row - col0
        if (d >= 0 && d < 4) f[d] += a;
    }
    if (WF32) {
        float4 o; o.x = f[0]; o.y = f[1]; o.z = f[2]; o.w = f[3];
        reinterpret_cast<float4*>(f32out)[i] = o;
    }
    union { bf16 b[4]; uint2 u; } H, L;
    #pragma unroll
    for (int j = 0; j < 4; j++) {
        bf16 h = __float2bfloat16(f[j]);
        H.b[j] = h;
        L.b[j] = __float2bfloat16(f[j] - __bfloat162float(h));
    }
    reinterpret_cast<uint2*>(hi)[i] = H.u;
    reinterpret_cast<uint2*>(lo)[i] = L.u;
}

// ---------------- async-copy / mma helpers ----------------
__device__ __forceinline__ void cp16(void* dst, const void* src) {
    unsigned d = (unsigned)__cvta_generic_to_shared(dst);
    asm volatile("cp.async.cg.shared.global [%0], [%1], 16;" :: "r"(d), "l"(src));
}
__device__ __forceinline__ void cp_commit() { asm volatile("cp.async.commit_group;"); }
template<int N>
__device__ __forceinline__ void cp_wait() { asm volatile("cp.async.wait_group %0;" :: "n"(N)); }

__device__ __forceinline__ void ldsm_x4(uint32_t a[4], const bf16* p) {
    unsigned s = (unsigned)__cvta_generic_to_shared(p);
    asm volatile("ldmatrix.sync.aligned.m8n8.x4.shared.b16 {%0,%1,%2,%3}, [%4];"
                 : "=r"(a[0]), "=r"(a[1]), "=r"(a[2]), "=r"(a[3]) : "r"(s));
}
__device__ __forceinline__ void ldsm_x2t(uint32_t b[2], const bf16* p) {
    unsigned s = (unsigned)__cvta_generic_to_shared(p);
    asm volatile("ldmatrix.sync.aligned.m8n8.x2.trans.shared.b16 {%0,%1}, [%2];"
                 : "=r"(b[0]), "=r"(b[1]) : "r"(s));
}
__device__ __forceinline__ void mma_bf16(float d[4], const uint32_t a[4], const uint32_t b[2]) {
    asm volatile("mma.sync.aligned.m16n8k16.row.col.f32.bf16.bf16.f32 "
                 "{%0,%1,%2,%3}, {%4,%5,%6,%7}, {%8,%9}, {%0,%1,%2,%3};"
                 : "+f"(d[0]), "+f"(d[1]), "+f"(d[2]), "+f"(d[3])
                 : "r"(a[0]), "r"(a[1]), "r"(a[2]), "r"(a[3]), "r"(b[0]), "r"(b[1]));
}

// ---------------- split-bf16 tensor-core GEMM (multi-stage, optional split-K) ----------------
// C[M,N] (+ blockIdx.z * M*N) = partial over K-chunk of (Ah+Al)@(Bh+Bl), dropping Al@Bl.
template<int BM, int BN, int WM, int WN, int THREADS, int STAGES>
__global__ __launch_bounds__(THREADS)
void mma_gemm(const bf16* __restrict__ Ah, const bf16* __restrict__ Al,
              const bf16* __restrict__ Bh, const bf16* __restrict__ Bl,
              float* __restrict__ C, int M, int N, int K)
{
    constexpr int BK = 32;
    constexpr int AP = BK + 8;
    constexpr int BP = BN + 8;
    constexpr int ASZ = BM * AP;
    constexpr int BSZ = BK * BP;
    constexpr int MI = WM / 16, NI = WN / 8;
    constexpr int WNC = BN / WN;
    constexpr int AC = (BM * BK / 8) / THREADS;
    constexpr int BC = (BK * BN / 8) / THREADS;

    extern __shared__ bf16 smem[];
    bf16* sA = smem;                         // [stage][split][BM][AP]
    bf16* sB = smem + STAGES * 2 * ASZ;      // [stage][split][BK][BP]

    const int tid = threadIdx.x, lane = tid & 31, wid = tid >> 5;
    const int wm = wid / WNC, wn = wid % WNC;
    const int row0 = blockIdx.y * BM, col0 = blockIdx.x * BN;

    const int kchunk = K / gridDim.z;
    const int kbeg   = blockIdx.z * kchunk;
    const int NITER  = kchunk / BK;
    C += (size_t)blockIdx.z * (size_t)M * N;

    float acc[MI][NI][4];
    #pragma unroll
    for (int mi = 0; mi < MI; mi++)
        #pragma unroll
        for (int ni = 0; ni < NI; ni++)
            #pragma unroll
            for (int r = 0; r < 4; r++) acc[mi][ni][r] = 0.f;

    auto load_stage = [&](int st, int iter) {
        if (iter < NITER) {
            int k0 = kbeg + iter * BK;
            #pragma unroll
            for (int s = 0; s < 2; s++) {
                const bf16* gA = s ? Al : Ah;
                #pragma unroll
                for (int i = 0; i < AC; i++) {
                    int c = tid + i * THREADS;
                    int r = c / (BK / 8), cc = c % (BK / 8);
                    cp16(&sA[(st * 2 + s) * ASZ + r * AP + cc * 8],
                         gA + (size_t)(row0 + r) * K + k0 + cc * 8);
                }
                const bf16* gB = s ? Bl : Bh;
                #pragma unroll
                for (int i = 0; i < BC; i++) {
                    int c = tid + i * THREADS;
                    int r = c / (BN / 8), cc = c % (BN / 8);
                    cp16(&sB[(st * 2 + s) * BSZ + r * BP + cc * 8],
                         gB + (size_t)(k0 + r) * N + col0 + cc * 8);
                }
            }
        }
        cp_commit();   // commit even when empty (keeps group accounting exact at the tail)
    };

    #pragma unroll
    for (int s = 0; s < STAGES - 1; s++) load_stage(s, s);

    for (int it = 0; it < NITER; it++) {
        cp_wait<STAGES - 2>();
        __syncthreads();
        load_stage((it + STAGES - 1) % STAGES, it + STAGES - 1);

        const int st = it % STAGES;
        const bf16* Ahs = &sA[(st * 2 + 0) * ASZ];
        const bf16* Als = &sA[(st * 2 + 1) * ASZ];
        const bf16* Bhs = &sB[(st * 2 + 0) * BSZ];
        const bf16* Bls = &sB[(st * 2 + 1) * BSZ];

        #pragma unroll
        for (int ks = 0; ks < 2; ks++) {
            const int k0 = ks * 16;
            uint32_t ah[MI][4], al[MI][4], bh[NI][2], bl[NI][2];
            #pragma unroll
            for (int mi = 0; mi < MI; mi++) {
                int r = wm * WM + mi * 16 + (lane & 15);
                int c = k0 + (lane >> 4) * 8;
                ldsm_x4(ah[mi], Ahs + r * AP + c);
                ldsm_x4(al[mi], Als + r * AP + c);
            }
            #pragma unroll
            for (int ni = 0; ni < NI; ni++) {
                int r = k0 + (lane & 15);
                int c = wn * WN + ni * 8;
                ldsm_x2t(bh[ni], Bhs + r * BP + c);
                ldsm_x2t(bl[ni], Bls + r * BP + c);
            }
            #pragma unroll
            for (int mi = 0; mi < MI; mi++)
                #pragma unroll
                for (int ni = 0; ni < NI; ni++) {
                    mma_bf16(acc[mi][ni], ah[mi], bh[ni]);
                    mma_bf16(acc[mi][ni], ah[mi], bl[ni]);
                    mma_bf16(acc[mi][ni], al[mi], bh[ni]);
                }
        }
    }

    #pragma unroll
    for (int mi = 0; mi < MI; mi++)
        #pragma unroll
        for (int ni = 0; ni < NI; ni++) {
            int r = row0 + wm * WM + mi * 16 + lane / 4;
            int c = col0 + wn * WN + ni * 8 + 2 * (lane % 4);
            *reinterpret_cast<float2*>(&C[(size_t)r * N + c]) =
                make_float2(acc[mi][ni][0], acc[mi][ni][1]);
            *reinterpret_cast<float2*>(&C[(size_t)(r + 8) * N + c]) =
                make_float2(acc[mi][ni][2], acc[mi][ni][3]);
        }
}

// ---------------- launch ----------------
extern "C" void kernel_launch(void* const* d_in, const int* in_sizes, int n_in,
                              void* d_out, int out_size)
{
    const float* x = (const float*)d_in[0];
    const float* W = (const float*)d_in[1];
    float* out = (float*)d_out;
    const int M = in_sizes[0] / DIM;   // 16384

    float *B, *B2, *Pt;
    cudaGetSymbolAddress((void**)&B,  g_B);
    cudaGetSymbolAddress((void**)&B2, g_B2);
    cudaGetSymbolAddress((void**)&Pt, g_part);
    bf16 *Bh,*Bl,*B2h,*B2l,*B3h,*B3l,*Ch,*Cl,*Ph,*Pl,*Th,*Tl,*Rh,*Rl,*xh,*xl;
    cudaGetSymbolAddress((void**)&Bh,  s_Bh);  cudaGetSymbolAddress((void**)&Bl,  s_Bl);
    cudaGetSymbolAddress((void**)&B2h, s_B2h); cudaGetSymbolAddress((void**)&B2l, s_B2l);
    cudaGetSymbolAddress((void**)&B3h, s_B3h); cudaGetSymbolAddress((void**)&B3l, s_B3l);
    cudaGetSymbolAddress((void**)&Ch,  s_Ch);  cudaGetSymbolAddress((void**)&Cl,  s_Cl);
    cudaGetSymbolAddress((void**)&Ph,  s_Ph);  cudaGetSymbolAddress((void**)&Pl,  s_Pl);
    cudaGetSymbolAddress((void**)&Th,  s_Th);  cudaGetSymbolAddress((void**)&Tl,  s_Tl);
    cudaGetSymbolAddress((void**)&Rh,  s_Rh);  cudaGetSymbolAddress((void**)&Rl,  s_Rl);
    cudaGetSymbolAddress((void**)&xh,  g_xh);  cudaGetSymbolAddress((void**)&xl,  g_xl);

    // smem: STAGES * 2 splits * (ASZ + BSZ) * 2 bytes
    constexpr int SMEM_MAIN  = 3 * 2 * (128 * 40 + 32 * 136) * 2;  // 113664
    constexpr int SMEM_SMALL = 3 * 2 * (64 * 40  + 32 * 72 ) * 2;  // 58368
    cudaFuncSetAttribute(mma_gemm<128,128,64,32,256,3>,
                         cudaFuncAttributeMaxDynamicSharedMemorySize, SMEM_MAIN);
    cudaFuncSetAttribute(mma_gemm<64,64,32,32,128,3>,
                         cudaFuncAttributeMaxDynamicSharedMemorySize, SMEM_SMALL);

    const dim3 gS(DIM / 64, DIM / 64, SPLITK);   // split-K small gemms -> 1024 CTAs
    const int  rb  = DIM * DIM / 1024;           // reduce blocks (float4 x 256 thr)
    const int  sbx = (size_t)M * DIM / 1024;

    // split x (off the expm critical path semantically, runs first)
    split_kernel<<<sbx, 256>>>(x, xh, xl);

    // B = (W - W^T)/2, fused split
    skew_split_kernel<<<dim3(DIM / 32, DIM / 8), dim3(32, 8)>>>(W, B, Bh, Bl);

    // G1: B2 = B@B   -> reduce writes B2 fp32 + split
    mma_gemm<64,64,32,32,128,3><<<gS, 128, SMEM_SMALL>>>(Bh, Bl, Bh, Bl, Pt, DIM, DIM, DIM);
    reduce_split<SPLITK,false,true><<<rb, 256>>>(Pt, B2, B2h, B2l, nullptr, nullptr, 0.f, 0.f, 0.f);

    // C2 = I/720 + B/5040 + B2/40320  (bf16 split only)
    reduce_split<0,true,false><<<rb, 256>>>(nullptr, nullptr, Ch, Cl, B, B2,
                                            1.f/720.f, 1.f/5040.f, 1.f/40320.f);

    // G2: B3 = B2@B  -> split only
    mma_gemm<64,64,32,32,128,3><<<gS, 128, SMEM_SMALL>>>(B2h, B2l, Bh, Bl, Pt, DIM, DIM, DIM);
    reduce_split<SPLITK,false,false><<<rb, 256>>>(Pt, nullptr, B3h, B3l, nullptr, nullptr, 0.f, 0.f, 0.f);

    // G3: P = C2@B3 + C1,  C1 = I/6 + B/24 + B2/120 fused in reduce
    mma_gemm<64,64,32,32,128,3><<<gS, 128, SMEM_SMALL>>>(Ch, Cl, B3h, B3l, Pt, DIM, DIM, DIM);
    reduce_split<SPLITK,true,false><<<rb, 256>>>(Pt, nullptr, Ph, Pl, B, B2,
                                                 1.f/6.f, 1.f/24.f, 1.f/120.f);

    // G4: T = P@B3 + C0,  C0 = I + B + B2/2 fused in reduce
    mma_gemm<64,64,32,32,128,3><<<gS, 128, SMEM_SMALL>>>(Ph, Pl, B3h, B3l, Pt, DIM, DIM, DIM);
    reduce_split<SPLITK,true,false><<<rb, 256>>>(Pt, nullptr, Th, Tl, B, B2,
                                                 1.f, 1.f, 0.5f);

    // G5: R = T@T (undo scaling)
    mma_gemm<64,64,32,32,128,3><<<gS, 128, SMEM_SMALL>>>(Th, Tl, Th, Tl, Pt, DIM, DIM, DIM);
    reduce_split<SPLITK,false,false><<<rb, 256>>>(Pt, nullptr, Rh, Rl, nullptr, nullptr, 0.f, 0.f, 0.f);

    // main: out = x @ R
    mma_gemm<128,128,64,32,256,3><<<dim3(DIM / 128, M / 128, 1), 256, SMEM_MAIN>>>(
        xh, xl, Rh, Rl, out, M, DIM, DIM);
}

// round 9
// speedup vs baseline: 2.9075x; 1.0506x over previous
#include <cuda_runtime.h>
#include <cuda_bf16.h>
#include <cstdint>

typedef __nv_bfloat16 bf16;
#define DIM 1024
#define SPLITK 4

// ---------------- scratch (static device globals; no allocation) ----------------
__device__ float g_B   [DIM*DIM];
__device__ float g_B2  [DIM*DIM];
__device__ float g_part[SPLITK*DIM*DIM];

__device__ bf16 s_Bh [DIM*DIM], s_Bl [DIM*DIM];
__device__ bf16 s_B2h[DIM*DIM], s_B2l[DIM*DIM];
__device__ bf16 s_B3h[DIM*DIM], s_B3l[DIM*DIM];
__device__ bf16 s_Ch [DIM*DIM], s_Cl [DIM*DIM];
__device__ bf16 s_Ph [DIM*DIM], s_Pl [DIM*DIM];
__device__ bf16 s_Th [DIM*DIM], s_Tl [DIM*DIM];
__device__ bf16 s_Rh [DIM*DIM], s_Rl [DIM*DIM];

// ---------------- fused skew + split ----------------
__global__ void skew_split_kernel(const float* __restrict__ W, float* __restrict__ B,
                                  bf16* __restrict__ hi, bf16* __restrict__ lo) {
    int j = blockIdx.x * 32 + threadIdx.x;
    int i = blockIdx.y * 8  + threadIdx.y;
    float v = 0.5f * (W[i * DIM + j] - W[j * DIM + i]);
    B[i * DIM + j] = v;
    bf16 h = __float2bfloat16(v);
    hi[i * DIM + j] = h;
    lo[i * DIM + j] = __float2bfloat16(v - __bfloat162float(h));
}

// ---------------- fused reduce(+comb)(+split)(+second comb output) ----------------
// v = sum parts (+ a*I + b*Bm + c*B2m if COMB). Writes split(v), optional fp32 v.
// If COMB2: also writes split(a2*I + b2*Bm + c2*v) to hi2/lo2 (uses v as "B2").
template<int NPART, bool COMB, bool WF32, bool COMB2>
__global__ void reduce_split(const float* __restrict__ part, float* __restrict__ f32out,
                             bf16* __restrict__ hi, bf16* __restrict__ lo,
                             const float* __restrict__ Bm, const float* __restrict__ B2m,
                             float a, float b, float c,
                             bf16* __restrict__ hi2, bf16* __restrict__ lo2,
                             float a2, float b2, float c2)
{
    constexpr int SZ4 = DIM * DIM / 4;
    int i = blockIdx.x * 256 + threadIdx.x;
    float f[4] = {0.f, 0.f, 0.f, 0.f};
    #pragma unroll
    for (int p = 0; p < NPART; p++) {
        float4 t = reinterpret_cast<const float4*>(part)[p * SZ4 + i];
        f[0] += t.x; f[1] += t.y; f[2] += t.z; f[3] += t.w;
    }
    float bmv[4];
    if (COMB || COMB2) {
        float4 bm = reinterpret_cast<const float4*>(Bm)[i];
        bmv[0] = bm.x; bmv[1] = bm.y; bmv[2] = bm.z; bmv[3] = bm.w;
    }
    int e0 = i * 4;
    int d = (e0 >> 10) - (e0 & (DIM - 1));    // row - col0 (diag hit if 0<=d<4)
    if (COMB) {
        float4 b2v = reinterpret_cast<const float4*>(B2m)[i];
        f[0] += b * bmv[0] + c * b2v.x;
        f[1] += b * bmv[1] + c * b2v.y;
        f[2] += b * bmv[2] + c * b2v.z;
        f[3] += b * bmv[3] + c * b2v.w;
        if (d >= 0 && d < 4) f[d] += a;
    }
    if (WF32) {
        float4 o; o.x = f[0]; o.y = f[1]; o.z = f[2]; o.w = f[3];
        reinterpret_cast<float4*>(f32out)[i] = o;
    }
    union { bf16 b[4]; uint2 u; } H, L;
    #pragma unroll
    for (int j = 0; j < 4; j++) {
        bf16 h = __float2bfloat16(f[j]);
        H.b[j] = h;
        L.b[j] = __float2bfloat16(f[j] - __bfloat162float(h));
    }
    reinterpret_cast<uint2*>(hi)[i] = H.u;
    reinterpret_cast<uint2*>(lo)[i] = L.u;

    if (COMB2) {
        float g[4];
        #pragma unroll
        for (int j = 0; j < 4; j++) g[j] = b2 * bmv[j] + c2 * f[j];
        if (d >= 0 && d < 4) g[d] += a2;
        union { bf16 b[4]; uint2 u; } H2, L2;
        #pragma unroll
        for (int j = 0; j < 4; j++) {
            bf16 h = __float2bfloat16(g[j]);
            H2.b[j] = h;
            L2.b[j] = __float2bfloat16(g[j] - __bfloat162float(h));
        }
        reinterpret_cast<uint2*>(hi2)[i] = H2.u;
        reinterpret_cast<uint2*>(lo2)[i] = L2.u;
    }
}

// ---------------- async-copy / mma helpers ----------------
__device__ __forceinline__ void cp16(void* dst, const void* src) {
    unsigned d = (unsigned)__cvta_generic_to_shared(dst);
    asm volatile("cp.async.cg.shared.global [%0], [%1], 16;" :: "r"(d), "l"(src));
}
__device__ __forceinline__ void cp_commit() { asm volatile("cp.async.commit_group;"); }
template<int N>
__device__ __forceinline__ void cp_wait() { asm volatile("cp.async.wait_group %0;" :: "n"(N)); }

__device__ __forceinline__ void ldsm_x4(uint32_t a[4], const bf16* p) {
    unsigned s = (unsigned)__cvta_generic_to_shared(p);
    asm volatile("ldmatrix.sync.aligned.m8n8.x4.shared.b16 {%0,%1,%2,%3}, [%4];"
                 : "=r"(a[0]), "=r"(a[1]), "=r"(a[2]), "=r"(a[3]) : "r"(s));
}
__device__ __forceinline__ void ldsm_x2t(uint32_t b[2], const bf16* p) {
    unsigned s = (unsigned)__cvta_generic_to_shared(p);
    asm volatile("ldmatrix.sync.aligned.m8n8.x2.trans.shared.b16 {%0,%1}, [%2];"
                 : "=r"(b[0]), "=r"(b[1]) : "r"(s));
}
__device__ __forceinline__ void mma_bf16(float d[4], const uint32_t a[4], const uint32_t b[2]) {
    asm volatile("mma.sync.aligned.m16n8k16.row.col.f32.bf16.bf16.f32 "
                 "{%0,%1,%2,%3}, {%4,%5,%6,%7}, {%8,%9}, {%0,%1,%2,%3};"
                 : "+f"(d[0]), "+f"(d[1]), "+f"(d[2]), "+f"(d[3])
                 : "r"(a[0]), "r"(a[1]), "r"(a[2]), "r"(a[3]), "r"(b[0]), "r"(b[1]));
}

// ---------------- split-bf16 mma.sync GEMM (expm chain, split-K) ----------------
template<int BM, int BN, int WM, int WN, int THREADS, int STAGES>
__global__ __launch_bounds__(THREADS)
void mma_gemm(const bf16* __restrict__ Ah, const bf16* __restrict__ Al,
              const bf16* __restrict__ Bh, const bf16* __restrict__ Bl,
              float* __restrict__ C, int M, int N, int K)
{
    constexpr int BK = 32;
    constexpr int AP = BK + 8;
    constexpr int BP = BN + 8;
    constexpr int ASZ = BM * AP;
    constexpr int BSZ = BK * BP;
    constexpr int MI = WM / 16, NI = WN / 8;
    constexpr int WNC = BN / WN;
    constexpr int AC = (BM * BK / 8) / THREADS;
    constexpr int BC = (BK * BN / 8) / THREADS;

    extern __shared__ bf16 smem[];
    bf16* sA = smem;
    bf16* sB = smem + STAGES * 2 * ASZ;

    const int tid = threadIdx.x, lane = tid & 31, wid = tid >> 5;
    const int wm = wid / WNC, wn = wid % WNC;
    const int row0 = blockIdx.y * BM, col0 = blockIdx.x * BN;

    const int kchunk = K / gridDim.z;
    const int kbeg   = blockIdx.z * kchunk;
    const int NITER  = kchunk / BK;
    C += (size_t)blockIdx.z * (size_t)M * N;

    float acc[MI][NI][4];
    #pragma unroll
    for (int mi = 0; mi < MI; mi++)
        #pragma unroll
        for (int ni = 0; ni < NI; ni++)
            #pragma unroll
            for (int r = 0; r < 4; r++) acc[mi][ni][r] = 0.f;

    auto load_stage = [&](int st, int iter) {
        if (iter < NITER) {
            int k0 = kbeg + iter * BK;
            #pragma unroll
            for (int s = 0; s < 2; s++) {
                const bf16* gA = s ? Al : Ah;
                #pragma unroll
                for (int i = 0; i < AC; i++) {
                    int c = tid + i * THREADS;
                    int r = c / (BK / 8), cc = c % (BK / 8);
                    cp16(&sA[(st * 2 + s) * ASZ + r * AP + cc * 8],
                         gA + (size_t)(row0 + r) * K + k0 + cc * 8);
                }
                const bf16* gB = s ? Bl : Bh;
                #pragma unroll
                for (int i = 0; i < BC; i++) {
                    int c = tid + i * THREADS;
                    int r = c / (BN / 8), cc = c % (BN / 8);
                    cp16(&sB[(st * 2 + s) * BSZ + r * BP + cc * 8],
                         gB + (size_t)(k0 + r) * N + col0 + cc * 8);
                }
            }
        }
        cp_commit();
    };

    #pragma unroll
    for (int s = 0; s < STAGES - 1; s++) load_stage(s, s);

    for (int it = 0; it < NITER; it++) {
        cp_wait<STAGES - 2>();
        __syncthreads();
        load_stage((it + STAGES - 1) % STAGES, it + STAGES - 1);

        const int st = it % STAGES;
        const bf16* Ahs = &sA[(st * 2 + 0) * ASZ];
        const bf16* Als = &sA[(st * 2 + 1) * ASZ];
        const bf16* Bhs = &sB[(st * 2 + 0) * BSZ];
        const bf16* Bls = &sB[(st * 2 + 1) * BSZ];

        #pragma unroll
        for (int ks = 0; ks < 2; ks++) {
            const int k0 = ks * 16;
            uint32_t ah[MI][4], al[MI][4], bh[NI][2], bl[NI][2];
            #pragma unroll
            for (int mi = 0; mi < MI; mi++) {
                int r = wm * WM + mi * 16 + (lane & 15);
                int c = k0 + (lane >> 4) * 8;
                ldsm_x4(ah[mi], Ahs + r * AP + c);
                ldsm_x4(al[mi], Als + r * AP + c);
            }
            #pragma unroll
            for (int ni = 0; ni < NI; ni++) {
                int r = k0 + (lane & 15);
                int c = wn * WN + ni * 8;
                ldsm_x2t(bh[ni], Bhs + r * BP + c);
                ldsm_x2t(bl[ni], Bls + r * BP + c);
            }
            #pragma unroll
            for (int mi = 0; mi < MI; mi++)
                #pragma unroll
                for (int ni = 0; ni < NI; ni++) {
                    mma_bf16(acc[mi][ni], ah[mi], bh[ni]);
                    mma_bf16(acc[mi][ni], ah[mi], bl[ni]);
                    mma_bf16(acc[mi][ni], al[mi], bh[ni]);
                }
        }
    }

    #pragma unroll
    for (int mi = 0; mi < MI; mi++)
        #pragma unroll
        for (int ni = 0; ni < NI; ni++) {
            int r = row0 + wm * WM + mi * 16 + lane / 4;
            int c = col0 + wn * WN + ni * 8 + 2 * (lane % 4);
            *reinterpret_cast<float2*>(&C[(size_t)r * N + c]) =
                make_float2(acc[mi][ni][0], acc[mi][ni][1]);
            *reinterpret_cast<float2*>(&C[(size_t)(r + 8) * N + c]) =
                make_float2(acc[mi][ni][2], acc[mi][ni][3]);
        }
}

// ---------------- main GEMM: out = x @ R, fp32 x converted in-kernel ----------------
// A (x) loaded as fp32 via LDG, split to bf16 hi/lo in registers, STS to smem.
// B (Rh/Rl) via cp.async 2-stage. 128x128x32 tile, 8 warps (64x32 each).
__global__ __launch_bounds__(256, 2)
void xr_gemm(const float* __restrict__ X,
             const bf16* __restrict__ Bh, const bf16* __restrict__ Bl,
             float* __restrict__ C, int M, int N, int K)
{
    constexpr int BM = 128, BN = 128, BK = 32;
    constexpr int AP = BK + 8;         // 40 bf16 pitch -> LDSM conflict-free
    constexpr int BP = BN + 8;         // 136
    constexpr int ASZ = BM * AP;       // per split
    constexpr int BSZ = BK * BP;
    constexpr int MI = 4, NI = 4;      // WM=64, WN=32

    extern __shared__ bf16 smem[];
    bf16* sA = smem;                   // [stage][split][BM][AP]
    bf16* sB = smem + 2 * 2 * ASZ;     // [stage][split][BK][BP]

    const int tid = threadIdx.x, lane = tid & 31, wid = tid >> 5;
    const int wm = wid >> 2, wn = wid & 3;
    const int row0 = blockIdx.y * BM, col0 = blockIdx.x * BN;
    const int NITER = K / BK;

    float acc[MI][NI][4];
    #pragma unroll
    for (int mi = 0; mi < MI; mi++)
        #pragma unroll
        for (int ni = 0; ni < NI; ni++)
            #pragma unroll
            for (int r = 0; r < 4; r++) acc[mi][ni][r] = 0.f;

    // per-thread A staging: 4 float4 (f4 = tid + i*256; r = f4>>3, c4 = f4&7)
    float4 av[4];
    auto ldgA = [&](int iter) {
        int k0 = iter * BK;
        #pragma unroll
        for (int i = 0; i < 4; i++) {
            int f4 = tid + i * 256;
            int r = f4 >> 3, c4 = f4 & 7;
            av[i] = *reinterpret_cast<const float4*>(
                &X[(size_t)(row0 + r) * K + k0 + c4 * 4]);
        }
    };
    auto stsA = [&](int st) {
        #pragma unroll
        for (int i = 0; i < 4; i++) {
            int f4 = tid + i * 256;
            int r = f4 >> 3, c4 = f4 & 7;
            float f[4] = {av[i].x, av[i].y, av[i].z, av[i].w};
            union { bf16 b[4]; uint2 u; } H, L;
            #pragma unroll
            for (int j = 0; j < 4; j++) {
                bf16 h = __float2bfloat16(f[j]);
                H.b[j] = h;
                L.b[j] = __float2bfloat16(f[j] - __bfloat162float(h));
            }
            *reinterpret_cast<uint2*>(&sA[(st * 2 + 0) * ASZ + r * AP + c4 * 4]) = H.u;
            *reinterpret_cast<uint2*>(&sA[(st * 2 + 1) * ASZ + r * AP + c4 * 4]) = L.u;
        }
    };
    auto cpB = [&](int st, int iter) {
        int k0 = iter * BK;
        #pragma unroll
        for (int s = 0; s < 2; s++) {
            const bf16* g = s ? Bl : Bh;
            #pragma unroll
            for (int i = 0; i < 2; i++) {       // (32*128/8)/256 = 2
                int c = tid + i * 256;
                int r = c >> 4, cc = c & 15;
                cp16(&sB[(st * 2 + s) * BSZ + r * BP + cc * 8],
                     g + (size_t)(k0 + r) * N + col0 + cc * 8);
            }
        }
        cp_commit();
    };

    // prologue: stage 0
    ldgA(0);
    cpB(0, 0);
    stsA(0);
    cp_wait<0>();
    __syncthreads();

    int st = 0;
    for (int it = 0; it < NITER; it++) {
        const bool more = (it + 1) < NITER;
        if (more) { ldgA(it + 1); cpB(st ^ 1, it + 1); }

        const bf16* Ahs = &sA[(st * 2 + 0) * ASZ];
        const bf16* Als = &sA[(st * 2 + 1) * ASZ];
        const bf16* Bhs = &sB[(st * 2 + 0) * BSZ];
        const bf16* Bls = &sB[(st * 2 + 1) * BSZ];

        #pragma unroll
        for (int ks = 0; ks < 2; ks++) {
            const int k0 = ks * 16;
            uint32_t ah[MI][4], al[MI][4], bh[NI][2], bl[NI][2];
            #pragma unroll
            for (int mi = 0; mi < MI; mi++) {
                int r = wm * 64 + mi * 16 + (lane & 15);
                int c = k0 + (lane >> 4) * 8;
                ldsm_x4(ah[mi], Ahs + r * AP + c);
                ldsm_x4(al[mi], Als + r * AP + c);
            }
            #pragma unroll
            for (int ni = 0; ni < NI; ni++) {
                int r = k0 + (lane & 15);
                int c = wn * 32 + ni * 8;
                ldsm_x2t(bh[ni], Bhs + r * BP + c);
                ldsm_x2t(bl[ni], Bls + r * BP + c);
            }
            #pragma unroll
            for (int mi = 0; mi < MI; mi++)
                #pragma unroll
                for (int ni = 0; ni < NI; ni++) {
                    mma_bf16(acc[mi][ni], ah[mi], bh[ni]);
                    mma_bf16(acc[mi][ni], ah[mi], bl[ni]);
                    mma_bf16(acc[mi][ni], al[mi], bh[ni]);
                }
        }

        if (more) stsA(st ^ 1);     // safe: st^1 consumers all past prior sync
        cp_wait<0>();
        __syncthreads();
        st ^= 1;
    }

    #pragma unroll
    for (int mi = 0; mi < MI; mi++)
        #pragma unroll
        for (int ni = 0; ni < NI; ni++) {
            int r = row0 + wm * 64 + mi * 16 + lane / 4;
            int c = col0 + wn * 32 + ni * 8 + 2 * (lane % 4);
            *reinterpret_cast<float2*>(&C[(size_t)r * N + c]) =
                make_float2(acc[mi][ni][0], acc[mi][ni][1]);
            *reinterpret_cast<float2*>(&C[(size_t)(r + 8) * N + c]) =
                make_float2(acc[mi][ni][2], acc[mi][ni][3]);
        }
}

// ---------------- launch ----------------
extern "C" void kernel_launch(void* const* d_in, const int* in_sizes, int n_in,
                              void* d_out, int out_size)
{
    const float* x = (const float*)d_in[0];
    const float* W = (const float*)d_in[1];
    float* out = (float*)d_out;
    const int M = in_sizes[0] / DIM;   // 16384

    float *B, *B2, *Pt;
    cudaGetSymbolAddress((void**)&B,  g_B);
    cudaGetSymbolAddress((void**)&B2, g_B2);
    cudaGetSymbolAddress((void**)&Pt, g_part);
    bf16 *Bh,*Bl,*B2h,*B2l,*B3h,*B3l,*Ch,*Cl,*Ph,*Pl,*Th,*Tl,*Rh,*Rl;
    cudaGetSymbolAddress((void**)&Bh,  s_Bh);  cudaGetSymbolAddress((void**)&Bl,  s_Bl);
    cudaGetSymbolAddress((void**)&B2h, s_B2h); cudaGetSymbolAddress((void**)&B2l, s_B2l);
    cudaGetSymbolAddress((void**)&B3h, s_B3h); cudaGetSymbolAddress((void**)&B3l, s_B3l);
    cudaGetSymbolAddress((void**)&Ch,  s_Ch);  cudaGetSymbolAddress((void**)&Cl,  s_Cl);
    cudaGetSymbolAddress((void**)&Ph,  s_Ph);  cudaGetSymbolAddress((void**)&Pl,  s_Pl);
    cudaGetSymbolAddress((void**)&Th,  s_Th);  cudaGetSymbolAddress((void**)&Tl,  s_Tl);
    cudaGetSymbolAddress((void**)&Rh,  s_Rh);  cudaGetSymbolAddress((void**)&Rl,  s_Rl);

    constexpr int SMEM_SMALL = 3 * 2 * (64 * 40 + 32 * 72) * 2;         // 58368
    constexpr int SMEM_MAIN  = 2 * 2 * (128 * 40 + 32 * 136) * 2;       // 75776
    cudaFuncSetAttribute(mma_gemm<64,64,32,32,128,3>,
                         cudaFuncAttributeMaxDynamicSharedMemorySize, SMEM_SMALL);
    cudaFuncSetAttribute(xr_gemm,
                         cudaFuncAttributeMaxDynamicSharedMemorySize, SMEM_MAIN);

    const dim3 gS(DIM / 64, DIM / 64, SPLITK);
    const int  rb = DIM * DIM / 1024;

    // B = (W - W^T)/2, fused split
    skew_split_kernel<<<dim3(DIM / 32, DIM / 8), dim3(32, 8)>>>(W, B, Bh, Bl);

    // G1: B2 = B@B -> reduce writes B2 fp32 + split, AND C2 = I/720 + B/5040 + B2/40320
    mma_gemm<64,64,32,32,128,3><<<gS, 128, SMEM_SMALL>>>(Bh, Bl, Bh, Bl, Pt, DIM, DIM, DIM);
    reduce_split<SPLITK,false,true,true><<<rb, 256>>>(Pt, B2, B2h, B2l, B, nullptr,
        0.f, 0.f, 0.f, Ch, Cl, 1.f/720.f, 1.f/5040.f, 1.f/40320.f);

    // G2: B3 = B2@B
    mma_gemm<64,64,32,32,128,3><<<gS, 128, SMEM_SMALL>>>(B2h, B2l, Bh, Bl, Pt, DIM, DIM, DIM);
    reduce_split<SPLITK,false,false,false><<<rb, 256>>>(Pt, nullptr, B3h, B3l, nullptr, nullptr,
        0.f, 0.f, 0.f, nullptr, nullptr, 0.f, 0.f, 0.f);

    // G3: P = C2@B3 + C1,  C1 = I/6 + B/24 + B2/120
    mma_gemm<64,64,32,32,128,3><<<gS, 128, SMEM_SMALL>>>(Ch, Cl, B3h, B3l, Pt, DIM, DIM, DIM);
    reduce_split<SPLITK,true,false,false><<<rb, 256>>>(Pt, nullptr, Ph, Pl, B, B2,
        1.f/6.f, 1.f/24.f, 1.f/120.f, nullptr, nullptr, 0.f, 0.f, 0.f);

    // G4: T = P@B3 + C0,  C0 = I + B + B2/2
    mma_gemm<64,64,32,32,128,3><<<gS, 128, SMEM_SMALL>>>(Ph, Pl, B3h, B3l, Pt, DIM, DIM, DIM);
    reduce_split<SPLITK,true,false,false><<<rb, 256>>>(Pt, nullptr, Th, Tl, B, B2,
        1.f, 1.f, 0.5f, nullptr, nullptr, 0.f, 0.f, 0.f);

    // G5: R = T@T (undo scaling)
    mma_gemm<64,64,32,32,128,3><<<gS, 128, SMEM_SMALL>>>(Th, Tl, Th, Tl, Pt, DIM, DIM, DIM);
    reduce_split<SPLITK,false,false,false><<<rb, 256>>>(Pt, nullptr, Rh, Rl, nullptr, nullptr,
        0.f, 0.f, 0.f, nullptr, nullptr, 0.f, 0.f, 0.f);

    // main: out = x @ R (fp32 x converted in-kernel)
    xr_gemm<<<dim3(DIM / 128, M / 128), 256, SMEM_MAIN>>>(x, Rh, Rl, out, M, DIM, DIM);
}

// round 10
// speedup vs baseline: 3.1388x; 1.0795x over previous
#include <cuda_runtime.h>
#include <cuda_bf16.h>
#include <cstdint>

typedef __nv_bfloat16 bf16;
#define DIM 1024
#define SPLITK 4

// ---------------- scratch (static device globals; no allocation) ----------------
__device__ float g_B   [DIM*DIM];
__device__ float g_B2  [DIM*DIM];
__device__ float g_B3  [DIM*DIM];
__device__ float g_part[SPLITK*DIM*DIM];

__device__ bf16 s_Bh [DIM*DIM], s_Bl [DIM*DIM];
__device__ bf16 s_B2h[DIM*DIM], s_B2l[DIM*DIM];
__device__ bf16 s_B3h[DIM*DIM], s_B3l[DIM*DIM];
__device__ bf16 s_Qh [DIM*DIM], s_Ql [DIM*DIM];
__device__ bf16 s_Th [DIM*DIM], s_Tl [DIM*DIM];
__device__ bf16 s_Rh [DIM*DIM], s_Rl [DIM*DIM];

// ---------------- fused skew + split ----------------
__global__ void skew_split_kernel(const float* __restrict__ W, float* __restrict__ B,
                                  bf16* __restrict__ hi, bf16* __restrict__ lo) {
    int j = blockIdx.x * 32 + threadIdx.x;
    int i = blockIdx.y * 8  + threadIdx.y;
    float v = 0.5f * (W[i * DIM + j] - W[j * DIM + i]);
    B[i * DIM + j] = v;
    bf16 h = __float2bfloat16(v);
    hi[i * DIM + j] = h;
    lo[i * DIM + j] = __float2bfloat16(v - __bfloat162float(h));
}

// ---------------- fused reduce(+comb)(+split)(+second comb) ----------------
// f = sum parts; if COMB: f += a*I + b*Bm + c*B2m (+ e*B3m if HAS3).
// Writes split(f) -> hi/lo; optional fp32 f.
// If COMB2: g = a2*I + b2*Bm + c2*B2m + e2*f, writes split(g) -> hi2/lo2.
template<int NPART, bool COMB, bool WF32, bool COMB2, bool HAS3>
__global__ void reduce_split(const float* __restrict__ part, float* __restrict__ f32out,
                             bf16* __restrict__ hi, bf16* __restrict__ lo,
                             const float* __restrict__ Bm, const float* __restrict__ B2m,
                             const float* __restrict__ B3m,
                             float a, float b, float c, float e,
                             bf16* __restrict__ hi2, bf16* __restrict__ lo2,
                             float a2, float b2, float c2, float e2)
{
    constexpr int SZ4 = DIM * DIM / 4;
    int i = blockIdx.x * 256 + threadIdx.x;
    float f[4] = {0.f, 0.f, 0.f, 0.f};
    #pragma unroll
    for (int p = 0; p < NPART; p++) {
        float4 t = reinterpret_cast<const float4*>(part)[p * SZ4 + i];
        f[0] += t.x; f[1] += t.y; f[2] += t.z; f[3] += t.w;
    }
    float bmv[4], b2v[4];
    if (COMB || COMB2) {
        float4 t1 = reinterpret_cast<const float4*>(Bm)[i];
        bmv[0] = t1.x; bmv[1] = t1.y; bmv[2] = t1.z; bmv[3] = t1.w;
        float4 t2 = reinterpret_cast<const float4*>(B2m)[i];
        b2v[0] = t2.x; b2v[1] = t2.y; b2v[2] = t2.z; b2v[3] = t2.w;
    }
    int e0 = i * 4;
    int d = (e0 >> 10) - (e0 & (DIM - 1));    // row - col0 (diag hit if 0<=d<4)
    if (COMB) {
        #pragma unroll
        for (int j = 0; j < 4; j++) f[j] += b * bmv[j] + c * b2v[j];
        if (HAS3) {
            float4 t3 = reinterpret_cast<const float4*>(B3m)[i];
            f[0] += e * t3.x; f[1] += e * t3.y; f[2] += e * t3.z; f[3] += e * t3.w;
        }
        if (d >= 0 && d < 4) f[d] += a;
    }
    if (WF32) {
        float4 o; o.x = f[0]; o.y = f[1]; o.z = f[2]; o.w = f[3];
        reinterpret_cast<float4*>(f32out)[i] = o;
    }
    union { bf16 b[4]; uint2 u; } H, L;
    #pragma unroll
    for (int j = 0; j < 4; j++) {
        bf16 h = __float2bfloat16(f[j]);
        H.b[j] = h;
        L.b[j] = __float2bfloat16(f[j] - __bfloat162float(h));
    }
    reinterpret_cast<uint2*>(hi)[i] = H.u;
    reinterpret_cast<uint2*>(lo)[i] = L.u;

    if (COMB2) {
        float g[4];
        #pragma unroll
        for (int j = 0; j < 4; j++) g[j] = b2 * bmv[j] + c2 * b2v[j] + e2 * f[j];
        if (d >= 0 && d < 4) g[d] += a2;
        union { bf16 b[4]; uint2 u; } H2, L2;
        #pragma unroll
        for (int j = 0; j < 4; j++) {
            bf16 h = __float2bfloat16(g[j]);
            H2.b[j] = h;
            L2.b[j] = __float2bfloat16(g[j] - __bfloat162float(h));
        }
        reinterpret_cast<uint2*>(hi2)[i] = H2.u;
        reinterpret_cast<uint2*>(lo2)[i] = L2.u;
    }
}

// ---------------- async-copy / mma helpers ----------------
__device__ __forceinline__ void cp16(void* dst, const void* src) {
    unsigned d = (unsigned)__cvta_generic_to_shared(dst);
    asm volatile("cp.async.cg.shared.global [%0], [%1], 16;" :: "r"(d), "l"(src));
}
__device__ __forceinline__ void cp_commit() { asm volatile("cp.async.commit_group;"); }
template<int N>
__device__ __forceinline__ void cp_wait() { asm volatile("cp.async.wait_group %0;" :: "n"(N)); }

__device__ __forceinline__ void ldsm_x4(uint32_t a[4], const bf16* p) {
    unsigned s = (unsigned)__cvta_generic_to_shared(p);
    asm volatile("ldmatrix.sync.aligned.m8n8.x4.shared.b16 {%0,%1,%2,%3}, [%4];"
                 : "=r"(a[0]), "=r"(a[1]), "=r"(a[2]), "=r"(a[3]) : "r"(s));
}
__device__ __forceinline__ void ldsm_x2t(uint32_t b[2], const bf16* p) {
    unsigned s = (unsigned)__cvta_generic_to_shared(p);
    asm volatile("ldmatrix.sync.aligned.m8n8.x2.trans.shared.b16 {%0,%1}, [%2];"
                 : "=r"(b[0]), "=r"(b[1]) : "r"(s));
}
__device__ __forceinline__ void mma_bf16(float d[4], const uint32_t a[4], const uint32_t b[2]) {
    asm volatile("mma.sync.aligned.m16n8k16.row.col.f32.bf16.bf16.f32 "
                 "{%0,%1,%2,%3}, {%4,%5,%6,%7}, {%8,%9}, {%0,%1,%2,%3};"
                 : "+f"(d[0]), "+f"(d[1]), "+f"(d[2]), "+f"(d[3])
                 : "r"(a[0]), "r"(a[1]), "r"(a[2]), "r"(a[3]), "r"(b[0]), "r"(b[1]));
}

// ---------------- split-bf16 mma.sync GEMM (expm chain, split-K) ----------------
template<int BM, int BN, int WM, int WN, int THREADS, int STAGES>
__global__ __launch_bounds__(THREADS)
void mma_gemm(const bf16* __restrict__ Ah, const bf16* __restrict__ Al,
              const bf16* __restrict__ Bh, const bf16* __restrict__ Bl,
              float* __restrict__ C, int M, int N, int K)
{
    constexpr int BK = 32;
    constexpr int AP = BK + 8;
    constexpr int BP = BN + 8;
    constexpr int ASZ = BM * AP;
    constexpr int BSZ = BK * BP;
    constexpr int MI = WM / 16, NI = WN / 8;
    constexpr int WNC = BN / WN;
    constexpr int AC = (BM * BK / 8) / THREADS;
    constexpr int BC = (BK * BN / 8) / THREADS;

    extern __shared__ bf16 smem[];
    bf16* sA = smem;
    bf16* sB = smem + STAGES * 2 * ASZ;

    const int tid = threadIdx.x, lane = tid & 31, wid = tid >> 5;
    const int wm = wid / WNC, wn = wid % WNC;
    const int row0 = blockIdx.y * BM, col0 = blockIdx.x * BN;

    const int kchunk = K / gridDim.z;
    const int kbeg   = blockIdx.z * kchunk;
    const int NITER  = kchunk / BK;
    C += (size_t)blockIdx.z * (size_t)M * N;

    float acc[MI][NI][4];
    #pragma unroll
    for (int mi = 0; mi < MI; mi++)
        #pragma unroll
        for (int ni = 0; ni < NI; ni++)
            #pragma unroll
            for (int r = 0; r < 4; r++) acc[mi][ni][r] = 0.f;

    auto load_stage = [&](int st, int iter) {
        if (iter < NITER) {
            int k0 = kbeg + iter * BK;
            #pragma unroll
            for (int s = 0; s < 2; s++) {
                const bf16* gA = s ? Al : Ah;
                #pragma unroll
                for (int i = 0; i < AC; i++) {
                    int c = tid + i * THREADS;
                    int r = c / (BK / 8), cc = c % (BK / 8);
                    cp16(&sA[(st * 2 + s) * ASZ + r * AP + cc * 8],
                         gA + (size_t)(row0 + r) * K + k0 + cc * 8);
                }
                const bf16* gB = s ? Bl : Bh;
                #pragma unroll
                for (int i = 0; i < BC; i++) {
                    int c = tid + i * THREADS;
                    int r = c / (BN / 8), cc = c % (BN / 8);
                    cp16(&sB[(st * 2 + s) * BSZ + r * BP + cc * 8],
                         gB + (size_t)(k0 + r) * N + col0 + cc * 8);
                }
            }
        }
        cp_commit();
    };

    #pragma unroll
    for (int s = 0; s < STAGES - 1; s++) load_stage(s, s);

    for (int it = 0; it < NITER; it++) {
        cp_wait<STAGES - 2>();
        __syncthreads();
        load_stage((it + STAGES - 1) % STAGES, it + STAGES - 1);

        const int st = it % STAGES;
        const bf16* Ahs = &sA[(st * 2 + 0) * ASZ];
        const bf16* Als = &sA[(st * 2 + 1) * ASZ];
        const bf16* Bhs = &sB[(st * 2 + 0) * BSZ];
        const bf16* Bls = &sB[(st * 2 + 1) * BSZ];

        #pragma unroll
        for (int ks = 0; ks < 2; ks++) {
            const int k0 = ks * 16;
            uint32_t ah[MI][4], al[MI][4], bh[NI][2], bl[NI][2];
            #pragma unroll
            for (int mi = 0; mi < MI; mi++) {
                int r = wm * WM + mi * 16 + (lane & 15);
                int c = k0 + (lane >> 4) * 8;
                ldsm_x4(ah[mi], Ahs + r * AP + c);
                ldsm_x4(al[mi], Als + r * AP + c);
            }
            #pragma unroll
            for (int ni = 0; ni < NI; ni++) {
                int r = k0 + (lane & 15);
                int c = wn * WN + ni * 8;
                ldsm_x2t(bh[ni], Bhs + r * BP + c);
                ldsm_x2t(bl[ni], Bls + r * BP + c);
            }
            #pragma unroll
            for (int mi = 0; mi < MI; mi++)
                #pragma unroll
                for (int ni = 0; ni < NI; ni++) {
                    mma_bf16(acc[mi][ni], ah[mi], bh[ni]);
                    mma_bf16(acc[mi][ni], ah[mi], bl[ni]);
                    mma_bf16(acc[mi][ni], al[mi], bh[ni]);
                }
        }
    }

    #pragma unroll
    for (int mi = 0; mi < MI; mi++)
        #pragma unroll
        for (int ni = 0; ni < NI; ni++) {
            int r = row0 + wm * WM + mi * 16 + lane / 4;
            int c = col0 + wn * WN + ni * 8 + 2 * (lane % 4);
            *reinterpret_cast<float2*>(&C[(size_t)r * N + c]) =
                make_float2(acc[mi][ni][0], acc[mi][ni][1]);
            *reinterpret_cast<float2*>(&C[(size_t)(r + 8) * N + c]) =
                make_float2(acc[mi][ni][2], acc[mi][ni][3]);
        }
}

// ---------------- main GEMM: out = x @ R, fp32 x converted in-kernel ----------------
__global__ __launch_bounds__(256, 2)
void xr_gemm(const float* __restrict__ X,
             const bf16* __restrict__ Bh, const bf16* __restrict__ Bl,
             float* __restrict__ C, int M, int N, int K)
{
    constexpr int BM = 128, BN = 128, BK = 32;
    constexpr int AP = BK + 8;
    constexpr int BP = BN + 8;
    constexpr int ASZ = BM * AP;
    constexpr int BSZ = BK * BP;
    constexpr int MI = 4, NI = 4;

    extern __shared__ bf16 smem[];
    bf16* sA = smem;
    bf16* sB = smem + 2 * 2 * ASZ;

    const int tid = threadIdx.x, lane = tid & 31, wid = tid >> 5;
    const int wm = wid >> 2, wn = wid & 3;
    const int row0 = blockIdx.y * BM, col0 = blockIdx.x * BN;
    const int NITER = K / BK;

    float acc[MI][NI][4];
    #pragma unroll
    for (int mi = 0; mi < MI; mi++)
        #pragma unroll
        for (int ni = 0; ni < NI; ni++)
            #pragma unroll
            for (int r = 0; r < 4; r++) acc[mi][ni][r] = 0.f;

    float4 av[4];
    auto ldgA = [&](int iter) {
        int k0 = iter * BK;
        #pragma unroll
        for (int i = 0; i < 4; i++) {
            int f4 = tid + i * 256;
            int r = f4 >> 3, c4 = f4 & 7;
            av[i] = *reinterpret_cast<const float4*>(
                &X[(size_t)(row0 + r) * K + k0 + c4 * 4]);
        }
    };
    auto stsA = [&](int st) {
        #pragma unroll
        for (int i = 0; i < 4; i++) {
            int f4 = tid + i * 256;
            int r = f4 >> 3, c4 = f4 & 7;
            float f[4] = {av[i].x, av[i].y, av[i].z, av[i].w};
            union { bf16 b[4]; uint2 u; } H, L;
            #pragma unroll
            for (int j = 0; j < 4; j++) {
                bf16 h = __float2bfloat16(f[j]);
                H.b[j] = h;
                L.b[j] = __float2bfloat16(f[j] - __bfloat162float(h));
            }
            *reinterpret_cast<uint2*>(&sA[(st * 2 + 0) * ASZ + r * AP + c4 * 4]) = H.u;
            *reinterpret_cast<uint2*>(&sA[(st * 2 + 1) * ASZ + r * AP + c4 * 4]) = L.u;
        }
    };
    auto cpB = [&](int st, int iter) {
        int k0 = iter * BK;
        #pragma unroll
        for (int s = 0; s < 2; s++) {
            const bf16* g = s ? Bl : Bh;
            #pragma unroll
            for (int i = 0; i < 2; i++) {
                int c = tid + i * 256;
                int r = c >> 4, cc = c & 15;
                cp16(&sB[(st * 2 + s) * BSZ + r * BP + cc * 8],
                     g + (size_t)(k0 + r) * N + col0 + cc * 8);
            }
        }
        cp_commit();
    };

    ldgA(0);
    cpB(0, 0);
    stsA(0);
    cp_wait<0>();
    __syncthreads();

    int st = 0;
    for (int it = 0; it < NITER; it++) {
        const bool more = (it + 1) < NITER;
        if (more) { ldgA(it + 1); cpB(st ^ 1, it + 1); }

        const bf16* Ahs = &sA[(st * 2 + 0) * ASZ];
        const bf16* Als = &sA[(st * 2 + 1) * ASZ];
        const bf16* Bhs = &sB[(st * 2 + 0) * BSZ];
        const bf16* Bls = &sB[(st * 2 + 1) * BSZ];

        #pragma unroll
        for (int ks = 0; ks < 2; ks++) {
            const int k0 = ks * 16;
            uint32_t ah[MI][4], al[MI][4], bh[NI][2], bl[NI][2];
            #pragma unroll
            for (int mi = 0; mi < MI; mi++) {
                int r = wm * 64 + mi * 16 + (lane & 15);
                int c = k0 + (lane >> 4) * 8;
                ldsm_x4(ah[mi], Ahs + r * AP + c);
                ldsm_x4(al[mi], Als + r * AP + c);
            }
            #pragma unroll
            for (int ni = 0; ni < NI; ni++) {
                int r = k0 + (lane & 15);
                int c = wn * 32 + ni * 8;
                ldsm_x2t(bh[ni], Bhs + r * BP + c);
                ldsm_x2t(bl[ni], Bls + r * BP + c);
            }
            #pragma unroll
            for (int mi = 0; mi < MI; mi++)
                #pragma unroll
                for (int ni = 0; ni < NI; ni++) {
                    mma_bf16(acc[mi][ni], ah[mi], bh[ni]);
                    mma_bf16(acc[mi][ni], ah[mi], bl[ni]);
                    mma_bf16(acc[mi][ni], al[mi], bh[ni]);
                }
        }

        if (more) stsA(st ^ 1);
        cp_wait<0>();
        __syncthreads();
        st ^= 1;
    }

    #pragma unroll
    for (int mi = 0; mi < MI; mi++)
        #pragma unroll
        for (int ni = 0; ni < NI; ni++) {
            int r = row0 + wm * 64 + mi * 16 + lane / 4;
            int c = col0 + wn * 32 + ni * 8 + 2 * (lane % 4);
            *reinterpret_cast<float2*>(&C[(size_t)r * N + c]) =
                make_float2(acc[mi][ni][0], acc[mi][ni][1]);
            *reinterpret_cast<float2*>(&C[(size_t)(r + 8) * N + c]) =
                make_float2(acc[mi][ni][2], acc[mi][ni][3]);
        }
}

// ---------------- launch ----------------
extern "C" void kernel_launch(void* const* d_in, const int* in_sizes, int n_in,
                              void* d_out, int out_size)
{
    const float* x = (const float*)d_in[0];
    const float* W = (const float*)d_in[1];
    float* out = (float*)d_out;
    const int M = in_sizes[0] / DIM;   // 16384

    float *B, *B2, *B3, *Pt;
    cudaGetSymbolAddress((void**)&B,  g_B);
    cudaGetSymbolAddress((void**)&B2, g_B2);
    cudaGetSymbolAddress((void**)&B3, g_B3);
    cudaGetSymbolAddress((void**)&Pt, g_part);
    bf16 *Bh,*Bl,*B2h,*B2l,*B3h,*B3l,*Qh,*Ql,*Th,*Tl,*Rh,*Rl;
    cudaGetSymbolAddress((void**)&Bh,  s_Bh);  cudaGetSymbolAddress((void**)&Bl,  s_Bl);
    cudaGetSymbolAddress((void**)&B2h, s_B2h); cudaGetSymbolAddress((void**)&B2l, s_B2l);
    cudaGetSymbolAddress((void**)&B3h, s_B3h); cudaGetSymbolAddress((void**)&B3l, s_B3l);
    cudaGetSymbolAddress((void**)&Qh,  s_Qh);  cudaGetSymbolAddress((void**)&Ql,  s_Ql);
    cudaGetSymbolAddress((void**)&Th,  s_Th);  cudaGetSymbolAddress((void**)&Tl,  s_Tl);
    cudaGetSymbolAddress((void**)&Rh,  s_Rh);  cudaGetSymbolAddress((void**)&Rl,  s_Rl);

    constexpr int SMEM_SMALL = 2 * 2 * (64 * 40 + 32 * 72) * 2;         // 38912
    constexpr int SMEM_MAIN  = 2 * 2 * (128 * 40 + 32 * 136) * 2;       // 75776
    cudaFuncSetAttribute(mma_gemm<64,64,32,32,128,2>,
                         cudaFuncAttributeMaxDynamicSharedMemorySize, SMEM_SMALL);
    cudaFuncSetAttribute(xr_gemm,
                         cudaFuncAttributeMaxDynamicSharedMemorySize, SMEM_MAIN);

    const dim3 gS(DIM / 64, DIM / 64, SPLITK);
    const int  rb = DIM * DIM / 1024;

    // B = (W - W^T)/2, fused split
    skew_split_kernel<<<dim3(DIM / 32, DIM / 8), dim3(32, 8)>>>(W, B, Bh, Bl);

    // G1: B2 = B@B -> fp32 B2 + split
    mma_gemm<64,64,32,32,128,2><<<gS, 128, SMEM_SMALL>>>(Bh, Bl, Bh, Bl, Pt, DIM, DIM, DIM);
    reduce_split<SPLITK,false,true,false,false><<<rb, 256>>>(Pt, B2, B2h, B2l,
        nullptr, nullptr, nullptr, 0.f, 0.f, 0.f, 0.f, nullptr, nullptr, 0.f, 0.f, 0.f, 0.f);

    // G2: B3 = B2@B -> fp32 B3 + split, AND Q = B/24 + B2/120 + B3/720 (split)
    mma_gemm<64,64,32,32,128,2><<<gS, 128, SMEM_SMALL>>>(B2h, B2l, Bh, Bl, Pt, DIM, DIM, DIM);
    reduce_split<SPLITK,false,true,true,false><<<rb, 256>>>(Pt, B3, B3h, B3l,
        B, B2, nullptr, 0.f, 0.f, 0.f, 0.f, Qh, Ql, 0.f, 1.f/24.f, 1.f/120.f, 1.f/720.f);

    // G3: T = Q@B3 + I + B + B2/2 + B3/6  (degree-6 Paterson-Stockmeyer)
    mma_gemm<64,64,32,32,128,2><<<gS, 128, SMEM_SMALL>>>(Qh, Ql, B3h, B3l, Pt, DIM, DIM, DIM);
    reduce_split<SPLITK,true,false,false,true><<<rb, 256>>>(Pt, nullptr, Th, Tl,
        B, B2, B3, 1.f, 1.f, 0.5f, 1.f/6.f, nullptr, nullptr, 0.f, 0.f, 0.f, 0.f);

    // G4: R = T@T (undo scaling)
    mma_gemm<64,64,32,32,128,2><<<gS, 128, SMEM_SMALL>>>(Th, Tl, Th, Tl, Pt, DIM, DIM, DIM);
    reduce_split<SPLITK,false,false,false,false><<<rb, 256>>>(Pt, nullptr, Rh, Rl,
        nullptr, nullptr, nullptr, 0.f, 0.f, 0.f, 0.f, nullptr, nullptr, 0.f, 0.f, 0.f, 0.f);

    // main: out = x @ R (fp32 x converted in-kernel)
    xr_gemm<<<dim3(DIM / 128, M / 128), 256, SMEM_MAIN>>>(x, Rh, Rl, out, M, DIM, DIM);
}

// round 11
// speedup vs baseline: 3.1789x; 1.0128x over previous
#include <cuda_runtime.h>
#include <cuda_bf16.h>
#include <cstdint>

typedef __nv_bfloat16 bf16;
#define DIM 1024
#define SPLITK 8

// ---------------- scratch (static device globals; no allocation) ----------------
__device__ float g_B   [DIM*DIM];
__device__ float g_B2  [DIM*DIM];
__device__ float g_B3  [DIM*DIM];
__device__ float g_part[SPLITK*DIM*DIM];

__device__ bf16 s_Bh [DIM*DIM], s_Bl [DIM*DIM];
__device__ bf16 s_B2h[DIM*DIM], s_B2l[DIM*DIM];
__device__ bf16 s_B3h[DIM*DIM], s_B3l[DIM*DIM];
__device__ bf16 s_Qh [DIM*DIM], s_Ql [DIM*DIM];
__device__ bf16 s_Th [DIM*DIM], s_Tl [DIM*DIM];
__device__ bf16 s_Rh [DIM*DIM], s_Rl [DIM*DIM];

// ---------------- fused skew + split ----------------
__global__ void skew_split_kernel(const float* __restrict__ W, float* __restrict__ B,
                                  bf16* __restrict__ hi, bf16* __restrict__ lo) {
    int j = blockIdx.x * 32 + threadIdx.x;
    int i = blockIdx.y * 8  + threadIdx.y;
    float v = 0.5f * (W[i * DIM + j] - W[j * DIM + i]);
    B[i * DIM + j] = v;
    bf16 h = __float2bfloat16(v);
    hi[i * DIM + j] = h;
    lo[i * DIM + j] = __float2bfloat16(v - __bfloat162float(h));
}

// ---------------- fused reduce(+comb)(+split)(+second comb) ----------------
template<int NPART, bool COMB, bool WF32, bool COMB2, bool HAS3>
__global__ void reduce_split(const float* __restrict__ part, float* __restrict__ f32out,
                             bf16* __restrict__ hi, bf16* __restrict__ lo,
                             const float* __restrict__ Bm, const float* __restrict__ B2m,
                             const float* __restrict__ B3m,
                             float a, float b, float c, float e,
                             bf16* __restrict__ hi2, bf16* __restrict__ lo2,
                             float a2, float b2, float c2, float e2)
{
    constexpr int SZ4 = DIM * DIM / 4;
    int i = blockIdx.x * 256 + threadIdx.x;
    float f[4] = {0.f, 0.f, 0.f, 0.f};
    #pragma unroll
    for (int p = 0; p < NPART; p++) {
        float4 t = reinterpret_cast<const float4*>(part)[p * SZ4 + i];
        f[0] += t.x; f[1] += t.y; f[2] += t.z; f[3] += t.w;
    }
    float bmv[4], b2v[4];
    if (COMB || COMB2) {
        float4 t1 = reinterpret_cast<const float4*>(Bm)[i];
        bmv[0] = t1.x; bmv[1] = t1.y; bmv[2] = t1.z; bmv[3] = t1.w;
        float4 t2 = reinterpret_cast<const float4*>(B2m)[i];
        b2v[0] = t2.x; b2v[1] = t2.y; b2v[2] = t2.z; b2v[3] = t2.w;
    }
    int e0 = i * 4;
    int d = (e0 >> 10) - (e0 & (DIM - 1));
    if (COMB) {
        #pragma unroll
        for (int j = 0; j < 4; j++) f[j] += b * bmv[j] + c * b2v[j];
        if (HAS3) {
            float4 t3 = reinterpret_cast<const float4*>(B3m)[i];
            f[0] += e * t3.x; f[1] += e * t3.y; f[2] += e * t3.z; f[3] += e * t3.w;
        }
        if (d >= 0 && d < 4) f[d] += a;
    }
    if (WF32) {
        float4 o; o.x = f[0]; o.y = f[1]; o.z = f[2]; o.w = f[3];
        reinterpret_cast<float4*>(f32out)[i] = o;
    }
    union { bf16 b[4]; uint2 u; } H, L;
    #pragma unroll
    for (int j = 0; j < 4; j++) {
        bf16 h = __float2bfloat16(f[j]);
        H.b[j] = h;
        L.b[j] = __float2bfloat16(f[j] - __bfloat162float(h));
    }
    reinterpret_cast<uint2*>(hi)[i] = H.u;
    reinterpret_cast<uint2*>(lo)[i] = L.u;

    if (COMB2) {
        float g[4];
        #pragma unroll
        for (int j = 0; j < 4; j++) g[j] = b2 * bmv[j] + c2 * b2v[j] + e2 * f[j];
        if (d >= 0 && d < 4) g[d] += a2;
        union { bf16 b[4]; uint2 u; } H2, L2;
        #pragma unroll
        for (int j = 0; j < 4; j++) {
            bf16 h = __float2bfloat16(g[j]);
            H2.b[j] = h;
            L2.b[j] = __float2bfloat16(g[j] - __bfloat162float(h));
        }
        reinterpret_cast<uint2*>(hi2)[i] = H2.u;
        reinterpret_cast<uint2*>(lo2)[i] = L2.u;
    }
}

// ---------------- async-copy / mma helpers ----------------
__device__ __forceinline__ void cp16(void* dst, const void* src) {
    unsigned d = (unsigned)__cvta_generic_to_shared(dst);
    asm volatile("cp.async.cg.shared.global [%0], [%1], 16;" :: "r"(d), "l"(src));
}
__device__ __forceinline__ void cp_commit() { asm volatile("cp.async.commit_group;"); }
template<int N>
__device__ __forceinline__ void cp_wait() { asm volatile("cp.async.wait_group %0;" :: "n"(N)); }

__device__ __forceinline__ void ldsm_x4(uint32_t a[4], const bf16* p) {
    unsigned s = (unsigned)__cvta_generic_to_shared(p);
    asm volatile("ldmatrix.sync.aligned.m8n8.x4.shared.b16 {%0,%1,%2,%3}, [%4];"
                 : "=r"(a[0]), "=r"(a[1]), "=r"(a[2]), "=r"(a[3]) : "r"(s));
}
__device__ __forceinline__ void ldsm_x2t(uint32_t b[2], const bf16* p) {
    unsigned s = (unsigned)__cvta_generic_to_shared(p);
    asm volatile("ldmatrix.sync.aligned.m8n8.x2.trans.shared.b16 {%0,%1}, [%2];"
                 : "=r"(b[0]), "=r"(b[1]) : "r"(s));
}
__device__ __forceinline__ void mma_bf16(float d[4], const uint32_t a[4], const uint32_t b[2]) {
    asm volatile("mma.sync.aligned.m16n8k16.row.col.f32.bf16.bf16.f32 "
                 "{%0,%1,%2,%3}, {%4,%5,%6,%7}, {%8,%9}, {%0,%1,%2,%3};"
                 : "+f"(d[0]), "+f"(d[1]), "+f"(d[2]), "+f"(d[3])
                 : "r"(a[0]), "r"(a[1]), "r"(a[2]), "r"(a[3]), "r"(b[0]), "r"(b[1]));
}

// ---------------- split-bf16 mma.sync GEMM (expm chain, split-K) ----------------
template<int BM, int BN, int WM, int WN, int THREADS, int STAGES>
__global__ __launch_bounds__(THREADS)
void mma_gemm(const bf16* __restrict__ Ah, const bf16* __restrict__ Al,
              const bf16* __restrict__ Bh, const bf16* __restrict__ Bl,
              float* __restrict__ C, int M, int N, int K)
{
    constexpr int BK = 32;
    constexpr int AP = BK + 8;
    constexpr int BP = BN + 8;
    constexpr int ASZ = BM * AP;
    constexpr int BSZ = BK * BP;
    constexpr int MI = WM / 16, NI = WN / 8;
    constexpr int WNC = BN / WN;
    constexpr int AC = (BM * BK / 8) / THREADS;
    constexpr int BC = (BK * BN / 8) / THREADS;

    extern __shared__ bf16 smem[];
    bf16* sA = smem;
    bf16* sB = smem + STAGES * 2 * ASZ;

    const int tid = threadIdx.x, lane = tid & 31, wid = tid >> 5;
    const int wm = wid / WNC, wn = wid % WNC;
    const int row0 = blockIdx.y * BM, col0 = blockIdx.x * BN;

    const int kchunk = K / gridDim.z;
    const int kbeg   = blockIdx.z * kchunk;
    const int NITER  = kchunk / BK;
    C += (size_t)blockIdx.z * (size_t)M * N;

    float acc[MI][NI][4];
    #pragma unroll
    for (int mi = 0; mi < MI; mi++)
        #pragma unroll
        for (int ni = 0; ni < NI; ni++)
            #pragma unroll
            for (int r = 0; r < 4; r++) acc[mi][ni][r] = 0.f;

    auto load_stage = [&](int st, int iter) {
        if (iter < NITER) {
            int k0 = kbeg + iter * BK;
            #pragma unroll
            for (int s = 0; s < 2; s++) {
                const bf16* gA = s ? Al : Ah;
                #pragma unroll
                for (int i = 0; i < AC; i++) {
                    int c = tid + i * THREADS;
                    int r = c / (BK / 8), cc = c % (BK / 8);
                    cp16(&sA[(st * 2 + s) * ASZ + r * AP + cc * 8],
                         gA + (size_t)(row0 + r) * K + k0 + cc * 8);
                }
                const bf16* gB = s ? Bl : Bh;
                #pragma unroll
                for (int i = 0; i < BC; i++) {
                    int c = tid + i * THREADS;
                    int r = c / (BN / 8), cc = c % (BN / 8);
                    cp16(&sB[(st * 2 + s) * BSZ + r * BP + cc * 8],
                         gB + (size_t)(k0 + r) * N + col0 + cc * 8);
                }
            }
        }
        cp_commit();
    };

    #pragma unroll
    for (int s = 0; s < STAGES - 1; s++) load_stage(s, s);

    for (int it = 0; it < NITER; it++) {
        cp_wait<STAGES - 2>();
        __syncthreads();
        load_stage((it + STAGES - 1) % STAGES, it + STAGES - 1);

        const int st = it % STAGES;
        const bf16* Ahs = &sA[(st * 2 + 0) * ASZ];
        const bf16* Als = &sA[(st * 2 + 1) * ASZ];
        const bf16* Bhs = &sB[(st * 2 + 0) * BSZ];
        const bf16* Bls = &sB[(st * 2 + 1) * BSZ];

        #pragma unroll
        for (int ks = 0; ks < 2; ks++) {
            const int k0 = ks * 16;
            uint32_t ah[MI][4], al[MI][4], bh[NI][2], bl[NI][2];
            #pragma unroll
            for (int mi = 0; mi < MI; mi++) {
                int r = wm * WM + mi * 16 + (lane & 15);
                int c = k0 + (lane >> 4) * 8;
                ldsm_x4(ah[mi], Ahs + r * AP + c);
                ldsm_x4(al[mi], Als + r * AP + c);
            }
            #pragma unroll
            for (int ni = 0; ni < NI; ni++) {
                int r = k0 + (lane & 15);
                int c = wn * WN + ni * 8;
                ldsm_x2t(bh[ni], Bhs + r * BP + c);
                ldsm_x2t(bl[ni], Bls + r * BP + c);
            }
            #pragma unroll
            for (int mi = 0; mi < MI; mi++)
                #pragma unroll
                for (int ni = 0; ni < NI; ni++) {
                    mma_bf16(acc[mi][ni], ah[mi], bh[ni]);
                    mma_bf16(acc[mi][ni], ah[mi], bl[ni]);
                    mma_bf16(acc[mi][ni], al[mi], bh[ni]);
                }
        }
    }

    #pragma unroll
    for (int mi = 0; mi < MI; mi++)
        #pragma unroll
        for (int ni = 0; ni < NI; ni++) {
            int r = row0 + wm * WM + mi * 16 + lane / 4;
            int c = col0 + wn * WN + ni * 8 + 2 * (lane % 4);
            *reinterpret_cast<float2*>(&C[(size_t)r * N + c]) =
                make_float2(acc[mi][ni][0], acc[mi][ni][1]);
            *reinterpret_cast<float2*>(&C[(size_t)(r + 8) * N + c]) =
                make_float2(acc[mi][ni][2], acc[mi][ni][3]);
        }
}

// ---------------- main GEMM: out = x @ R, 3-stage, fp32 x converted in-kernel ----
// Stage rotation (mod 3): compute stage it; STS A for it+1 (from regs loaded at
// it-1... held in av); cp.async B for it+2; wait_group<=1 keeps one group in flight.
__global__ __launch_bounds__(256, 2)
void xr_gemm(const float* __restrict__ X,
             const bf16* __restrict__ Bh, const bf16* __restrict__ Bl,
             float* __restrict__ C, int M, int N, int K)
{
    constexpr int BM = 128, BN = 128, BK = 32;
    constexpr int AP = BK + 8;
    constexpr int BP = BN + 8;
    constexpr int ASZ = BM * AP;
    constexpr int BSZ = BK * BP;
    constexpr int MI = 4, NI = 4;
    constexpr int ST = 3;

    extern __shared__ bf16 smem[];
    bf16* sA = smem;                    // [stage][split][BM][AP]
    bf16* sB = smem + ST * 2 * ASZ;     // [stage][split][BK][BP]

    const int tid = threadIdx.x, lane = tid & 31, wid = tid >> 5;
    const int wm = wid >> 2, wn = wid & 3;
    const int row0 = blockIdx.y * BM, col0 = blockIdx.x * BN;
    const int NITER = K / BK;

    float acc[MI][NI][4];
    #pragma unroll
    for (int mi = 0; mi < MI; mi++)
        #pragma unroll
        for (int ni = 0; ni < NI; ni++)
            #pragma unroll
            for (int r = 0; r < 4; r++) acc[mi][ni][r] = 0.f;

    float4 av[4];
    auto ldgA = [&](int iter) {
        int k0 = iter * BK;
        #pragma unroll
        for (int i = 0; i < 4; i++) {
            int f4 = tid + i * 256;
            int r = f4 >> 3, c4 = f4 & 7;
            av[i] = *reinterpret_cast<const float4*>(
                &X[(size_t)(row0 + r) * K + k0 + c4 * 4]);
        }
    };
    auto stsA = [&](int st) {
        #pragma unroll
        for (int i = 0; i < 4; i++) {
            int f4 = tid + i * 256;
            int r = f4 >> 3, c4 = f4 & 7;
            float f[4] = {av[i].x, av[i].y, av[i].z, av[i].w};
            union { bf16 b[4]; uint2 u; } H, L;
            #pragma unroll
            for (int j = 0; j < 4; j++) {
                bf16 h = __float2bfloat16(f[j]);
                H.b[j] = h;
                L.b[j] = __float2bfloat16(f[j] - __bfloat162float(h));
            }
            *reinterpret_cast<uint2*>(&sA[(st * 2 + 0) * ASZ + r * AP + c4 * 4]) = H.u;
            *reinterpret_cast<uint2*>(&sA[(st * 2 + 1) * ASZ + r * AP + c4 * 4]) = L.u;
        }
    };
    auto cpB = [&](int st, int iter) {       // always commits (group accounting)
        if (iter < NITER) {
            int k0 = iter * BK;
            #pragma unroll
            for (int s = 0; s < 2; s++) {
                const bf16* g = s ? Bl : Bh;
                #pragma unroll
                for (int i = 0; i < 2; i++) {
                    int c = tid + i * 256;
                    int r = c >> 4, cc = c & 15;
                    cp16(&sB[(st * 2 + s) * BSZ + r * BP + cc * 8],
                         g + (size_t)(k0 + r) * N + col0 + cc * 8);
                }
            }
        }
        cp_commit();
    };

    // prologue: A0 direct, B0+B1 async, A1 held in regs
    ldgA(0);
    stsA(0);
    cpB(0, 0);
    ldgA(1);
    cpB(1, 1);

    for (int it = 0; it < NITER; it++) {
        cp_wait<1>();          // B(it) landed; B(it+1) may still fly
        __syncthreads();

        const int st = it % ST;
        const bf16* Ahs = &sA[(st * 2 + 0) * ASZ];
        const bf16* Als = &sA[(st * 2 + 1) * ASZ];
        const bf16* Bhs = &sB[(st * 2 + 0) * BSZ];
        const bf16* Bls = &sB[(st * 2 + 1) * BSZ];

        #pragma unroll
        for (int ks = 0; ks < 2; ks++) {
            const int k0 = ks * 16;
            uint32_t ah[MI][4], al[MI][4], bh[NI][2], bl[NI][2];
            #pragma unroll
            for (int mi = 0; mi < MI; mi++) {
                int r = wm * 64 + mi * 16 + (lane & 15);
                int c = k0 + (lane >> 4) * 8;
                ldsm_x4(ah[mi], Ahs + r * AP + c);
                ldsm_x4(al[mi], Als + r * AP + c);
            }
            #pragma unroll
            for (int ni = 0; ni < NI; ni++) {
                int r = k0 + (lane & 15);
                int c = wn * 32 + ni * 8;
                ldsm_x2t(bh[ni], Bhs + r * BP + c);
                ldsm_x2t(bl[ni], Bls + r * BP + c);
            }
            #pragma unroll
            for (int mi = 0; mi < MI; mi++)
                #pragma unroll
                for (int ni = 0; ni < NI; ni++) {
                    mma_bf16(acc[mi][ni], ah[mi], bh[ni]);
                    mma_bf16(acc[mi][ni], ah[mi], bl[ni]);
                    mma_bf16(acc[mi][ni], al[mi], bh[ni]);
                }
        }

        // stage (it+1)%3: A from av (write-safe: last read two syncs ago)
        if (it + 1 < NITER) stsA((it + 1) % ST);
        // stage (it+2)%3: B async + next A into regs
        if (it + 2 < NITER) ldgA(it + 2);
        cpB((it + 2) % ST, it + 2);
    }

    #pragma unroll
    for (int mi = 0; mi < MI; mi++)
        #pragma unroll
        for (int ni = 0; ni < NI; ni++) {
            int r = row0 + wm * 64 + mi * 16 + lane / 4;
            int c = col0 + wn * 32 + ni * 8 + 2 * (lane % 4);
            *reinterpret_cast<float2*>(&C[(size_t)r * N + c]) =
                make_float2(acc[mi][ni][0], acc[mi][ni][1]);
            *reinterpret_cast<float2*>(&C[(size_t)(r + 8) * N + c]) =
                make_float2(acc[mi][ni][2], acc[mi][ni][3]);
        }
}

// ---------------- launch ----------------
extern "C" void kernel_launch(void* const* d_in, const int* in_sizes, int n_in,
                              void* d_out, int out_size)
{
    const float* x = (const float*)d_in[0];
    const float* W = (const float*)d_in[1];
    float* out = (float*)d_out;
    const int M = in_sizes[0] / DIM;   // 16384

    float *B, *B2, *B3, *Pt;
    cudaGetSymbolAddress((void**)&B,  g_B);
    cudaGetSymbolAddress((void**)&B2, g_B2);
    cudaGetSymbolAddress((void**)&B3, g_B3);
    cudaGetSymbolAddress((void**)&Pt, g_part);
    bf16 *Bh,*Bl,*B2h,*B2l,*B3h,*B3l,*Qh,*Ql,*Th,*Tl,*Rh,*Rl;
    cudaGetSymbolAddress((void**)&Bh,  s_Bh);  cudaGetSymbolAddress((void**)&Bl,  s_Bl);
    cudaGetSymbolAddress((void**)&B2h, s_B2h); cudaGetSymbolAddress((void**)&B2l, s_B2l);
    cudaGetSymbolAddress((void**)&B3h, s_B3h); cudaGetSymbolAddress((void**)&B3l, s_B3l);
    cudaGetSymbolAddress((void**)&Qh,  s_Qh);  cudaGetSymbolAddress((void**)&Ql,  s_Ql);
    cudaGetSymbolAddress((void**)&Th,  s_Th);  cudaGetSymbolAddress((void**)&Tl,  s_Tl);
    cudaGetSymbolAddress((void**)&Rh,  s_Rh);  cudaGetSymbolAddress((void**)&Rl,  s_Rl);

    constexpr int SMEM_SMALL = 2 * 2 * (64 * 40 + 32 * 72) * 2;         // 38912
    constexpr int SMEM_MAIN  = 3 * 2 * (128 * 40 + 32 * 136) * 2;       // 113664
    cudaFuncSetAttribute(mma_gemm<64,64,32,32,128,2>,
                         cudaFuncAttributeMaxDynamicSharedMemorySize, SMEM_SMALL);
    cudaFuncSetAttribute(xr_gemm,
                         cudaFuncAttributeMaxDynamicSharedMemorySize, SMEM_MAIN);

    const dim3 gS(DIM / 64, DIM / 64, SPLITK);
    const int  rb = DIM * DIM / 1024;

    // B = (W - W^T)/2, fused split
    skew_split_kernel<<<dim3(DIM / 32, DIM / 8), dim3(32, 8)>>>(W, B, Bh, Bl);

    // G1: B2 = B@B -> fp32 B2 + split
    mma_gemm<64,64,32,32,128,2><<<gS, 128, SMEM_SMALL>>>(Bh, Bl, Bh, Bl, Pt, DIM, DIM, DIM);
    reduce_split<SPLITK,false,true,false,false><<<rb, 256>>>(Pt, B2, B2h, B2l,
        nullptr, nullptr, nullptr, 0.f, 0.f, 0.f, 0.f, nullptr, nullptr, 0.f, 0.f, 0.f, 0.f);

    // G2: B3 = B2@B -> fp32 B3 + split, AND Q = B/24 + B2/120 + B3/720 (split)
    mma_gemm<64,64,32,32,128,2><<<gS, 128, SMEM_SMALL>>>(B2h, B2l, Bh, Bl, Pt, DIM, DIM, DIM);
    reduce_split<SPLITK,false,true,true,false><<<rb, 256>>>(Pt, B3, B3h, B3l,
        B, B2, nullptr, 0.f, 0.f, 0.f, 0.f, Qh, Ql, 0.f, 1.f/24.f, 1.f/120.f, 1.f/720.f);

    // G3: T = Q@B3 + I + B + B2/2 + B3/6  (degree-6 Paterson-Stockmeyer)
    mma_gemm<64,64,32,32,128,2><<<gS, 128, SMEM_SMALL>>>(Qh, Ql, B3h, B3l, Pt, DIM, DIM, DIM);
    reduce_split<SPLITK,true,false,false,true><<<rb, 256>>>(Pt, nullptr, Th, Tl,
        B, B2, B3, 1.f, 1.f, 0.5f, 1.f/6.f, nullptr, nullptr, 0.f, 0.f, 0.f, 0.f);

    // G4: R = T@T (undo scaling)
    mma_gemm<64,64,32,32,128,2><<<gS, 128, SMEM_SMALL>>>(Th, Tl, Th, Tl, Pt, DIM, DIM, DIM);
    reduce_split<SPLITK,false,false,false,false><<<rb, 256>>>(Pt, nullptr, Rh, Rl,
        nullptr, nullptr, nullptr, 0.f, 0.f, 0.f, 0.f, nullptr, nullptr, 0.f, 0.f, 0.f, 0.f);

    // main: out = x @ R (fp32 x converted in-kernel, 3-stage)
    xr_gemm<<<dim3(DIM / 128, M / 128), 256, SMEM_MAIN>>>(x, Rh, Rl, out, M, DIM, DIM);
}

// round 13
// speedup vs baseline: 3.1818x; 1.0009x over previous
#include <cuda_runtime.h>
#include <cuda_bf16.h>
#include <cstdint>

typedef __nv_bfloat16 bf16;
#define DIM 1024
#define SPLITK 8

// ---------------- scratch (static device globals; no allocation) ----------------
__device__ float g_B   [DIM*DIM];
__device__ float g_B2  [DIM*DIM];
__device__ float g_B3  [DIM*DIM];
__device__ float g_part[SPLITK*DIM*DIM];

__device__ bf16 s_Bh [DIM*DIM], s_Bl [DIM*DIM];
__device__ bf16 s_B2h[DIM*DIM], s_B2l[DIM*DIM];
__device__ bf16 s_B3h[DIM*DIM], s_B3l[DIM*DIM];
__device__ bf16 s_Qh [DIM*DIM], s_Ql [DIM*DIM];
__device__ bf16 s_Th [DIM*DIM], s_Tl [DIM*DIM];
__device__ bf16 s_Rh [DIM*DIM], s_Rl [DIM*DIM];

// ---------------- fused skew + split (coalesced via smem transpose tile) --------
__global__ void skew_split_kernel(const float* __restrict__ W, float* __restrict__ B,
                                  bf16* __restrict__ hi, bf16* __restrict__ lo) {
    __shared__ float t[32][33];
    int tx = threadIdx.x, ty = threadIdx.y;          // 32 x 8
    int bx = blockIdx.x * 32, by = blockIdx.y * 32;
    // t[a][b] = W[(bx+a)][by+b]  (coalesced row reads of the transpose source)
    #pragma unroll
    for (int i = 0; i < 4; i++)
        t[ty + i * 8][tx] = W[(size_t)(bx + ty + i * 8) * DIM + by + tx];
    __syncthreads();
    #pragma unroll
    for (int i = 0; i < 4; i++) {
        int r = by + ty + i * 8, c = bx + tx;
        float v = 0.5f * (W[(size_t)r * DIM + c] - t[tx][ty + i * 8]);
        B[(size_t)r * DIM + c] = v;
        bf16 h = __float2bfloat16(v);
        hi[(size_t)r * DIM + c] = h;
        lo[(size_t)r * DIM + c] = __float2bfloat16(v - __bfloat162float(h));
    }
}

// ---------------- fused reduce(+comb)(+split)(+second comb) ----------------
template<int NPART, bool COMB, bool WF32, bool COMB2, bool HAS3>
__global__ void reduce_split(const float* __restrict__ part, float* __restrict__ f32out,
                             bf16* __restrict__ hi, bf16* __restrict__ lo,
                             const float* __restrict__ Bm, const float* __restrict__ B2m,
                             const float* __restrict__ B3m,
                             float a, float b, float c, float e,
                             bf16* __restrict__ hi2, bf16* __restrict__ lo2,
                             float a2, float b2, float c2, float e2)
{
    constexpr int SZ4 = DIM * DIM / 4;
    int i = blockIdx.x * 256 + threadIdx.x;
    float f[4] = {0.f, 0.f, 0.f, 0.f};
    #pragma unroll
    for (int p = 0; p < NPART; p++) {
        float4 t = reinterpret_cast<const float4*>(part)[p * SZ4 + i];
        f[0] += t.x; f[1] += t.y; f[2] += t.z; f[3] += t.w;
    }
    float bmv[4], b2v[4];
    if (COMB || COMB2) {
        float4 t1 = reinterpret_cast<const float4*>(Bm)[i];
        bmv[0] = t1.x; bmv[1] = t1.y; bmv[2] = t1.z; bmv[3] = t1.w;
        float4 t2 = reinterpret_cast<const float4*>(B2m)[i];
        b2v[0] = t2.x; b2v[1] = t2.y; b2v[2] = t2.z; b2v[3] = t2.w;
    }
    int e0 = i * 4;
    int d = (e0 >> 10) - (e0 & (DIM - 1));
    if (COMB) {
        #pragma unroll
        for (int j = 0; j < 4; j++) f[j] += b * bmv[j] + c * b2v[j];
        if (HAS3) {
            float4 t3 = reinterpret_cast<const float4*>(B3m)[i];
            f[0] += e * t3.x; f[1] += e * t3.y; f[2] += e * t3.z; f[3] += e * t3.w;
        }
        if (d >= 0 && d < 4) f[d] += a;
    }
    if (WF32) {
        float4 o; o.x = f[0]; o.y = f[1]; o.z = f[2]; o.w = f[3];
        reinterpret_cast<float4*>(f32out)[i] = o;
    }
    union { bf16 b[4]; uint2 u; } H, L;
    #pragma unroll
    for (int j = 0; j < 4; j++) {
        bf16 h = __float2bfloat16(f[j]);
        H.b[j] = h;
        L.b[j] = __float2bfloat16(f[j] - __bfloat162float(h));
    }
    reinterpret_cast<uint2*>(hi)[i] = H.u;
    reinterpret_cast<uint2*>(lo)[i] = L.u;

    if (COMB2) {
        float g[4];
        #pragma unroll
        for (int j = 0; j < 4; j++) g[j] = b2 * bmv[j] + c2 * b2v[j] + e2 * f[j];
        if (d >= 0 && d < 4) g[d] += a2;
        union { bf16 b[4]; uint2 u; } H2, L2;
        #pragma unroll
        for (int j = 0; j < 4; j++) {
            bf16 h = __float2bfloat16(g[j]);
            H2.b[j] = h;
            L2.b[j] = __float2bfloat16(g[j] - __bfloat162float(h));
        }
        reinterpret_cast<uint2*>(hi2)[i] = H2.u;
        reinterpret_cast<uint2*>(lo2)[i] = L2.u;
    }
}

// ---------------- async-copy / mma helpers ----------------
__device__ __forceinline__ void cp16(void* dst, const void* src) {
    unsigned d = (unsigned)__cvta_generic_to_shared(dst);
    asm volatile("cp.async.cg.shared.global [%0], [%1], 16;" :: "r"(d), "l"(src));
}
__device__ __forceinline__ void cp_commit() { asm volatile("cp.async.commit_group;"); }
template<int N>
__device__ __forceinline__ void cp_wait() { asm volatile("cp.async.wait_group %0;" :: "n"(N)); }

__device__ __forceinline__ void ldsm_x4(uint32_t a[4], const bf16* p) {
    unsigned s = (unsigned)__cvta_generic_to_shared(p);
    asm volatile("ldmatrix.sync.aligned.m8n8.x4.shared.b16 {%0,%1,%2,%3}, [%4];"
                 : "=r"(a[0]), "=r"(a[1]), "=r"(a[2]), "=r"(a[3]) : "r"(s));
}
__device__ __forceinline__ void ldsm_x2t(uint32_t b[2], const bf16* p) {
    unsigned s = (unsigned)__cvta_generic_to_shared(p);
    asm volatile("ldmatrix.sync.aligned.m8n8.x2.trans.shared.b16 {%0,%1}, [%2];"
                 : "=r"(b[0]), "=r"(b[1]) : "r"(s));
}
__device__ __forceinline__ void mma_bf16(float d[4], const uint32_t a[4], const uint32_t b[2]) {
    asm volatile("mma.sync.aligned.m16n8k16.row.col.f32.bf16.bf16.f32 "
                 "{%0,%1,%2,%3}, {%4,%5,%6,%7}, {%8,%9}, {%0,%1,%2,%3};"
                 : "+f"(d[0]), "+f"(d[1]), "+f"(d[2]), "+f"(d[3])
                 : "r"(a[0]), "r"(a[1]), "r"(a[2]), "r"(a[3]), "r"(b[0]), "r"(b[1]));
}

// ---------------- split-bf16 mma.sync GEMM (expm chain, split-K) ----------------
template<int BM, int BN, int WM, int WN, int THREADS, int STAGES>
__global__ __launch_bounds__(THREADS)
void mma_gemm(const bf16* __restrict__ Ah, const bf16* __restrict__ Al,
              const bf16* __restrict__ Bh, const bf16* __restrict__ Bl,
              float* __restrict__ C, int M, int N, int K)
{
    constexpr int BK = 32;
    constexpr int AP = BK + 8;
    constexpr int BP = BN + 8;
    constexpr int ASZ = BM * AP;
    constexpr int BSZ = BK * BP;
    constexpr int MI = WM / 16, NI = WN / 8;
    constexpr int WNC = BN / WN;
    constexpr int AC = (BM * BK / 8) / THREADS;
    constexpr int BC = (BK * BN / 8) / THREADS;

    extern __shared__ bf16 smem[];
    bf16* sA = smem;
    bf16* sB = smem + STAGES * 2 * ASZ;

    const int tid = threadIdx.x, lane = tid & 31, wid = tid >> 5;
    const int wm = wid / WNC, wn = wid % WNC;
    const int row0 = blockIdx.y * BM, col0 = blockIdx.x * BN;

    const int kchunk = K / gridDim.z;
    const int kbeg   = blockIdx.z * kchunk;
    const int NITER  = kchunk / BK;
    C += (size_t)blockIdx.z * (size_t)M * N;

    float acc[MI][NI][4];
    #pragma unroll
    for (int mi = 0; mi < MI; mi++)
        #pragma unroll
        for (int ni = 0; ni < NI; ni++)
            #pragma unroll
            for (int r = 0; r < 4; r++) acc[mi][ni][r] = 0.f;

    auto load_stage = [&](int st, int iter) {
        if (iter < NITER) {
            int k0 = kbeg + iter * BK;
            #pragma unroll
            for (int s = 0; s < 2; s++) {
                const bf16* gA = s ? Al : Ah;
                #pragma unroll
                for (int i = 0; i < AC; i++) {
                    int c = tid + i * THREADS;
                    int r = c / (BK / 8), cc = c % (BK / 8);
                    cp16(&sA[(st * 2 + s) * ASZ + r * AP + cc * 8],
                         gA + (size_t)(row0 + r) * K + k0 + cc * 8);
                }
                const bf16* gB = s ? Bl : Bh;
                #pragma unroll
                for (int i = 0; i < BC; i++) {
                    int c = tid + i * THREADS;
                    int r = c / (BN / 8), cc = c % (BN / 8);
                    cp16(&sB[(st * 2 + s) * BSZ + r * BP + cc * 8],
                         gB + (size_t)(k0 + r) * N + col0 + cc * 8);
                }
            }
        }
        cp_commit();
    };

    #pragma unroll
    for (int s = 0; s < STAGES - 1; s++) load_stage(s, s);

    for (int it = 0; it < NITER; it++) {
        cp_wait<STAGES - 2>();
        __syncthreads();
        load_stage((it + STAGES - 1) % STAGES, it + STAGES - 1);

        const int st = it % STAGES;
        const bf16* Ahs = &sA[(st * 2 + 0) * ASZ];
        const bf16* Als = &sA[(st * 2 + 1) * ASZ];
        const bf16* Bhs = &sB[(st * 2 + 0) * BSZ];
        const bf16* Bls = &sB[(st * 2 + 1) * BSZ];

        #pragma unroll
        for (int ks = 0; ks < 2; ks++) {
            const int k0 = ks * 16;
            uint32_t ah[MI][4], al[MI][4], bh[NI][2], bl[NI][2];
            #pragma unroll
            for (int mi = 0; mi < MI; mi++) {
                int r = wm * WM + mi * 16 + (lane & 15);
                int c = k0 + (lane >> 4) * 8;
                ldsm_x4(ah[mi], Ahs + r * AP + c);
                ldsm_x4(al[mi], Als + r * AP + c);
            }
            #pragma unroll
            for (int ni = 0; ni < NI; ni++) {
                int r = k0 + (lane & 15);
                int c = wn * WN + ni * 8;
                ldsm_x2t(bh[ni], Bhs + r * BP + c);
                ldsm_x2t(bl[ni], Bls + r * BP + c);
            }
            #pragma unroll
            for (int mi = 0; mi < MI; mi++)
                #pragma unroll
                for (int ni = 0; ni < NI; ni++) {
                    mma_bf16(acc[mi][ni], ah[mi], bh[ni]);
                    mma_bf16(acc[mi][ni], ah[mi], bl[ni]);
                    mma_bf16(acc[mi][ni], al[mi], bh[ni]);
                }
        }
    }

    #pragma unroll
    for (int mi = 0; mi < MI; mi++)
        #pragma unroll
        for (int ni = 0; ni < NI; ni++) {
            int r = row0 + wm * WM + mi * 16 + lane / 4;
            int c = col0 + wn * WN + ni * 8 + 2 * (lane % 4);
            *reinterpret_cast<float2*>(&C[(size_t)r * N + c]) =
                make_float2(acc[mi][ni][0], acc[mi][ni][1]);
            *reinterpret_cast<float2*>(&C[(size_t)(r + 8) * N + c]) =
                make_float2(acc[mi][ni][2], acc[mi][ni][3]);
        }
}

// ---------------- main GEMM: out = x @ R, 3-stage, fp32 x converted in-kernel ----
__global__ __launch_bounds__(256, 2)
void xr_gemm(const float* __restrict__ X,
             const bf16* __restrict__ Bh, const bf16* __restrict__ Bl,
             float* __restrict__ C, int M, int N, int K)
{
    constexpr int BM = 128, BN = 128, BK = 32;
    constexpr int AP = BK + 8;
    constexpr int BP = BN + 8;
    constexpr int ASZ = BM * AP;
    constexpr int BSZ = BK * BP;
    constexpr int MI = 4, NI = 4;
    constexpr int ST = 3;

    extern __shared__ bf16 smem[];
    bf16* sA = smem;
    bf16* sB = smem + ST * 2 * ASZ;

    const int tid = threadIdx.x, lane = tid & 31, wid = tid >> 5;
    const int wm = wid >> 2, wn = wid & 3;
    const int row0 = blockIdx.y * BM, col0 = blockIdx.x * BN;
    const int NITER = K / BK;

    float acc[MI][NI][4];
    #pragma unroll
    for (int mi = 0; mi < MI; mi++)
        #pragma unroll
        for (int ni = 0; ni < NI; ni++)
            #pragma unroll
            for (int r = 0; r < 4; r++) acc[mi][ni][r] = 0.f;

    float4 av[4];
    auto ldgA = [&](int iter) {
        int k0 = iter * BK;
        #pragma unroll
        for (int i = 0; i < 4; i++) {
            int f4 = tid + i * 256;
            int r = f4 >> 3, c4 = f4 & 7;
            av[i] = *reinterpret_cast<const float4*>(
                &X[(size_t)(row0 + r) * K + k0 + c4 * 4]);
        }
    };
    auto stsA = [&](int st) {
        #pragma unroll
        for (int i = 0; i < 4; i++) {
            int f4 = tid + i * 256;
            int r = f4 >> 3, c4 = f4 & 7;
            float f[4] = {av[i].x, av[i].y, av[i].z, av[i].w};
            union { bf16 b[4]; uint2 u; } H, L;
            #pragma unroll
            for (int j = 0; j < 4; j++) {
                bf16 h = __float2bfloat16(f[j]);
                H.b[j] = h;
                L.b[j] = __float2bfloat16(f[j] - __bfloat162float(h));
            }
            *reinterpret_cast<uint2*>(&sA[(st * 2 + 0) * ASZ + r * AP + c4 * 4]) = H.u;
            *reinterpret_cast<uint2*>(&sA[(st * 2 + 1) * ASZ + r * AP + c4 * 4]) = L.u;
        }
    };
    auto cpB = [&](int st, int iter) {
        if (iter < NITER) {
            int k0 = iter * BK;
            #pragma unroll
            for (int s = 0; s < 2; s++) {
                const bf16* g = s ? Bl : Bh;
                #pragma unroll
                for (int i = 0; i < 2; i++) {
                    int c = tid + i * 256;
                    int r = c >> 4, cc = c & 15;
                    cp16(&sB[(st * 2 + s) * BSZ + r * BP + cc * 8],
                         g + (size_t)(k0 + r) * N + col0 + cc * 8);
                }
            }
        }
        cp_commit();
    };

    ldgA(0);
    stsA(0);
    cpB(0, 0);
    ldgA(1);
    cpB(1, 1);

    for (int it = 0; it < NITER; it++) {
        cp_wait<1>();
        __syncthreads();

        const int st = it % ST;
        const bf16* Ahs = &sA[(st * 2 + 0) * ASZ];
        const bf16* Als = &sA[(st * 2 + 1) * ASZ];
        const bf16* Bhs = &sB[(st * 2 + 0) * BSZ];
        const bf16* Bls = &sB[(st * 2 + 1) * BSZ];

        #pragma unroll
        for (int ks = 0; ks < 2; ks++) {
            const int k0 = ks * 16;
            uint32_t ah[MI][4], al[MI][4], bh[NI][2], bl[NI][2];
            #pragma unroll
            for (int mi = 0; mi < MI; mi++) {
                int r = wm * 64 + mi * 16 + (lane & 15);
                int c = k0 + (lane >> 4) * 8;
                ldsm_x4(ah[mi], Ahs + r * AP + c);
                ldsm_x4(al[mi], Als + r * AP + c);
            }
            #pragma unroll
            for (int ni = 0; ni < NI; ni++) {
                int r = k0 + (lane & 15);
                int c = wn * 32 + ni * 8;
                ldsm_x2t(bh[ni], Bhs + r * BP + c);
                ldsm_x2t(bl[ni], Bls + r * BP + c);
            }
            #pragma unroll
            for (int mi = 0; mi < MI; mi++)
                #pragma unroll
                for (int ni = 0; ni < NI; ni++) {
                    mma_bf16(acc[mi][ni], ah[mi], bh[ni]);
                    mma_bf16(acc[mi][ni], ah[mi], bl[ni]);
                    mma_bf16(acc[mi][ni], al[mi], bh[ni]);
                }
        }

        if (it + 1 < NITER) stsA((it + 1) % ST);
        if (it + 2 < NITER) ldgA(it + 2);
        cpB((it + 2) % ST, it + 2);
    }

    #pragma unroll
    for (int mi = 0; mi < MI; mi++)
        #pragma unroll
        for (int ni = 0; ni < NI; ni++) {
            int r = row0 + wm * 64 + mi * 16 + lane / 4;
            int c = col0 + wn * 32 + ni * 8 + 2 * (lane % 4);
            *reinterpret_cast<float2*>(&C[(size_t)r * N + c]) =
                make_float2(acc[mi][ni][0], acc[mi][ni][1]);
            *reinterpret_cast<float2*>(&C[(size_t)(r + 8) * N + c]) =
                make_float2(acc[mi][ni][2], acc[mi][ni][3]);
        }
}

// ---------------- launch ----------------
extern "C" void kernel_launch(void* const* d_in, const int* in_sizes, int n_in,
                              void* d_out, int out_size)
{
    const float* x = (const float*)d_in[0];
    const float* W = (const float*)d_in[1];
    float* out = (float*)d_out;
    const int M = in_sizes[0] / DIM;   // 16384

    float *B, *B2, *B3, *Pt;
    cudaGetSymbolAddress((void**)&B,  g_B);
    cudaGetSymbolAddress((void**)&B2, g_B2);
    cudaGetSymbolAddress((void**)&B3, g_B3);
    cudaGetSymbolAddress((void**)&Pt, g_part);
    bf16 *Bh,*Bl,*B2h,*B2l,*B3h,*B3l,*Qh,*Ql,*Th,*Tl,*Rh,*Rl;
    cudaGetSymbolAddress((void**)&Bh,  s_Bh);  cudaGetSymbolAddress((void**)&Bl,  s_Bl);
    cudaGetSymbolAddress((void**)&B2h, s_B2h); cudaGetSymbolAddress((void**)&B2l, s_B2l);
    cudaGetSymbolAddress((void**)&B3h, s_B3h); cudaGetSymbolAddress((void**)&B3l, s_B3l);
    cudaGetSymbolAddress((void**)&Qh,  s_Qh);  cudaGetSymbolAddress((void**)&Ql,  s_Ql);
    cudaGetSymbolAddress((void**)&Th,  s_Th);  cudaGetSymbolAddress((void**)&Tl,  s_Tl);
    cudaGetSymbolAddress((void**)&Rh,  s_Rh);  cudaGetSymbolAddress((void**)&Rl,  s_Rl);

    // chain tile 128x64, 2 stages: 2*2*(128*40 + 32*72)*2 = 59392
    constexpr int SMEM_CHAIN = 2 * 2 * (128 * 40 + 32 * 72) * 2;
    constexpr int SMEM_MAIN  = 3 * 2 * (128 * 40 + 32 * 136) * 2;       // 113664
    cudaFuncSetAttribute(mma_gemm<128,64,64,32,128,2>,
                         cudaFuncAttributeMaxDynamicSharedMemorySize, SMEM_CHAIN);
    cudaFuncSetAttribute(xr_gemm,
                         cudaFuncAttributeMaxDynamicSharedMemorySize, SMEM_MAIN);

    const dim3 gS(DIM / 64, DIM / 128, SPLITK);   // (16, 8, 8) = 1024 CTAs
    const int  rb = DIM * DIM / 1024;

    // B = (W - W^T)/2, fused split
    skew_split_kernel<<<dim3(DIM / 32, DIM / 32), dim3(32, 8)>>>(W, B, Bh, Bl);

    // G1: B2 = B@B -> fp32 B2 + split
    mma_gemm<128,64,64,32,128,2><<<gS, 128, SMEM_CHAIN>>>(Bh, Bl, Bh, Bl, Pt, DIM, DIM, DIM);
    reduce_split<SPLITK,false,true,false,false><<<rb, 256>>>(Pt, B2, B2h, B2l,
        nullptr, nullptr, nullptr, 0.f, 0.f, 0.f, 0.f, nullptr, nullptr, 0.f, 0.f, 0.f, 0.f);

    // G2: B3 = B2@B -> fp32 B3 + split, AND Q = B/24 + B2/120 + B3/720 (split)
    mma_gemm<128,64,64,32,128,2><<<gS, 128, SMEM_CHAIN>>>(B2h, B2l, Bh, Bl, Pt, DIM, DIM, DIM);
    reduce_split<SPLITK,false,true,true,false><<<rb, 256>>>(Pt, B3, B3h, B3l,
        B, B2, nullptr, 0.f, 0.f, 0.f, 0.f, Qh, Ql, 0.f, 1.f/24.f, 1.f/120.f, 1.f/720.f);

    // G3: T = Q@B3 + I + B + B2/2 + B3/6  (degree-6 Paterson-Stockmeyer)
    mma_gemm<128,64,64,32,128,2><<<gS, 128, SMEM_CHAIN>>>(Qh, Ql, B3h, B3l, Pt, DIM, DIM, DIM);
    reduce_split<SPLITK,true,false,false,true><<<rb, 256>>>(Pt, nullptr, Th, Tl,
        B, B2, B3, 1.f, 1.f, 0.5f, 1.f/6.f, nullptr, nullptr, 0.f, 0.f, 0.f, 0.f);

    // G4: R = T@T (undo scaling)
    mma_gemm<128,64,64,32,128,2><<<gS, 128, SMEM_CHAIN>>>(Th, Tl, Th, Tl, Pt, DIM, DIM, DIM);
    reduce_split<SPLITK,false,false,false,false><<<rb, 256>>>(Pt, nullptr, Rh, Rl,
        nullptr, nullptr, nullptr, 0.f, 0.f, 0.f, 0.f, nullptr, nullptr, 0.f, 0.f, 0.f, 0.f);

    // main: out = x @ R (fp32 x converted in-kernel, 3-stage)
    xr_gemm<<<dim3(DIM / 128, M / 128), 256, SMEM_MAIN>>>(x, Rh, Rl, out, M, DIM, DIM);
}

// round 14
// speedup vs baseline: 3.2681x; 1.0271x over previous
#include <cuda_runtime.h>
#include <cuda_bf16.h>
#include <cstdint>

typedef __nv_bfloat16 bf16;
#define DIM 1024
#define SPLITK 4

// ---------------- scratch (static device globals; no allocation) ----------------
__device__ float g_B   [DIM*DIM];
__device__ float g_B2  [DIM*DIM];
__device__ float g_B3  [DIM*DIM];
__device__ float g_part[SPLITK*DIM*DIM];

__device__ bf16 s_Bh [DIM*DIM], s_Bl [DIM*DIM];
__device__ bf16 s_B2h[DIM*DIM], s_B2l[DIM*DIM];
__device__ bf16 s_B3h[DIM*DIM], s_B3l[DIM*DIM];
__device__ bf16 s_Qh [DIM*DIM], s_Ql [DIM*DIM];
__device__ bf16 s_Th [DIM*DIM], s_Tl [DIM*DIM];
__device__ bf16 s_Rh [DIM*DIM], s_Rl [DIM*DIM];

// ---------------- fused skew + split (coalesced via smem transpose tile) --------
__global__ void skew_split_kernel(const float* __restrict__ W, float* __restrict__ B,
                                  bf16* __restrict__ hi, bf16* __restrict__ lo) {
    __shared__ float t[32][33];
    int tx = threadIdx.x, ty = threadIdx.y;          // 32 x 8
    int bx = blockIdx.x * 32, by = blockIdx.y * 32;
    #pragma unroll
    for (int i = 0; i < 4; i++)
        t[ty + i * 8][tx] = W[(size_t)(bx + ty + i * 8) * DIM + by + tx];
    __syncthreads();
    #pragma unroll
    for (int i = 0; i < 4; i++) {
        int r = by + ty + i * 8, c = bx + tx;
        float v = 0.5f * (W[(size_t)r * DIM + c] - t[tx][ty + i * 8]);
        B[(size_t)r * DIM + c] = v;
        bf16 h = __float2bfloat16(v);
        hi[(size_t)r * DIM + c] = h;
        lo[(size_t)r * DIM + c] = __float2bfloat16(v - __bfloat162float(h));
    }
}

// ---------------- fused reduce(+comb)(+split)(+second comb) ----------------
template<int NPART, bool COMB, bool WF32, bool COMB2, bool HAS3>
__global__ void reduce_split(const float* __restrict__ part, float* __restrict__ f32out,
                             bf16* __restrict__ hi, bf16* __restrict__ lo,
                             const float* __restrict__ Bm, const float* __restrict__ B2m,
                             const float* __restrict__ B3m,
                             float a, float b, float c, float e,
                             bf16* __restrict__ hi2, bf16* __restrict__ lo2,
                             float a2, float b2, float c2, float e2)
{
    constexpr int SZ4 = DIM * DIM / 4;
    int i = blockIdx.x * 256 + threadIdx.x;
    float f[4] = {0.f, 0.f, 0.f, 0.f};
    #pragma unroll
    for (int p = 0; p < NPART; p++) {
        float4 t = reinterpret_cast<const float4*>(part)[p * SZ4 + i];
        f[0] += t.x; f[1] += t.y; f[2] += t.z; f[3] += t.w;
    }
    float bmv[4], b2v[4];
    if (COMB || COMB2) {
        float4 t1 = reinterpret_cast<const float4*>(Bm)[i];
        bmv[0] = t1.x; bmv[1] = t1.y; bmv[2] = t1.z; bmv[3] = t1.w;
        float4 t2 = reinterpret_cast<const float4*>(B2m)[i];
        b2v[0] = t2.x; b2v[1] = t2.y; b2v[2] = t2.z; b2v[3] = t2.w;
    }
    int e0 = i * 4;
    int d = (e0 >> 10) - (e0 & (DIM - 1));
    if (COMB) {
        #pragma unroll
        for (int j = 0; j < 4; j++) f[j] += b * bmv[j] + c * b2v[j];
        if (HAS3) {
            float4 t3 = reinterpret_cast<const float4*>(B3m)[i];
            f[0] += e * t3.x; f[1] += e * t3.y; f[2] += e * t3.z; f[3] += e * t3.w;
        }
        if (d >= 0 && d < 4) f[d] += a;
    }
    if (WF32) {
        float4 o; o.x = f[0]; o.y = f[1]; o.z = f[2]; o.w = f[3];
        reinterpret_cast<float4*>(f32out)[i] = o;
    }
    union { bf16 b[4]; uint2 u; } H, L;
    #pragma unroll
    for (int j = 0; j < 4; j++) {
        bf16 h = __float2bfloat16(f[j]);
        H.b[j] = h;
        L.b[j] = __float2bfloat16(f[j] - __bfloat162float(h));
    }
    reinterpret_cast<uint2*>(hi)[i] = H.u;
    reinterpret_cast<uint2*>(lo)[i] = L.u;

    if (COMB2) {
        float g[4];
        #pragma unroll
        for (int j = 0; j < 4; j++) g[j] = b2 * bmv[j] + c2 * b2v[j] + e2 * f[j];
        if (d >= 0 && d < 4) g[d] += a2;
        union { bf16 b[4]; uint2 u; } H2, L2;
        #pragma unroll
        for (int j = 0; j < 4; j++) {
            bf16 h = __float2bfloat16(g[j]);
            H2.b[j] = h;
            L2.b[j] = __float2bfloat16(g[j] - __bfloat162float(h));
        }
        reinterpret_cast<uint2*>(hi2)[i] = H2.u;
        reinterpret_cast<uint2*>(lo2)[i] = L2.u;
    }
}

// ---------------- async-copy / mma helpers ----------------
__device__ __forceinline__ void cp16(void* dst, const void* src) {
    unsigned d = (unsigned)__cvta_generic_to_shared(dst);
    asm volatile("cp.async.cg.shared.global [%0], [%1], 16;" :: "r"(d), "l"(src));
}
__device__ __forceinline__ void cp_commit() { asm volatile("cp.async.commit_group;"); }
template<int N>
__device__ __forceinline__ void cp_wait() { asm volatile("cp.async.wait_group %0;" :: "n"(N)); }

__device__ __forceinline__ void ldsm_x4(uint32_t a[4], const bf16* p) {
    unsigned s = (unsigned)__cvta_generic_to_shared(p);
    asm volatile("ldmatrix.sync.aligned.m8n8.x4.shared.b16 {%0,%1,%2,%3}, [%4];"
                 : "=r"(a[0]), "=r"(a[1]), "=r"(a[2]), "=r"(a[3]) : "r"(s));
}
__device__ __forceinline__ void ldsm_x2t(uint32_t b[2], const bf16* p) {
    unsigned s = (unsigned)__cvta_generic_to_shared(p);
    asm volatile("ldmatrix.sync.aligned.m8n8.x2.trans.shared.b16 {%0,%1}, [%2];"
                 : "=r"(b[0]), "=r"(b[1]) : "r"(s));
}
__device__ __forceinline__ void mma_bf16(float d[4], const uint32_t a[4], const uint32_t b[2]) {
    asm volatile("mma.sync.aligned.m16n8k16.row.col.f32.bf16.bf16.f32 "
                 "{%0,%1,%2,%3}, {%4,%5,%6,%7}, {%8,%9}, {%0,%1,%2,%3};"
                 : "+f"(d[0]), "+f"(d[1]), "+f"(d[2]), "+f"(d[3])
                 : "r"(a[0]), "r"(a[1]), "r"(a[2]), "r"(a[3]), "r"(b[0]), "r"(b[1]));
}

// ---------------- split-bf16 mma.sync GEMM (expm chain, split-K) ----------------
template<int BM, int BN, int WM, int WN, int THREADS, int STAGES>
__global__ __launch_bounds__(THREADS)
void mma_gemm(const bf16* __restrict__ Ah, const bf16* __restrict__ Al,
              const bf16* __restrict__ Bh, const bf16* __restrict__ Bl,
              float* __restrict__ C, int M, int N, int K)
{
    constexpr int BK = 32;
    constexpr int AP = BK + 8;
    constexpr int BP = BN + 8;
    constexpr int ASZ = BM * AP;
    constexpr int BSZ = BK * BP;
    constexpr int MI = WM / 16, NI = WN / 8;
    constexpr int WNC = BN / WN;
    constexpr int AC = (BM * BK / 8) / THREADS;
    constexpr int BC = (BK * BN / 8) / THREADS;

    extern __shared__ bf16 smem[];
    bf16* sA = smem;
    bf16* sB = smem + STAGES * 2 * ASZ;

    const int tid = threadIdx.x, lane = tid & 31, wid = tid >> 5;
    const int wm = wid / WNC, wn = wid % WNC;
    const int row0 = blockIdx.y * BM, col0 = blockIdx.x * BN;

    const int kchunk = K / gridDim.z;
    const int kbeg   = blockIdx.z * kchunk;
    const int NITER  = kchunk / BK;
    C += (size_t)blockIdx.z * (size_t)M * N;

    float acc[MI][NI][4];
    #pragma unroll
    for (int mi = 0; mi < MI; mi++)
        #pragma unroll
        for (int ni = 0; ni < NI; ni++)
            #pragma unroll
            for (int r = 0; r < 4; r++) acc[mi][ni][r] = 0.f;

    auto load_stage = [&](int st, int iter) {
        if (iter < NITER) {
            int k0 = kbeg + iter * BK;
            #pragma unroll
            for (int s = 0; s < 2; s++) {
                const bf16* gA = s ? Al : Ah;
                #pragma unroll
                for (int i = 0; i < AC; i++) {
                    int c = tid + i * THREADS;
                    int r = c / (BK / 8), cc = c % (BK / 8);
                    cp16(&sA[(st * 2 + s) * ASZ + r * AP + cc * 8],
                         gA + (size_t)(row0 + r) * K + k0 + cc * 8);
                }
                const bf16* gB = s ? Bl : Bh;
                #pragma unroll
                for (int i = 0; i < BC; i++) {
                    int c = tid + i * THREADS;
                    int r = c / (BN / 8), cc = c % (BN / 8);
                    cp16(&sB[(st * 2 + s) * BSZ + r * BP + cc * 8],
                         gB + (size_t)(k0 + r) * N + col0 + cc * 8);
                }
            }
        }
        cp_commit();
    };

    #pragma unroll
    for (int s = 0; s < STAGES - 1; s++) load_stage(s, s);

    for (int it = 0; it < NITER; it++) {
        cp_wait<STAGES - 2>();
        __syncthreads();
        load_stage((it + STAGES - 1) % STAGES, it + STAGES - 1);

        const int st = it % STAGES;
        const bf16* Ahs = &sA[(st * 2 + 0) * ASZ];
        const bf16* Als = &sA[(st * 2 + 1) * ASZ];
        const bf16* Bhs = &sB[(st * 2 + 0) * BSZ];
        const bf16* Bls = &sB[(st * 2 + 1) * BSZ];

        #pragma unroll
        for (int ks = 0; ks < 2; ks++) {
            const int k0 = ks * 16;
            uint32_t ah[MI][4], al[MI][4], bh[NI][2], bl[NI][2];
            #pragma unroll
            for (int mi = 0; mi < MI; mi++) {
                int r = wm * WM + mi * 16 + (lane & 15);
                int c = k0 + (lane >> 4) * 8;
                ldsm_x4(ah[mi], Ahs + r * AP + c);
                ldsm_x4(al[mi], Als + r * AP + c);
            }
            #pragma unroll
            for (int ni = 0; ni < NI; ni++) {
                int r = k0 + (lane & 15);
                int c = wn * WN + ni * 8;
                ldsm_x2t(bh[ni], Bhs + r * BP + c);
                ldsm_x2t(bl[ni], Bls + r * BP + c);
            }
            #pragma unroll
            for (int mi = 0; mi < MI; mi++)
                #pragma unroll
                for (int ni = 0; ni < NI; ni++) {
                    mma_bf16(acc[mi][ni], ah[mi], bh[ni]);
                    mma_bf16(acc[mi][ni], ah[mi], bl[ni]);
                    mma_bf16(acc[mi][ni], al[mi], bh[ni]);
                }
        }
    }

    #pragma unroll
    for (int mi = 0; mi < MI; mi++)
        #pragma unroll
        for (int ni = 0; ni < NI; ni++) {
            int r = row0 + wm * WM + mi * 16 + lane / 4;
            int c = col0 + wn * WN + ni * 8 + 2 * (lane % 4);
            *reinterpret_cast<float2*>(&C[(size_t)r * N + c]) =
                make_float2(acc[mi][ni][0], acc[mi][ni][1]);
            *reinterpret_cast<float2*>(&C[(size_t)(r + 8) * N + c]) =
                make_float2(acc[mi][ni][2], acc[mi][ni][3]);
        }
}

// ---------------- main GEMM: out = x @ R, 3-stage, fp32 x converted in-kernel ----
__global__ __launch_bounds__(256, 2)
void xr_gemm(const float* __restrict__ X,
             const bf16* __restrict__ Bh, const bf16* __restrict__ Bl,
             float* __restrict__ C, int M, int N, int K)
{
    constexpr int BM = 128, BN = 128, BK = 32;
    constexpr int AP = BK + 8;
    constexpr int BP = BN + 8;
    constexpr int ASZ = BM * AP;
    constexpr int BSZ = BK * BP;
    constexpr int MI = 4, NI = 4;
    constexpr int ST = 3;

    extern __shared__ bf16 smem[];
    bf16* sA = smem;
    bf16* sB = smem + ST * 2 * ASZ;

    const int tid = threadIdx.x, lane = tid & 31, wid = tid >> 5;
    const int wm = wid >> 2, wn = wid & 3;
    const int row0 = blockIdx.y * BM, col0 = blockIdx.x * BN;
    const int NITER = K / BK;

    float acc[MI][NI][4];
    #pragma unroll
    for (int mi = 0; mi < MI; mi++)
        #pragma unroll
        for (int ni = 0; ni < NI; ni++)
            #pragma unroll
            for (int r = 0; r < 4; r++) acc[mi][ni][r] = 0.f;

    float4 av[4];
    auto ldgA = [&](int iter) {
        int k0 = iter * BK;
        #pragma unroll
        for (int i = 0; i < 4; i++) {
            int f4 = tid + i * 256;
            int r = f4 >> 3, c4 = f4 & 7;
            av[i] = *reinterpret_cast<const float4*>(
                &X[(size_t)(row0 + r) * K + k0 + c4 * 4]);
        }
    };
    auto stsA = [&](int st) {
        #pragma unroll
        for (int i = 0; i < 4; i++) {
            int f4 = tid + i * 256;
            int r = f4 >> 3, c4 = f4 & 7;
            float f[4] = {av[i].x, av[i].y, av[i].z, av[i].w};
            union { bf16 b[4]; uint2 u; } H, L;
            #pragma unroll
            for (int j = 0; j < 4; j++) {
                bf16 h = __float2bfloat16(f[j]);
                H.b[j] = h;
                L.b[j] = __float2bfloat16(f[j] - __bfloat162float(h));
            }
            *reinterpret_cast<uint2*>(&sA[(st * 2 + 0) * ASZ + r * AP + c4 * 4]) = H.u;
            *reinterpret_cast<uint2*>(&sA[(st * 2 + 1) * ASZ + r * AP + c4 * 4]) = L.u;
        }
    };
    auto cpB = [&](int st, int iter) {
        if (iter < NITER) {
            int k0 = iter * BK;
            #pragma unroll
            for (int s = 0; s < 2; s++) {
                const bf16* g = s ? Bl : Bh;
                #pragma unroll
                for (int i = 0; i < 2; i++) {
                    int c = tid + i * 256;
                    int r = c >> 4, cc = c & 15;
                    cp16(&sB[(st * 2 + s) * BSZ + r * BP + cc * 8],
                         g + (size_t)(k0 + r) * N + col0 + cc * 8);
                }
            }
        }
        cp_commit();
    };

    ldgA(0);
    stsA(0);
    cpB(0, 0);
    ldgA(1);
    cpB(1, 1);

    for (int it = 0; it < NITER; it++) {
        cp_wait<1>();
        __syncthreads();

        const int st = it % ST;
        const bf16* Ahs = &sA[(st * 2 + 0) * ASZ];
        const bf16* Als = &sA[(st * 2 + 1) * ASZ];
        const bf16* Bhs = &sB[(st * 2 + 0) * BSZ];
        const bf16* Bls = &sB[(st * 2 + 1) * BSZ];

        #pragma unroll
        for (int ks = 0; ks < 2; ks++) {
            const int k0 = ks * 16;
            uint32_t ah[MI][4], al[MI][4], bh[NI][2], bl[NI][2];
            #pragma unroll
            for (int mi = 0; mi < MI; mi++) {
                int r = wm * 64 + mi * 16 + (lane & 15);
                int c = k0 + (lane >> 4) * 8;
                ldsm_x4(ah[mi], Ahs + r * AP + c);
                ldsm_x4(al[mi], Als + r * AP + c);
            }
            #pragma unroll
            for (int ni = 0; ni < NI; ni++) {
                int r = k0 + (lane & 15);
                int c = wn * 32 + ni * 8;
                ldsm_x2t(bh[ni], Bhs + r * BP + c);
                ldsm_x2t(bl[ni], Bls + r * BP + c);
            }
            #pragma unroll
            for (int mi = 0; mi < MI; mi++)
                #pragma unroll
                for (int ni = 0; ni < NI; ni++) {
                    mma_bf16(acc[mi][ni], ah[mi], bh[ni]);
                    mma_bf16(acc[mi][ni], ah[mi], bl[ni]);
                    mma_bf16(acc[mi][ni], al[mi], bh[ni]);
                }
        }

        if (it + 1 < NITER) stsA((it + 1) % ST);
        if (it + 2 < NITER) ldgA(it + 2);
        cpB((it + 2) % ST, it + 2);
    }

    #pragma unroll
    for (int mi = 0; mi < MI; mi++)
        #pragma unroll
        for (int ni = 0; ni < NI; ni++) {
            int r = row0 + wm * 64 + mi * 16 + lane / 4;
            int c = col0 + wn * 32 + ni * 8 + 2 * (lane % 4);
            *reinterpret_cast<float2*>(&C[(size_t)r * N + c]) =
                make_float2(acc[mi][ni][0], acc[mi][ni][1]);
            *reinterpret_cast<float2*>(&C[(size_t)(r + 8) * N + c]) =
                make_float2(acc[mi][ni][2], acc[mi][ni][3]);
        }
}

// ---------------- launch ----------------
extern "C" void kernel_launch(void* const* d_in, const int* in_sizes, int n_in,
                              void* d_out, int out_size)
{
    const float* x = (const float*)d_in[0];
    const float* W = (const float*)d_in[1];
    float* out = (float*)d_out;
    const int M = in_sizes[0] / DIM;   // 16384

    float *B, *B2, *B3, *Pt;
    cudaGetSymbolAddress((void**)&B,  g_B);
    cudaGetSymbolAddress((void**)&B2, g_B2);
    cudaGetSymbolAddress((void**)&B3, g_B3);
    cudaGetSymbolAddress((void**)&Pt, g_part);
    bf16 *Bh,*Bl,*B2h,*B2l,*B3h,*B3l,*Qh,*Ql,*Th,*Tl,*Rh,*Rl;
    cudaGetSymbolAddress((void**)&Bh,  s_Bh);  cudaGetSymbolAddress((void**)&Bl,  s_Bl);
    cudaGetSymbolAddress((void**)&B2h, s_B2h); cudaGetSymbolAddress((void**)&B2l, s_B2l);
    cudaGetSymbolAddress((void**)&B3h, s_B3h); cudaGetSymbolAddress((void**)&B3l, s_B3l);
    cudaGetSymbolAddress((void**)&Qh,  s_Qh);  cudaGetSymbolAddress((void**)&Ql,  s_Ql);
    cudaGetSymbolAddress((void**)&Th,  s_Th);  cudaGetSymbolAddress((void**)&Tl,  s_Tl);
    cudaGetSymbolAddress((void**)&Rh,  s_Rh);  cudaGetSymbolAddress((void**)&Rl,  s_Rl);

    constexpr int SMEM_CHAIN = 2 * 2 * (64 * 40 + 32 * 72) * 2;         // 38912
    constexpr int SMEM_MAIN  = 3 * 2 * (128 * 40 + 32 * 136) * 2;       // 113664
    cudaFuncSetAttribute(mma_gemm<64,64,32,32,128,2>,
                         cudaFuncAttributeMaxDynamicSharedMemorySize, SMEM_CHAIN);
    cudaFuncSetAttribute(xr_gemm,
                         cudaFuncAttributeMaxDynamicSharedMemorySize, SMEM_MAIN);

    const dim3 gS(DIM / 64, DIM / 64, SPLITK);    // (16, 16, 4) = 1024 CTAs
    const int  rb = DIM * DIM / 1024;

    // B = (W - W^T)/2, fused split
    skew_split_kernel<<<dim3(DIM / 32, DIM / 32), dim3(32, 8)>>>(W, B, Bh, Bl);

    // G1: B2 = B@B -> fp32 B2 + split
    mma_gemm<64,64,32,32,128,2><<<gS, 128, SMEM_CHAIN>>>(Bh, Bl, Bh, Bl, Pt, DIM, DIM, DIM);
    reduce_split<SPLITK,false,true,false,false><<<rb, 256>>>(Pt, B2, B2h, B2l,
        nullptr, nullptr, nullptr, 0.f, 0.f, 0.f, 0.f, nullptr, nullptr, 0.f, 0.f, 0.f, 0.f);

    // G2: B3 = B2@B -> fp32 B3 + split, AND Q = B/24 + B2/120 + B3/720 (split)
    mma_gemm<64,64,32,32,128,2><<<gS, 128, SMEM_CHAIN>>>(B2h, B2l, Bh, Bl, Pt, DIM, DIM, DIM);
    reduce_split<SPLITK,false,true,true,false><<<rb, 256>>>(Pt, B3, B3h, B3l,
        B, B2, nullptr, 0.f, 0.f, 0.f, 0.f, Qh, Ql, 0.f, 1.f/24.f, 1.f/120.f, 1.f/720.f);

    // G3: T = Q@B3 + I + B + B2/2 + B3/6  (degree-6 Paterson-Stockmeyer)
    mma_gemm<64,64,32,32,128,2><<<gS, 128, SMEM_CHAIN>>>(Qh, Ql, B3h, B3l, Pt, DIM, DIM, DIM);
    reduce_split<SPLITK,true,false,false,true><<<rb, 256>>>(Pt, nullptr, Th, Tl,
        B, B2, B3, 1.f, 1.f, 0.5f, 1.f/6.f, nullptr, nullptr, 0.f, 0.f, 0.f, 0.f);

    // G4: R = T@T (undo scaling)
    mma_gemm<64,64,32,32,128,2><<<gS, 128, SMEM_CHAIN>>>(Th, Tl, Th, Tl, Pt, DIM, DIM, DIM);
    reduce_split<SPLITK,false,false,false,false><<<rb, 256>>>(Pt, nullptr, Rh, Rl,
        nullptr, nullptr, nullptr, 0.f, 0.f, 0.f, 0.f, nullptr, nullptr, 0.f, 0.f, 0.f, 0.f);

    // main: out = x @ R (fp32 x converted in-kernel, 3-stage)
    xr_gemm<<<dim3(DIM / 128, M / 128), 256, SMEM_MAIN>>>(x, Rh, Rl, out, M, DIM, DIM);
}

// round 15
// speedup vs baseline: 4.2169x; 1.2903x over previous
#include <cuda_runtime.h>
#include <cuda_bf16.h>
#include <cuda_fp16.h>
#include <cstdint>

typedef __nv_bfloat16 bf16;
#define DIM 1024
#define SPLITK 4
#define RSCALE 256.0f
#define RISCALE 0.00390625f

// ---------------- scratch (static device globals; no allocation) ----------------
__device__ float g_B   [DIM*DIM];
__device__ float g_B2  [DIM*DIM];
__device__ float g_B3  [DIM*DIM];
__device__ float g_part[SPLITK*DIM*DIM];

__device__ bf16 s_Bh [DIM*DIM], s_Bl [DIM*DIM];
__device__ bf16 s_B2h[DIM*DIM], s_B2l[DIM*DIM];
__device__ bf16 s_B3h[DIM*DIM], s_B3l[DIM*DIM];
__device__ bf16 s_Qh [DIM*DIM], s_Ql [DIM*DIM];
__device__ bf16 s_Th [DIM*DIM], s_Tl [DIM*DIM];
__device__ __half s_Rh16[DIM*DIM], s_Rl16[DIM*DIM];   // 256*R fp16 hi/lo

// ---------------- fused skew + split (coalesced via smem transpose tile) --------
__global__ void skew_split_kernel(const float* __restrict__ W, float* __restrict__ B,
                                  bf16* __restrict__ hi, bf16* __restrict__ lo) {
    __shared__ float t[32][33];
    int tx = threadIdx.x, ty = threadIdx.y;          // 32 x 8
    int bx = blockIdx.x * 32, by = blockIdx.y * 32;
    #pragma unroll
    for (int i = 0; i < 4; i++)
        t[ty + i * 8][tx] = W[(size_t)(bx + ty + i * 8) * DIM + by + tx];
    __syncthreads();
    #pragma unroll
    for (int i = 0; i < 4; i++) {
        int r = by + ty + i * 8, c = bx + tx;
        float v = 0.5f * (W[(size_t)r * DIM + c] - t[tx][ty + i * 8]);
        B[(size_t)r * DIM + c] = v;
        bf16 h = __float2bfloat16(v);
        hi[(size_t)r * DIM + c] = h;
        lo[(size_t)r * DIM + c] = __float2bfloat16(v - __bfloat162float(h));
    }
}

// ---------------- fused reduce(+comb)(+split)(+second comb) ----------------
template<int NPART, bool COMB, bool WF32, bool COMB2, bool HAS3>
__global__ void reduce_split(const float* __restrict__ part, float* __restrict__ f32out,
                             bf16* __restrict__ hi, bf16* __restrict__ lo,
                             const float* __restrict__ Bm, const float* __restrict__ B2m,
                             const float* __restrict__ B3m,
                             float a, float b, float c, float e,
                             bf16* __restrict__ hi2, bf16* __restrict__ lo2,
                             float a2, float b2, float c2, float e2)
{
    constexpr int SZ4 = DIM * DIM / 4;
    int i = blockIdx.x * 256 + threadIdx.x;
    float f[4] = {0.f, 0.f, 0.f, 0.f};
    #pragma unroll
    for (int p = 0; p < NPART; p++) {
        float4 t = reinterpret_cast<const float4*>(part)[p * SZ4 + i];
        f[0] += t.x; f[1] += t.y; f[2] += t.z; f[3] += t.w;
    }
    float bmv[4], b2v[4];
    if (COMB || COMB2) {
        float4 t1 = reinterpret_cast<const float4*>(Bm)[i];
        bmv[0] = t1.x; bmv[1] = t1.y; bmv[2] = t1.z; bmv[3] = t1.w;
        float4 t2 = reinterpret_cast<const float4*>(B2m)[i];
        b2v[0] = t2.x; b2v[1] = t2.y; b2v[2] = t2.z; b2v[3] = t2.w;
    }
    int e0 = i * 4;
    int d = (e0 >> 10) - (e0 & (DIM - 1));
    if (COMB) {
        #pragma unroll
        for (int j = 0; j < 4; j++) f[j] += b * bmv[j] + c * b2v[j];
        if (HAS3) {
            float4 t3 = reinterpret_cast<const float4*>(B3m)[i];
            f[0] += e * t3.x; f[1] += e * t3.y; f[2] += e * t3.z; f[3] += e * t3.w;
        }
        if (d >= 0 && d < 4) f[d] += a;
    }
    if (WF32) {
        float4 o; o.x = f[0]; o.y = f[1]; o.z = f[2]; o.w = f[3];
        reinterpret_cast<float4*>(f32out)[i] = o;
    }
    union { bf16 b[4]; uint2 u; } H, L;
    #pragma unroll
    for (int j = 0; j < 4; j++) {
        bf16 h = __float2bfloat16(f[j]);
        H.b[j] = h;
        L.b[j] = __float2bfloat16(f[j] - __bfloat162float(h));
    }
    reinterpret_cast<uint2*>(hi)[i] = H.u;
    reinterpret_cast<uint2*>(lo)[i] = L.u;

    if (COMB2) {
        float g[4];
        #pragma unroll
        for (int j = 0; j < 4; j++) g[j] = b2 * bmv[j] + c2 * b2v[j] + e2 * f[j];
        if (d >= 0 && d < 4) g[d] += a2;
        union { bf16 b[4]; uint2 u; } H2, L2;
        #pragma unroll
        for (int j = 0; j < 4; j++) {
            bf16 h = __float2bfloat16(g[j]);
            H2.b[j] = h;
            L2.b[j] = __float2bfloat16(g[j] - __bfloat162float(h));
        }
        reinterpret_cast<uint2*>(hi2)[i] = H2.u;
        reinterpret_cast<uint2*>(lo2)[i] = L2.u;
    }
}

// ---------------- final reduce: R partials -> fp16 hi/lo of 256*R ----------------
__global__ void reduce_split_h16(const float* __restrict__ part,
                                 __half* __restrict__ hi, __half* __restrict__ lo)
{
    constexpr int SZ4 = DIM * DIM / 4;
    int i = blockIdx.x * 256 + threadIdx.x;
    float f[4] = {0.f, 0.f, 0.f, 0.f};
    #pragma unroll
    for (int p = 0; p < SPLITK; p++) {
        float4 t = reinterpret_cast<const float4*>(part)[p * SZ4 + i];
        f[0] += t.x; f[1] += t.y; f[2] += t.z; f[3] += t.w;
    }
    union { __half h[4]; uint2 u; } H, L;
    #pragma unroll
    for (int j = 0; j < 4; j++) {
        float v = f[j] * RSCALE;
        __half h = __float2half(v);
        H.h[j] = h;
        L.h[j] = __float2half(v - __half2float(h));
    }
    reinterpret_cast<uint2*>(hi)[i] = H.u;
    reinterpret_cast<uint2*>(lo)[i] = L.u;
}

// ---------------- async-copy / mma helpers ----------------
__device__ __forceinline__ void cp16(void* dst, const void* src) {
    unsigned d = (unsigned)__cvta_generic_to_shared(dst);
    asm volatile("cp.async.cg.shared.global [%0], [%1], 16;" :: "r"(d), "l"(src));
}
__device__ __forceinline__ void cp_commit() { asm volatile("cp.async.commit_group;"); }
template<int N>
__device__ __forceinline__ void cp_wait() { asm volatile("cp.async.wait_group %0;" :: "n"(N)); }

__device__ __forceinline__ void ldsm_x4(uint32_t a[4], const void* p) {
    unsigned s = (unsigned)__cvta_generic_to_shared(p);
    asm volatile("ldmatrix.sync.aligned.m8n8.x4.shared.b16 {%0,%1,%2,%3}, [%4];"
                 : "=r"(a[0]), "=r"(a[1]), "=r"(a[2]), "=r"(a[3]) : "r"(s));
}
__device__ __forceinline__ void ldsm_x2t(uint32_t b[2], const void* p) {
    unsigned s = (unsigned)__cvta_generic_to_shared(p);
    asm volatile("ldmatrix.sync.aligned.m8n8.x2.trans.shared.b16 {%0,%1}, [%2];"
                 : "=r"(b[0]), "=r"(b[1]) : "r"(s));
}
__device__ __forceinline__ void mma_bf16(float d[4], const uint32_t a[4], const uint32_t b[2]) {
    asm volatile("mma.sync.aligned.m16n8k16.row.col.f32.bf16.bf16.f32 "
                 "{%0,%1,%2,%3}, {%4,%5,%6,%7}, {%8,%9}, {%0,%1,%2,%3};"
                 : "+f"(d[0]), "+f"(d[1]), "+f"(d[2]), "+f"(d[3])
                 : "r"(a[0]), "r"(a[1]), "r"(a[2]), "r"(a[3]), "r"(b[0]), "r"(b[1]));
}
__device__ __forceinline__ void mma_f16(float d[4], const uint32_t a[4], const uint32_t b[2]) {
    asm volatile("mma.sync.aligned.m16n8k16.row.col.f32.f16.f16.f32 "
                 "{%0,%1,%2,%3}, {%4,%5,%6,%7}, {%8,%9}, {%0,%1,%2,%3};"
                 : "+f"(d[0]), "+f"(d[1]), "+f"(d[2]), "+f"(d[3])
                 : "r"(a[0]), "r"(a[1]), "r"(a[2]), "r"(a[3]), "r"(b[0]), "r"(b[1]));
}

// ---------------- split-bf16 mma.sync GEMM (expm chain, split-K) ----------------
template<int BM, int BN, int WM, int WN, int THREADS, int STAGES>
__global__ __launch_bounds__(THREADS)
void mma_gemm(const bf16* __restrict__ Ah, const bf16* __restrict__ Al,
              const bf16* __restrict__ Bh, const bf16* __restrict__ Bl,
              float* __restrict__ C, int M, int N, int K)
{
    constexpr int BK = 32;
    constexpr int AP = BK + 8;
    constexpr int BP = BN + 8;
    constexpr int ASZ = BM * AP;
    constexpr int BSZ = BK * BP;
    constexpr int MI = WM / 16, NI = WN / 8;
    constexpr int WNC = BN / WN;
    constexpr int AC = (BM * BK / 8) / THREADS;
    constexpr int BC = (BK * BN / 8) / THREADS;

    extern __shared__ bf16 smem[];
    bf16* sA = smem;
    bf16* sB = smem + STAGES * 2 * ASZ;

    const int tid = threadIdx.x, lane = tid & 31, wid = tid >> 5;
    const int wm = wid / WNC, wn = wid % WNC;
    const int row0 = blockIdx.y * BM, col0 = blockIdx.x * BN;

    const int kchunk = K / gridDim.z;
    const int kbeg   = blockIdx.z * kchunk;
    const int NITER  = kchunk / BK;
    C += (size_t)blockIdx.z * (size_t)M * N;

    float acc[MI][NI][4];
    #pragma unroll
    for (int mi = 0; mi < MI; mi++)
        #pragma unroll
        for (int ni = 0; ni < NI; ni++)
            #pragma unroll
            for (int r = 0; r < 4; r++) acc[mi][ni][r] = 0.f;

    auto load_stage = [&](int st, int iter) {
        if (iter < NITER) {
            int k0 = kbeg + iter * BK;
            #pragma unroll
            for (int s = 0; s < 2; s++) {
                const bf16* gA = s ? Al : Ah;
                #pragma unroll
                for (int i = 0; i < AC; i++) {
                    int c = tid + i * THREADS;
                    int r = c / (BK / 8), cc = c % (BK / 8);
                    cp16(&sA[(st * 2 + s) * ASZ + r * AP + cc * 8],
                         gA + (size_t)(row0 + r) * K + k0 + cc * 8);
                }
                const bf16* gB = s ? Bl : Bh;
                #pragma unroll
                for (int i = 0; i < BC; i++) {
                    int c = tid + i * THREADS;
                    int r = c / (BN / 8), cc = c % (BN / 8);
                    cp16(&sB[(st * 2 + s) * BSZ + r * BP + cc * 8],
                         gB + (size_t)(k0 + r) * N + col0 + cc * 8);
                }
            }
        }
        cp_commit();
    };

    #pragma unroll
    for (int s = 0; s < STAGES - 1; s++) load_stage(s, s);

    for (int it = 0; it < NITER; it++) {
        cp_wait<STAGES - 2>();
        __syncthreads();
        load_stage((it + STAGES - 1) % STAGES, it + STAGES - 1);

        const int st = it % STAGES;
        const bf16* Ahs = &sA[(st * 2 + 0) * ASZ];
        const bf16* Als = &sA[(st * 2 + 1) * ASZ];
        const bf16* Bhs = &sB[(st * 2 + 0) * BSZ];
        const bf16* Bls = &sB[(st * 2 + 1) * BSZ];

        #pragma unroll
        for (int ks = 0; ks < 2; ks++) {
            const int k0 = ks * 16;
            uint32_t ah[MI][4], al[MI][4], bh[NI][2], bl[NI][2];
            #pragma unroll
            for (int mi = 0; mi < MI; mi++) {
                int r = wm * WM + mi * 16 + (lane & 15);
                int c = k0 + (lane >> 4) * 8;
                ldsm_x4(ah[mi], Ahs + r * AP + c);
                ldsm_x4(al[mi], Als + r * AP + c);
            }
            #pragma unroll
            for (int ni = 0; ni < NI; ni++) {
                int r = k0 + (lane & 15);
                int c = wn * WN + ni * 8;
                ldsm_x2t(bh[ni], Bhs + r * BP + c);
                ldsm_x2t(bl[ni], Bls + r * BP + c);
            }
            #pragma unroll
            for (int mi = 0; mi < MI; mi++)
                #pragma unroll
                for (int ni = 0; ni < NI; ni++) {
                    mma_bf16(acc[mi][ni], ah[mi], bh[ni]);
                    mma_bf16(acc[mi][ni], ah[mi], bl[ni]);
                    mma_bf16(acc[mi][ni], al[mi], bh[ni]);
                }
        }
    }

    #pragma unroll
    for (int mi = 0; mi < MI; mi++)
        #pragma unroll
        for (int ni = 0; ni < NI; ni++) {
            int r = row0 + wm * WM + mi * 16 + lane / 4;
            int c = col0 + wn * WN + ni * 8 + 2 * (lane % 4);
            *reinterpret_cast<float2*>(&C[(size_t)r * N + c]) =
                make_float2(acc[mi][ni][0], acc[mi][ni][1]);
            *reinterpret_cast<float2*>(&C[(size_t)(r + 8) * N + c]) =
                make_float2(acc[mi][ni][2], acc[mi][ni][3]);
        }
}

// ---------------- main GEMM: out = x @ R, fp16 2-term, 3-stage ----------------
// A = fp16(x) (single term), B = fp16 hi/lo of 256*R. acc scaled by 1/256 at end.
__global__ __launch_bounds__(256, 2)
void xr_gemm(const float* __restrict__ X,
             const __half* __restrict__ Bh, const __half* __restrict__ Bl,
             float* __restrict__ C, int M, int N, int K)
{
    constexpr int BM = 128, BN = 128, BK = 32;
    constexpr int AP = BK + 8;
    constexpr int BP = BN + 8;
    constexpr int ASZ = BM * AP;          // single split now
    constexpr int BSZ = BK * BP;
    constexpr int MI = 4, NI = 4;
    constexpr int ST = 3;

    extern __shared__ __half hsm[];
    __half* sA = hsm;                     // [stage][BM][AP]
    __half* sB = hsm + ST * ASZ;          // [stage][split][BK][BP]

    const int tid = threadIdx.x, lane = tid & 31, wid = tid >> 5;
    const int wm = wid >> 2, wn = wid & 3;
    const int row0 = blockIdx.y * BM, col0 = blockIdx.x * BN;
    const int NITER = K / BK;

    float acc[MI][NI][4];
    #pragma unroll
    for (int mi = 0; mi < MI; mi++)
        #pragma unroll
        for (int ni = 0; ni < NI; ni++)
            #pragma unroll
            for (int r = 0; r < 4; r++) acc[mi][ni][r] = 0.f;

    float4 av[4];
    auto ldgA = [&](int iter) {
        int k0 = iter * BK;
        #pragma unroll
        for (int i = 0; i < 4; i++) {
            int f4 = tid + i * 256;
            int r = f4 >> 3, c4 = f4 & 7;
            av[i] = *reinterpret_cast<const float4*>(
                &X[(size_t)(row0 + r) * K + k0 + c4 * 4]);
        }
    };
    auto stsA = [&](int st) {
        #pragma unroll
        for (int i = 0; i < 4; i++) {
            int f4 = tid + i * 256;
            int r = f4 >> 3, c4 = f4 & 7;
            union { __half h[4]; uint2 u; } H;
            H.h[0] = __float2half(av[i].x);
            H.h[1] = __float2half(av[i].y);
            H.h[2] = __float2half(av[i].z);
            H.h[3] = __float2half(av[i].w);
            *reinterpret_cast<uint2*>(&sA[st * ASZ + r * AP + c4 * 4]) = H.u;
        }
    };
    auto cpB = [&](int st, int iter) {
        if (iter < NITER) {
            int k0 = iter * BK;
            #pragma unroll
            for (int s = 0; s < 2; s++) {
                const __half* g = s ? Bl : Bh;
                #pragma unroll
                for (int i = 0; i < 2; i++) {
                    int c = tid + i * 256;
                    int r = c >> 4, cc = c & 15;
                    cp16(&sB[(st * 2 + s) * BSZ + r * BP + cc * 8],
                         g + (size_t)(k0 + r) * N + col0 + cc * 8);
                }
            }
        }
        cp_commit();
    };

    ldgA(0);
    stsA(0);
    cpB(0, 0);
    ldgA(1);
    cpB(1, 1);

    for (int it = 0; it < NITER; it++) {
        cp_wait<1>();
        __syncthreads();

        const int st = it % ST;
        const __half* As  = &sA[st * ASZ];
        const __half* Bhs = &sB[(st * 2 + 0) * BSZ];
        const __half* Bls = &sB[(st * 2 + 1) * BSZ];

        #pragma unroll
        for (int ks = 0; ks < 2; ks++) {
            const int k0 = ks * 16;
            uint32_t ah[MI][4], bh[NI][2], bl[NI][2];
            #pragma unroll
            for (int mi = 0; mi < MI; mi++) {
                int r = wm * 64 + mi * 16 + (lane & 15);
                int c = k0 + (lane >> 4) * 8;
                ldsm_x4(ah[mi], As + r * AP + c);
            }
            #pragma unroll
            for (int ni = 0; ni < NI; ni++) {
                int r = k0 + (lane & 15);
                int c = wn * 32 + ni * 8;
                ldsm_x2t(bh[ni], Bhs + r * BP + c);
                ldsm_x2t(bl[ni], Bls + r * BP + c);
            }
            #pragma unroll
            for (int mi = 0; mi < MI; mi++)
                #pragma unroll
                for (int ni = 0; ni < NI; ni++) {
                    mma_f16(acc[mi][ni], ah[mi], bh[ni]);
                    mma_f16(acc[mi][ni], ah[mi], bl[ni]);
                }
        }

        if (it + 1 < NITER) stsA((it + 1) % ST);
        if (it + 2 < NITER) ldgA(it + 2);
        cpB((it + 2) % ST, it + 2);
    }

    #pragma unroll
    for (int mi = 0; mi < MI; mi++)
        #pragma unroll
        for (int ni = 0; ni < NI; ni++) {
            int r = row0 + wm * 64 + mi * 16 + lane / 4;
            int c = col0 + wn * 32 + ni * 8 + 2 * (lane % 4);
            *reinterpret_cast<float2*>(&C[(size_t)r * N + c]) =
                make_float2(acc[mi][ni][0] * RISCALE, acc[mi][ni][1] * RISCALE);
            *reinterpret_cast<float2*>(&C[(size_t)(r + 8) * N + c]) =
                make_float2(acc[mi][ni][2] * RISCALE, acc[mi][ni][3] * RISCALE);
        }
}

// ---------------- launch ----------------
extern "C" void kernel_launch(void* const* d_in, const int* in_sizes, int n_in,
                              void* d_out, int out_size)
{
    const float* x = (const float*)d_in[0];
    const float* W = (const float*)d_in[1];
    float* out = (float*)d_out;
    const int M = in_sizes[0] / DIM;   // 16384

    float *B, *B2, *B3, *Pt;
    cudaGetSymbolAddress((void**)&B,  g_B);
    cudaGetSymbolAddress((void**)&B2, g_B2);
    cudaGetSymbolAddress((void**)&B3, g_B3);
    cudaGetSymbolAddress((void**)&Pt, g_part);
    bf16 *Bh,*Bl,*B2h,*B2l,*B3h,*B3l,*Qh,*Ql,*Th,*Tl;
    __half *Rh16, *Rl16;
    cudaGetSymbolAddress((void**)&Bh,  s_Bh);  cudaGetSymbolAddress((void**)&Bl,  s_Bl);
    cudaGetSymbolAddress((void**)&B2h, s_B2h); cudaGetSymbolAddress((void**)&B2l, s_B2l);
    cudaGetSymbolAddress((void**)&B3h, s_B3h); cudaGetSymbolAddress((void**)&B3l, s_B3l);
    cudaGetSymbolAddress((void**)&Qh,  s_Qh);  cudaGetSymbolAddress((void**)&Ql,  s_Ql);
    cudaGetSymbolAddress((void**)&Th,  s_Th);  cudaGetSymbolAddress((void**)&Tl,  s_Tl);
    cudaGetSymbolAddress((void**)&Rh16, s_Rh16);
    cudaGetSymbolAddress((void**)&Rl16, s_Rl16);

    constexpr int SMEM_CHAIN = 2 * 2 * (64 * 40 + 32 * 72) * 2;                 // 38912
    constexpr int SMEM_MAIN  = (3 * 128 * 40 + 3 * 2 * 32 * 136) * 2;           // 82944
    cudaFuncSetAttribute(mma_gemm<64,64,32,32,128,2>,
                         cudaFuncAttributeMaxDynamicSharedMemorySize, SMEM_CHAIN);
    cudaFuncSetAttribute(xr_gemm,
                         cudaFuncAttributeMaxDynamicSharedMemorySize, SMEM_MAIN);

    const dim3 gS(DIM / 64, DIM / 64, SPLITK);    // (16, 16, 4) = 1024 CTAs
    const int  rb = DIM * DIM / 1024;

    // B = (W - W^T)/2, fused split
    skew_split_kernel<<<dim3(DIM / 32, DIM / 32), dim3(32, 8)>>>(W, B, Bh, Bl);

    // G1: B2 = B@B -> fp32 B2 + split
    mma_gemm<64,64,32,32,128,2><<<gS, 128, SMEM_CHAIN>>>(Bh, Bl, Bh, Bl, Pt, DIM, DIM, DIM);
    reduce_split<SPLITK,false,true,false,false><<<rb, 256>>>(Pt, B2, B2h, B2l,
        nullptr, nullptr, nullptr, 0.f, 0.f, 0.f, 0.f, nullptr, nullptr, 0.f, 0.f, 0.f, 0.f);

    // G2: B3 = B2@B -> fp32 B3 + split, AND Q = B/24 + B2/120 + B3/720 (split)
    mma_gemm<64,64,32,32,128,2><<<gS, 128, SMEM_CHAIN>>>(B2h, B2l, Bh, Bl, Pt, DIM, DIM, DIM);
    reduce_split<SPLITK,false,true,true,false><<<rb, 256>>>(Pt, B3, B3h, B3l,
        B, B2, nullptr, 0.f, 0.f, 0.f, 0.f, Qh, Ql, 0.f, 1.f/24.f, 1.f/120.f, 1.f/720.f);

    // G3: T = Q@B3 + I + B + B2/2 + B3/6  (degree-6 Paterson-Stockmeyer)
    mma_gemm<64,64,32,32,128,2><<<gS, 128, SMEM_CHAIN>>>(Qh, Ql, B3h, B3l, Pt, DIM, DIM, DIM);
    reduce_split<SPLITK,true,false,false,true><<<rb, 256>>>(Pt, nullptr, Th, Tl,
        B, B2, B3, 1.f, 1.f, 0.5f, 1.f/6.f, nullptr, nullptr, 0.f, 0.f, 0.f, 0.f);

    // G4: R = T@T -> fp16 hi/lo of 256*R
    mma_gemm<64,64,32,32,128,2><<<gS, 128, SMEM_CHAIN>>>(Th, Tl, Th, Tl, Pt, DIM, DIM, DIM);
    reduce_split_h16<<<rb, 256>>>(Pt, Rh16, Rl16);

    // main: out = x @ R  (fp16 2-term, scale undone in epilogue)
    xr_gemm<<<dim3(DIM / 128, M / 128), 256, SMEM_MAIN>>>(x, Rh16, Rl16, out, M, DIM, DIM);
}

// round 16
// speedup vs baseline: 4.6352x; 1.0992x over previous
#include <cuda_runtime.h>
#include <cuda_bf16.h>
#include <cuda_fp16.h>
#include <cstdint>

typedef __nv_bfloat16 bf16;
#define DIM 1024
#define SPLITK 4
#define RSCALE 256.0f
#define RISCALE 0.00390625f

// ---------------- scratch (static device globals; no allocation) ----------------
__device__ float g_B   [DIM*DIM];
__device__ float g_B2  [DIM*DIM];
__device__ float g_part[SPLITK*DIM*DIM];

__device__ bf16 s_Bh [DIM*DIM], s_Bl [DIM*DIM];
__device__ bf16 s_B2h[DIM*DIM], s_B2l[DIM*DIM];
__device__ bf16 s_B3h[DIM*DIM], s_B3l[DIM*DIM];
__device__ bf16 s_Qh [DIM*DIM], s_Ql [DIM*DIM];
__device__ __half s_Rh16[DIM*DIM], s_Rl16[DIM*DIM];   // 256*R fp16 hi/lo

// ---------------- fused skew + split: B = W - W^T (NO scaling; s=0) ------------
__global__ void skew_split_kernel(const float* __restrict__ W, float* __restrict__ B,
                                  bf16* __restrict__ hi, bf16* __restrict__ lo) {
    __shared__ float t[32][33];
    int tx = threadIdx.x, ty = threadIdx.y;          // 32 x 8
    int bx = blockIdx.x * 32, by = blockIdx.y * 32;
    #pragma unroll
    for (int i = 0; i < 4; i++)
        t[ty + i * 8][tx] = W[(size_t)(bx + ty + i * 8) * DIM + by + tx];
    __syncthreads();
    #pragma unroll
    for (int i = 0; i < 4; i++) {
        int r = by + ty + i * 8, c = bx + tx;
        float v = W[(size_t)r * DIM + c] - t[tx][ty + i * 8];
        B[(size_t)r * DIM + c] = v;
        bf16 h = __float2bfloat16(v);
        hi[(size_t)r * DIM + c] = h;
        lo[(size_t)r * DIM + c] = __float2bfloat16(v - __bfloat162float(h));
    }
}

// ---------------- fused reduce(+comb)(+split)(+second comb) ----------------
// f = sum parts; if COMB: f += a*I + b*Bm + c*B2m. Writes split(f) -> hi/lo; opt fp32.
// If COMB2: g = a2*I + b2*Bm + c2*B2m + e2*f, writes split(g) -> hi2/lo2.
template<int NPART, bool COMB, bool WF32, bool COMB2>
__global__ void reduce_split(const float* __restrict__ part, float* __restrict__ f32out,
                             bf16* __restrict__ hi, bf16* __restrict__ lo,
                             const float* __restrict__ Bm, const float* __restrict__ B2m,
                             float a, float b, float c,
                             bf16* __restrict__ hi2, bf16* __restrict__ lo2,
                             float a2, float b2, float c2, float e2)
{
    constexpr int SZ4 = DIM * DIM / 4;
    int i = blockIdx.x * 256 + threadIdx.x;
    float f[4] = {0.f, 0.f, 0.f, 0.f};
    #pragma unroll
    for (int p = 0; p < NPART; p++) {
        float4 t = reinterpret_cast<const float4*>(part)[p * SZ4 + i];
        f[0] += t.x; f[1] += t.y; f[2] += t.z; f[3] += t.w;
    }
    float bmv[4], b2v[4];
    if (COMB || COMB2) {
        float4 t1 = reinterpret_cast<const float4*>(Bm)[i];
        bmv[0] = t1.x; bmv[1] = t1.y; bmv[2] = t1.z; bmv[3] = t1.w;
        float4 t2 = reinterpret_cast<const float4*>(B2m)[i];
        b2v[0] = t2.x; b2v[1] = t2.y; b2v[2] = t2.z; b2v[3] = t2.w;
    }
    int e0 = i * 4;
    int d = (e0 >> 10) - (e0 & (DIM - 1));
    if (COMB) {
        #pragma unroll
        for (int j = 0; j < 4; j++) f[j] += b * bmv[j] + c * b2v[j];
        if (d >= 0 && d < 4) f[d] += a;
    }
    if (WF32) {
        float4 o; o.x = f[0]; o.y = f[1]; o.z = f[2]; o.w = f[3];
        reinterpret_cast<float4*>(f32out)[i] = o;
    }
    union { bf16 b[4]; uint2 u; } H, L;
    #pragma unroll
    for (int j = 0; j < 4; j++) {
        bf16 h = __float2bfloat16(f[j]);
        H.b[j] = h;
        L.b[j] = __float2bfloat16(f[j] - __bfloat162float(h));
    }
    reinterpret_cast<uint2*>(hi)[i] = H.u;
    reinterpret_cast<uint2*>(lo)[i] = L.u;

    if (COMB2) {
        float g[4];
        #pragma unroll
        for (int j = 0; j < 4; j++) g[j] = b2 * bmv[j] + c2 * b2v[j] + e2 * f[j];
        if (d >= 0 && d < 4) g[d] += a2;
        union { bf16 b[4]; uint2 u; } H2, L2;
        #pragma unroll
        for (int j = 0; j < 4; j++) {
            bf16 h = __float2bfloat16(g[j]);
            H2.b[j] = h;
            L2.b[j] = __float2bfloat16(g[j] - __bfloat162float(h));
        }
        reinterpret_cast<uint2*>(hi2)[i] = H2.u;
        reinterpret_cast<uint2*>(lo2)[i] = L2.u;
    }
}

// ---------------- final reduce: R = Σpart + I + B + B2/2 -> fp16 hi/lo of 256*R --
__global__ void reduce_h16_comb(const float* __restrict__ part,
                                const float* __restrict__ Bm,
                                const float* __restrict__ B2m,
                                __half* __restrict__ hi, __half* __restrict__ lo)
{
    constexpr int SZ4 = DIM * DIM / 4;
    int i = blockIdx.x * 256 + threadIdx.x;
    float f[4] = {0.f, 0.f, 0.f, 0.f};
    #pragma unroll
    for (int p = 0; p < SPLITK; p++) {
        float4 t = reinterpret_cast<const float4*>(part)[p * SZ4 + i];
        f[0] += t.x; f[1] += t.y; f[2] += t.z; f[3] += t.w;
    }
    float4 t1 = reinterpret_cast<const float4*>(Bm)[i];
    float4 t2 = reinterpret_cast<const float4*>(B2m)[i];
    f[0] += t1.x + 0.5f * t2.x;
    f[1] += t1.y + 0.5f * t2.y;
    f[2] += t1.z + 0.5f * t2.z;
    f[3] += t1.w + 0.5f * t2.w;
    int e0 = i * 4;
    int d = (e0 >> 10) - (e0 & (DIM - 1));
    if (d >= 0 && d < 4) f[d] += 1.0f;
    union { __half h[4]; uint2 u; } H, L;
    #pragma unroll
    for (int j = 0; j < 4; j++) {
        float v = f[j] * RSCALE;
        __half h = __float2half(v);
        H.h[j] = h;
        L.h[j] = __float2half(v - __half2float(h));
    }
    reinterpret_cast<uint2*>(hi)[i] = H.u;
    reinterpret_cast<uint2*>(lo)[i] = L.u;
}

// ---------------- async-copy / mma helpers ----------------
__device__ __forceinline__ void cp16(void* dst, const void* src) {
    unsigned d = (unsigned)__cvta_generic_to_shared(dst);
    asm volatile("cp.async.cg.shared.global [%0], [%1], 16;" :: "r"(d), "l"(src));
}
__device__ __forceinline__ void cp_commit() { asm volatile("cp.async.commit_group;"); }
template<int N>
__device__ __forceinline__ void cp_wait() { asm volatile("cp.async.wait_group %0;" :: "n"(N)); }

__device__ __forceinline__ void ldsm_x4(uint32_t a[4], const void* p) {
    unsigned s = (unsigned)__cvta_generic_to_shared(p);
    asm volatile("ldmatrix.sync.aligned.m8n8.x4.shared.b16 {%0,%1,%2,%3}, [%4];"
                 : "=r"(a[0]), "=r"(a[1]), "=r"(a[2]), "=r"(a[3]) : "r"(s));
}
__device__ __forceinline__ void ldsm_x2t(uint32_t b[2], const void* p) {
    unsigned s = (unsigned)__cvta_generic_to_shared(p);
    asm volatile("ldmatrix.sync.aligned.m8n8.x2.trans.shared.b16 {%0,%1}, [%2];"
                 : "=r"(b[0]), "=r"(b[1]) : "r"(s));
}
__device__ __forceinline__ void mma_bf16(float d[4], const uint32_t a[4], const uint32_t b[2]) {
    asm volatile("mma.sync.aligned.m16n8k16.row.col.f32.bf16.bf16.f32 "
                 "{%0,%1,%2,%3}, {%4,%5,%6,%7}, {%8,%9}, {%0,%1,%2,%3};"
                 : "+f"(d[0]), "+f"(d[1]), "+f"(d[2]), "+f"(d[3])
                 : "r"(a[0]), "r"(a[1]), "r"(a[2]), "r"(a[3]), "r"(b[0]), "r"(b[1]));
}
__device__ __forceinline__ void mma_f16(float d[4], const uint32_t a[4], const uint32_t b[2]) {
    asm volatile("mma.sync.aligned.m16n8k16.row.col.f32.f16.f16.f32 "
                 "{%0,%1,%2,%3}, {%4,%5,%6,%7}, {%8,%9}, {%0,%1,%2,%3};"
                 : "+f"(d[0]), "+f"(d[1]), "+f"(d[2]), "+f"(d[3])
                 : "r"(a[0]), "r"(a[1]), "r"(a[2]), "r"(a[3]), "r"(b[0]), "r"(b[1]));
}

// ---------------- split-bf16 mma.sync GEMM (expm chain, split-K) ----------------
template<int BM, int BN, int WM, int WN, int THREADS, int STAGES>
__global__ __launch_bounds__(THREADS)
void mma_gemm(const bf16* __restrict__ Ah, const bf16* __restrict__ Al,
              const bf16* __restrict__ Bh, const bf16* __restrict__ Bl,
              float* __restrict__ C, int M, int N, int K)
{
    constexpr int BK = 32;
    constexpr int AP = BK + 8;
    constexpr int BP = BN + 8;
    constexpr int ASZ = BM * AP;
    constexpr int BSZ = BK * BP;
    constexpr int MI = WM / 16, NI = WN / 8;
    constexpr int WNC = BN / WN;
    constexpr int AC = (BM * BK / 8) / THREADS;
    constexpr int BC = (BK * BN / 8) / THREADS;

    extern __shared__ bf16 smem[];
    bf16* sA = smem;
    bf16* sB = smem + STAGES * 2 * ASZ;

    const int tid = threadIdx.x, lane = tid & 31, wid = tid >> 5;
    const int wm = wid / WNC, wn = wid % WNC;
    const int row0 = blockIdx.y * BM, col0 = blockIdx.x * BN;

    const int kchunk = K / gridDim.z;
    const int kbeg   = blockIdx.z * kchunk;
    const int NITER  = kchunk / BK;
    C += (size_t)blockIdx.z * (size_t)M * N;

    float acc[MI][NI][4];
    #pragma unroll
    for (int mi = 0; mi < MI; mi++)
        #pragma unroll
        for (int ni = 0; ni < NI; ni++)
            #pragma unroll
            for (int r = 0; r < 4; r++) acc[mi][ni][r] = 0.f;

    auto load_stage = [&](int st, int iter) {
        if (iter < NITER) {
            int k0 = kbeg + iter * BK;
            #pragma unroll
            for (int s = 0; s < 2; s++) {
                const bf16* gA = s ? Al : Ah;
                #pragma unroll
                for (int i = 0; i < AC; i++) {
                    int c = tid + i * THREADS;
                    int r = c / (BK / 8), cc = c % (BK / 8);
                    cp16(&sA[(st * 2 + s) * ASZ + r * AP + cc * 8],
                         gA + (size_t)(row0 + r) * K + k0 + cc * 8);
                }
                const bf16* gB = s ? Bl : Bh;
                #pragma unroll
                for (int i = 0; i < BC; i++) {
                    int c = tid + i * THREADS;
                    int r = c / (BN / 8), cc = c % (BN / 8);
                    cp16(&sB[(st * 2 + s) * BSZ + r * BP + cc * 8],
                         gB + (size_t)(k0 + r) * N + col0 + cc * 8);
                }
            }
        }
        cp_commit();
    };

    #pragma unroll
    for (int s = 0; s < STAGES - 1; s++) load_stage(s, s);

    for (int it = 0; it < NITER; it++) {
        cp_wait<STAGES - 2>();
        __syncthreads();
        load_stage((it + STAGES - 1) % STAGES, it + STAGES - 1);

        const int st = it % STAGES;
        const bf16* Ahs = &sA[(st * 2 + 0) * ASZ];
        const bf16* Als = &sA[(st * 2 + 1) * ASZ];
        const bf16* Bhs = &sB[(st * 2 + 0) * BSZ];
        const bf16* Bls = &sB[(st * 2 + 1) * BSZ];

        #pragma unroll
        for (int ks = 0; ks < 2; ks++) {
            const int k0 = ks * 16;
            uint32_t ah[MI][4], al[MI][4], bh[NI][2], bl[NI][2];
            #pragma unroll
            for (int mi = 0; mi < MI; mi++) {
                int r = wm * WM + mi * 16 + (lane & 15);
                int c = k0 + (lane >> 4) * 8;
                ldsm_x4(ah[mi], Ahs + r * AP + c);
                ldsm_x4(al[mi], Als + r * AP + c);
            }
            #pragma unroll
            for (int ni = 0; ni < NI; ni++) {
                int r = k0 + (lane & 15);
                int c = wn * WN + ni * 8;
                ldsm_x2t(bh[ni], Bhs + r * BP + c);
                ldsm_x2t(bl[ni], Bls + r * BP + c);
            }
            #pragma unroll
            for (int mi = 0; mi < MI; mi++)
                #pragma unroll
                for (int ni = 0; ni < NI; ni++) {
                    mma_bf16(acc[mi][ni], ah[mi], bh[ni]);
                    mma_bf16(acc[mi][ni], ah[mi], bl[ni]);
                    mma_bf16(acc[mi][ni], al[mi], bh[ni]);
                }
        }
    }

    #pragma unroll
    for (int mi = 0; mi < MI; mi++)
        #pragma unroll
        for (int ni = 0; ni < NI; ni++) {
            int r = row0 + wm * WM + mi * 16 + lane / 4;
            int c = col0 + wn * WN + ni * 8 + 2 * (lane % 4);
            *reinterpret_cast<float2*>(&C[(size_t)r * N + c]) =
                make_float2(acc[mi][ni][0], acc[mi][ni][1]);
            *reinterpret_cast<float2*>(&C[(size_t)(r + 8) * N + c]) =
                make_float2(acc[mi][ni][2], acc[mi][ni][3]);
        }
}

// ---------------- main GEMM: out = x @ R, fp16 2-term, 3-stage ----------------
__global__ __launch_bounds__(256, 2)
void xr_gemm(const float* __restrict__ X,
             const __half* __restrict__ Bh, const __half* __restrict__ Bl,
             float* __restrict__ C, int M, int N, int K)
{
    constexpr int BM = 128, BN = 128, BK = 32;
    constexpr int AP = BK + 8;
    constexpr int BP = BN + 8;
    constexpr int ASZ = BM * AP;
    constexpr int BSZ = BK * BP;
    constexpr int MI = 4, NI = 4;
    constexpr int ST = 3;

    extern __shared__ __half hsm[];
    __half* sA = hsm;
    __half* sB = hsm + ST * ASZ;

    const int tid = threadIdx.x, lane = tid & 31, wid = tid >> 5;
    const int wm = wid >> 2, wn = wid & 3;
    const int row0 = blockIdx.y * BM, col0 = blockIdx.x * BN;
    const int NITER = K / BK;

    float acc[MI][NI][4];
    #pragma unroll
    for (int mi = 0; mi < MI; mi++)
        #pragma unroll
        for (int ni = 0; ni < NI; ni++)
            #pragma unroll
            for (int r = 0; r < 4; r++) acc[mi][ni][r] = 0.f;

    float4 av[4];
    auto ldgA = [&](int iter) {
        int k0 = iter * BK;
        #pragma unroll
        for (int i = 0; i < 4; i++) {
            int f4 = tid + i * 256;
            int r = f4 >> 3, c4 = f4 & 7;
            av[i] = *reinterpret_cast<const float4*>(
                &X[(size_t)(row0 + r) * K + k0 + c4 * 4]);
        }
    };
    auto stsA = [&](int st) {
        #pragma unroll
        for (int i = 0; i < 4; i++) {
            int f4 = tid + i * 256;
            int r = f4 >> 3, c4 = f4 & 7;
            union { __half h[4]; uint2 u; } H;
            H.h[0] = __float2half(av[i].x);
            H.h[1] = __float2half(av[i].y);
            H.h[2] = __float2half(av[i].z);
            H.h[3] = __float2half(av[i].w);
            *reinterpret_cast<uint2*>(&sA[st * ASZ + r * AP + c4 * 4]) = H.u;
        }
    };
    auto cpB = [&](int st, int iter) {
        if (iter < NITER) {
            int k0 = iter * BK;
            #pragma unroll
            for (int s = 0; s < 2; s++) {
                const __half* g = s ? Bl : Bh;
                #pragma unroll
                for (int i = 0; i < 2; i++) {
                    int c = tid + i * 256;
                    int r = c >> 4, cc = c & 15;
                    cp16(&sB[(st * 2 + s) * BSZ + r * BP + cc * 8],
                         g + (size_t)(k0 + r) * N + col0 + cc * 8);
                }
            }
        }
        cp_commit();
    };

    ldgA(0);
    stsA(0);
    cpB(0, 0);
    ldgA(1);
    cpB(1, 1);

    for (int it = 0; it < NITER; it++) {
        cp_wait<1>();
        __syncthreads();

        const int st = it % ST;
        const __half* As  = &sA[st * ASZ];
        const __half* Bhs = &sB[(st * 2 + 0) * BSZ];
        const __half* Bls = &sB[(st * 2 + 1) * BSZ];

        #pragma unroll
        for (int ks = 0; ks < 2; ks++) {
            const int k0 = ks * 16;
            uint32_t ah[MI][4], bh[NI][2], bl[NI][2];
            #pragma unroll
            for (int mi = 0; mi < MI; mi++) {
                int r = wm * 64 + mi * 16 + (lane & 15);
                int c = k0 + (lane >> 4) * 8;
                ldsm_x4(ah[mi], As + r * AP + c);
            }
            #pragma unroll
            for (int ni = 0; ni < NI; ni++) {
                int r = k0 + (lane & 15);
                int c = wn * 32 + ni * 8;
                ldsm_x2t(bh[ni], Bhs + r * BP + c);
                ldsm_x2t(bl[ni], Bls + r * BP + c);
            }
            #pragma unroll
            for (int mi = 0; mi < MI; mi++)
                #pragma unroll
                for (int ni = 0; ni < NI; ni++) {
                    mma_f16(acc[mi][ni], ah[mi], bh[ni]);
                    mma_f16(acc[mi][ni], ah[mi], bl[ni]);
                }
        }

        if (it + 1 < NITER) stsA((it + 1) % ST);
        if (it + 2 < NITER) ldgA(it + 2);
        cpB((it + 2) % ST, it + 2);
    }

    #pragma unroll
    for (int mi = 0; mi < MI; mi++)
        #pragma unroll
        for (int ni = 0; ni < NI; ni++) {
            int r = row0 + wm * 64 + mi * 16 + lane / 4;
            int c = col0 + wn * 32 + ni * 8 + 2 * (lane % 4);
            *reinterpret_cast<float2*>(&C[(size_t)r * N + c]) =
                make_float2(acc[mi][ni][0] * RISCALE, acc[mi][ni][1] * RISCALE);
            *reinterpret_cast<float2*>(&C[(size_t)(r + 8) * N + c]) =
                make_float2(acc[mi][ni][2] * RISCALE, acc[mi][ni][3] * RISCALE);
        }
}

// ---------------- launch ----------------
extern "C" void kernel_launch(void* const* d_in, const int* in_sizes, int n_in,
                              void* d_out, int out_size)
{
    const float* x = (const float*)d_in[0];
    const float* W = (const float*)d_in[1];
    float* out = (float*)d_out;
    const int M = in_sizes[0] / DIM;   // 16384

    float *B, *B2, *Pt;
    cudaGetSymbolAddress((void**)&B,  g_B);
    cudaGetSymbolAddress((void**)&B2, g_B2);
    cudaGetSymbolAddress((void**)&Pt, g_part);
    bf16 *Bh,*Bl,*B2h,*B2l,*B3h,*B3l,*Qh,*Ql;
    __half *Rh16, *Rl16;
    cudaGetSymbolAddress((void**)&Bh,  s_Bh);  cudaGetSymbolAddress((void**)&Bl,  s_Bl);
    cudaGetSymbolAddress((void**)&B2h, s_B2h); cudaGetSymbolAddress((void**)&B2l, s_B2l);
    cudaGetSymbolAddress((void**)&B3h, s_B3h); cudaGetSymbolAddress((void**)&B3l, s_B3l);
    cudaGetSymbolAddress((void**)&Qh,  s_Qh);  cudaGetSymbolAddress((void**)&Ql,  s_Ql);
    cudaGetSymbolAddress((void**)&Rh16, s_Rh16);
    cudaGetSymbolAddress((void**)&Rl16, s_Rl16);

    constexpr int SMEM_CHAIN = 2 * 2 * (64 * 40 + 32 * 72) * 2;                 // 38912
    constexpr int SMEM_MAIN  = (3 * 128 * 40 + 3 * 2 * 32 * 136) * 2;           // 82944
    cudaFuncSetAttribute(mma_gemm<64,64,32,32,128,2>,
                         cudaFuncAttributeMaxDynamicSharedMemorySize, SMEM_CHAIN);
    cudaFuncSetAttribute(xr_gemm,
                         cudaFuncAttributeMaxDynamicSharedMemorySize, SMEM_MAIN);

    const dim3 gS(DIM / 64, DIM / 64, SPLITK);    // (16, 16, 4) = 1024 CTAs
    const int  rb = DIM * DIM / 1024;

    // B = W - W^T (unscaled; degree-6 Taylor directly on A), fused split
    skew_split_kernel<<<dim3(DIM / 32, DIM / 32), dim3(32, 8)>>>(W, B, Bh, Bl);

    // G1: B2 = B@B -> fp32 B2 + split
    mma_gemm<64,64,32,32,128,2><<<gS, 128, SMEM_CHAIN>>>(Bh, Bl, Bh, Bl, Pt, DIM, DIM, DIM);
    reduce_split<SPLITK,false,true,false><<<rb, 256>>>(Pt, B2, B2h, B2l,
        nullptr, nullptr, 0.f, 0.f, 0.f, nullptr, nullptr, 0.f, 0.f, 0.f, 0.f);

    // G2: B3 = B2@B -> split, AND Q = I/6 + B/24 + B2/120 + B3/720 (comb2, split)
    mma_gemm<64,64,32,32,128,2><<<gS, 128, SMEM_CHAIN>>>(B2h, B2l, Bh, Bl, Pt, DIM, DIM, DIM);
    reduce_split<SPLITK,false,false,true><<<rb, 256>>>(Pt, nullptr, B3h, B3l,
        B, B2, 0.f, 0.f, 0.f, Qh, Ql, 1.f/6.f, 1.f/24.f, 1.f/120.f, 1.f/720.f);

    // G3: R = Q@B3 + I + B + B2/2  -> fp16 hi/lo of 256*R (degree-6 PS, no squaring)
    mma_gemm<64,64,32,32,128,2><<<gS, 128, SMEM_CHAIN>>>(Qh, Ql, B3h, B3l, Pt, DIM, DIM, DIM);
    reduce_h16_comb<<<rb, 256>>>(Pt, B, B2, Rh16, Rl16);

    // main: out = x @ R  (fp16 2-term, scale undone in epilogue)
    xr_gemm<<<dim3(DIM / 128, M / 128), 256, SMEM_MAIN>>>(x, Rh16, Rl16, out, M, DIM, DIM);
}

// round 17
// speedup vs baseline: 6.1109x; 1.3184x over previous
#include <cuda_runtime.h>
#include <cuda_bf16.h>
#include <cuda_fp16.h>
#include <cstdint>

typedef __nv_bfloat16 bf16;
#define DIM 1024
#define SPLITK 4
#define RSCALE 256.0f
#define RISCALE 0.00390625f

// ---------------- scratch (static device globals; no allocation) ----------------
__device__ float g_B   [DIM*DIM];
__device__ float g_B2  [DIM*DIM];
__device__ float g_part[SPLITK*DIM*DIM];

__device__ bf16 s_Bh [DIM*DIM], s_Bl [DIM*DIM];
__device__ bf16 s_B2h[DIM*DIM], s_B2l[DIM*DIM];
__device__ bf16 s_B3h[DIM*DIM], s_B3l[DIM*DIM];
__device__ bf16 s_Qh [DIM*DIM], s_Ql [DIM*DIM];
__device__ __half s_Rh16[DIM*DIM];          // fp16(256*R)

// ---------------- fused skew + split: B = W - W^T ----------------
__global__ void skew_split_kernel(const float* __restrict__ W, float* __restrict__ B,
                                  bf16* __restrict__ hi, bf16* __restrict__ lo) {
    __shared__ float t[32][33];
    int tx = threadIdx.x, ty = threadIdx.y;          // 32 x 8
    int bx = blockIdx.x * 32, by = blockIdx.y * 32;
    #pragma unroll
    for (int i = 0; i < 4; i++)
        t[ty + i * 8][tx] = W[(size_t)(bx + ty + i * 8) * DIM + by + tx];
    __syncthreads();
    #pragma unroll
    for (int i = 0; i < 4; i++) {
        int r = by + ty + i * 8, c = bx + tx;
        float v = W[(size_t)r * DIM + c] - t[tx][ty + i * 8];
        B[(size_t)r * DIM + c] = v;
        bf16 h = __float2bfloat16(v);
        hi[(size_t)r * DIM + c] = h;
        lo[(size_t)r * DIM + c] = __float2bfloat16(v - __bfloat162float(h));
    }
}

// ---------------- fused reduce(+comb)(+split)(+second comb) ----------------
template<int NPART, bool COMB, bool WF32, bool COMB2>
__global__ void reduce_split(const float* __restrict__ part, float* __restrict__ f32out,
                             bf16* __restrict__ hi, bf16* __restrict__ lo,
                             const float* __restrict__ Bm, const float* __restrict__ B2m,
                             float a, float b, float c,
                             bf16* __restrict__ hi2, bf16* __restrict__ lo2,
                             float a2, float b2, float c2, float e2)
{
    constexpr int SZ4 = DIM * DIM / 4;
    int i = blockIdx.x * 256 + threadIdx.x;
    float f[4] = {0.f, 0.f, 0.f, 0.f};
    #pragma unroll
    for (int p = 0; p < NPART; p++) {
        float4 t = reinterpret_cast<const float4*>(part)[p * SZ4 + i];
        f[0] += t.x; f[1] += t.y; f[2] += t.z; f[3] += t.w;
    }
    float bmv[4], b2v[4];
    if (COMB || COMB2) {
        float4 t1 = reinterpret_cast<const float4*>(Bm)[i];
        bmv[0] = t1.x; bmv[1] = t1.y; bmv[2] = t1.z; bmv[3] = t1.w;
        float4 t2 = reinterpret_cast<const float4*>(B2m)[i];
        b2v[0] = t2.x; b2v[1] = t2.y; b2v[2] = t2.z; b2v[3] = t2.w;
    }
    int e0 = i * 4;
    int d = (e0 >> 10) - (e0 & (DIM - 1));
    if (COMB) {
        #pragma unroll
        for (int j = 0; j < 4; j++) f[j] += b * bmv[j] + c * b2v[j];
        if (d >= 0 && d < 4) f[d] += a;
    }
    if (WF32) {
        float4 o; o.x = f[0]; o.y = f[1]; o.z = f[2]; o.w = f[3];
        reinterpret_cast<float4*>(f32out)[i] = o;
    }
    union { bf16 b[4]; uint2 u; } H, L;
    #pragma unroll
    for (int j = 0; j < 4; j++) {
        bf16 h = __float2bfloat16(f[j]);
        H.b[j] = h;
        L.b[j] = __float2bfloat16(f[j] - __bfloat162float(h));
    }
    reinterpret_cast<uint2*>(hi)[i] = H.u;
    reinterpret_cast<uint2*>(lo)[i] = L.u;

    if (COMB2) {
        float g[4];
        #pragma unroll
        for (int j = 0; j < 4; j++) g[j] = b2 * bmv[j] + c2 * b2v[j] + e2 * f[j];
        if (d >= 0 && d < 4) g[d] += a2;
        union { bf16 b[4]; uint2 u; } H2, L2;
        #pragma unroll
        for (int j = 0; j < 4; j++) {
            bf16 h = __float2bfloat16(g[j]);
            H2.b[j] = h;
            L2.b[j] = __float2bfloat16(g[j] - __bfloat162float(h));
        }
        reinterpret_cast<uint2*>(hi2)[i] = H2.u;
        reinterpret_cast<uint2*>(lo2)[i] = L2.u;
    }
}

// ---------------- final reduce: R = Σpart + I + B + B2/2 -> fp16(256*R) --------
__global__ void reduce_h16_comb(const float* __restrict__ part,
                                const float* __restrict__ Bm,
                                const float* __restrict__ B2m,
                                __half* __restrict__ hi)
{
    constexpr int SZ4 = DIM * DIM / 4;
    int i = blockIdx.x * 256 + threadIdx.x;
    float f[4] = {0.f, 0.f, 0.f, 0.f};
    #pragma unroll
    for (int p = 0; p < SPLITK; p++) {
        float4 t = reinterpret_cast<const float4*>(part)[p * SZ4 + i];
        f[0] += t.x; f[1] += t.y; f[2] += t.z; f[3] += t.w;
    }
    float4 t1 = reinterpret_cast<const float4*>(Bm)[i];
    float4 t2 = reinterpret_cast<const float4*>(B2m)[i];
    f[0] += t1.x + 0.5f * t2.x;
    f[1] += t1.y + 0.5f * t2.y;
    f[2] += t1.z + 0.5f * t2.z;
    f[3] += t1.w + 0.5f * t2.w;
    int e0 = i * 4;
    int d = (e0 >> 10) - (e0 & (DIM - 1));
    if (d >= 0 && d < 4) f[d] += 1.0f;
    union { __half h[4]; uint2 u; } H;
    #pragma unroll
    for (int j = 0; j < 4; j++)
        H.h[j] = __float2half(f[j] * RSCALE);
    reinterpret_cast<uint2*>(hi)[i] = H.u;
}

// ---------------- async-copy / mma helpers ----------------
__device__ __forceinline__ void cp16(void* dst, const void* src) {
    unsigned d = (unsigned)__cvta_generic_to_shared(dst);
    asm volatile("cp.async.cg.shared.global [%0], [%1], 16;" :: "r"(d), "l"(src));
}
__device__ __forceinline__ void cp_commit() { asm volatile("cp.async.commit_group;"); }
template<int N>
__device__ __forceinline__ void cp_wait() { asm volatile("cp.async.wait_group %0;" :: "n"(N)); }

__device__ __forceinline__ void ldsm_x4(uint32_t a[4], const void* p) {
    unsigned s = (unsigned)__cvta_generic_to_shared(p);
    asm volatile("ldmatrix.sync.aligned.m8n8.x4.shared.b16 {%0,%1,%2,%3}, [%4];"
                 : "=r"(a[0]), "=r"(a[1]), "=r"(a[2]), "=r"(a[3]) : "r"(s));
}
__device__ __forceinline__ void ldsm_x2t(uint32_t b[2], const void* p) {
    unsigned s = (unsigned)__cvta_generic_to_shared(p);
    asm volatile("ldmatrix.sync.aligned.m8n8.x2.trans.shared.b16 {%0,%1}, [%2];"
                 : "=r"(b[0]), "=r"(b[1]) : "r"(s));
}
__device__ __forceinline__ void mma_bf16(float d[4], const uint32_t a[4], const uint32_t b[2]) {
    asm volatile("mma.sync.aligned.m16n8k16.row.col.f32.bf16.bf16.f32 "
                 "{%0,%1,%2,%3}, {%4,%5,%6,%7}, {%8,%9}, {%0,%1,%2,%3};"
                 : "+f"(d[0]), "+f"(d[1]), "+f"(d[2]), "+f"(d[3])
                 : "r"(a[0]), "r"(a[1]), "r"(a[2]), "r"(a[3]), "r"(b[0]), "r"(b[1]));
}
__device__ __forceinline__ void mma_f16(float d[4], const uint32_t a[4], const uint32_t b[2]) {
    asm volatile("mma.sync.aligned.m16n8k16.row.col.f32.f16.f16.f32 "
                 "{%0,%1,%2,%3}, {%4,%5,%6,%7}, {%8,%9}, {%0,%1,%2,%3};"
                 : "+f"(d[0]), "+f"(d[1]), "+f"(d[2]), "+f"(d[3])
                 : "r"(a[0]), "r"(a[1]), "r"(a[2]), "r"(a[3]), "r"(b[0]), "r"(b[1]));
}

// ---------------- split-bf16 mma.sync GEMM (expm chain, split-K) ----------------
template<int BM, int BN, int WM, int WN, int THREADS, int STAGES>
__global__ __launch_bounds__(THREADS)
void mma_gemm(const bf16* __restrict__ Ah, const bf16* __restrict__ Al,
              const bf16* __restrict__ Bh, const bf16* __restrict__ Bl,
              float* __restrict__ C, int M, int N, int K)
{
    constexpr int BK = 32;
    constexpr int AP = BK + 8;
    constexpr int BP = BN + 8;
    constexpr int ASZ = BM * AP;
    constexpr int BSZ = BK * BP;
    constexpr int MI = WM / 16, NI = WN / 8;
    constexpr int WNC = BN / WN;
    constexpr int AC = (BM * BK / 8) / THREADS;
    constexpr int BC = (BK * BN / 8) / THREADS;

    extern __shared__ bf16 smem[];
    bf16* sA = smem;
    bf16* sB = smem + STAGES * 2 * ASZ;

    const int tid = threadIdx.x, lane = tid & 31, wid = tid >> 5;
    const int wm = wid / WNC, wn = wid % WNC;
    const int row0 = blockIdx.y * BM, col0 = blockIdx.x * BN;

    const int kchunk = K / gridDim.z;
    const int kbeg   = blockIdx.z * kchunk;
    const int NITER  = kchunk / BK;
    C += (size_t)blockIdx.z * (size_t)M * N;

    float acc[MI][NI][4];
    #pragma unroll
    for (int mi = 0; mi < MI; mi++)
        #pragma unroll
        for (int ni = 0; ni < NI; ni++)
            #pragma unroll
            for (int r = 0; r < 4; r++) acc[mi][ni][r] = 0.f;

    auto load_stage = [&](int st, int iter) {
        if (iter < NITER) {
            int k0 = kbeg + iter * BK;
            #pragma unroll
            for (int s = 0; s < 2; s++) {
                const bf16* gA = s ? Al : Ah;
                #pragma unroll
                for (int i = 0; i < AC; i++) {
                    int c = tid + i * THREADS;
                    int r = c / (BK / 8), cc = c % (BK / 8);
                    cp16(&sA[(st * 2 + s) * ASZ + r * AP + cc * 8],
                         gA + (size_t)(row0 + r) * K + k0 + cc * 8);
                }
                const bf16* gB = s ? Bl : Bh;
                #pragma unroll
                for (int i = 0; i < BC; i++) {
                    int c = tid + i * THREADS;
                    int r = c / (BN / 8), cc = c % (BN / 8);
                    cp16(&sB[(st * 2 + s) * BSZ + r * BP + cc * 8],
                         gB + (size_t)(k0 + r) * N + col0 + cc * 8);
                }
            }
        }
        cp_commit();
    };

    #pragma unroll
    for (int s = 0; s < STAGES - 1; s++) load_stage(s, s);

    for (int it = 0; it < NITER; it++) {
        cp_wait<STAGES - 2>();
        __syncthreads();
        load_stage((it + STAGES - 1) % STAGES, it + STAGES - 1);

        const int st = it % STAGES;
        const bf16* Ahs = &sA[(st * 2 + 0) * ASZ];
        const bf16* Als = &sA[(st * 2 + 1) * ASZ];
        const bf16* Bhs = &sB[(st * 2 + 0) * BSZ];
        const bf16* Bls = &sB[(st * 2 + 1) * BSZ];

        #pragma unroll
        for (int ks = 0; ks < 2; ks++) {
            const int k0 = ks * 16;
            uint32_t ah[MI][4], al[MI][4], bh[NI][2], bl[NI][2];
            #pragma unroll
            for (int mi = 0; mi < MI; mi++) {
                int r = wm * WM + mi * 16 + (lane & 15);
                int c = k0 + (lane >> 4) * 8;
                ldsm_x4(ah[mi], Ahs + r * AP + c);
                ldsm_x4(al[mi], Als + r * AP + c);
            }
            #pragma unroll
            for (int ni = 0; ni < NI; ni++) {
                int r = k0 + (lane & 15);
                int c = wn * WN + ni * 8;
                ldsm_x2t(bh[ni], Bhs + r * BP + c);
                ldsm_x2t(bl[ni], Bls + r * BP + c);
            }
            #pragma unroll
            for (int mi = 0; mi < MI; mi++)
                #pragma unroll
                for (int ni = 0; ni < NI; ni++) {
                    mma_bf16(acc[mi][ni], ah[mi], bh[ni]);
                    mma_bf16(acc[mi][ni], ah[mi], bl[ni]);
                    mma_bf16(acc[mi][ni], al[mi], bh[ni]);
                }
        }
    }

    #pragma unroll
    for (int mi = 0; mi < MI; mi++)
        #pragma unroll
        for (int ni = 0; ni < NI; ni++) {
            int r = row0 + wm * WM + mi * 16 + lane / 4;
            int c = col0 + wn * WN + ni * 8 + 2 * (lane % 4);
            *reinterpret_cast<float2*>(&C[(size_t)r * N + c]) =
                make_float2(acc[mi][ni][0], acc[mi][ni][1]);
            *reinterpret_cast<float2*>(&C[(size_t)(r + 8) * N + c]) =
                make_float2(acc[mi][ni][2], acc[mi][ni][3]);
        }
}

// ---------------- main GEMM: out = x @ R, fp16 SINGLE term, 3-stage ------------
// A = fp16(x), B = fp16(256*R). acc scaled by 1/256 in epilogue.
__global__ __launch_bounds__(256, 2)
void xr_gemm(const float* __restrict__ X,
             const __half* __restrict__ Bh,
             float* __restrict__ C, int M, int N, int K)
{
    constexpr int BM = 128, BN = 128, BK = 32;
    constexpr int AP = BK + 8;
    constexpr int BP = BN + 8;
    constexpr int ASZ = BM * AP;
    constexpr int BSZ = BK * BP;
    constexpr int MI = 4, NI = 4;
    constexpr int ST = 3;

    extern __shared__ __half hsm[];
    __half* sA = hsm;                     // [stage][BM][AP]
    __half* sB = hsm + ST * ASZ;          // [stage][BK][BP]

    const int tid = threadIdx.x, lane = tid & 31, wid = tid >> 5;
    const int wm = wid >> 2, wn = wid & 3;
    const int row0 = blockIdx.y * BM, col0 = blockIdx.x * BN;
    const int NITER = K / BK;

    float acc[MI][NI][4];
    #pragma unroll
    for (int mi = 0; mi < MI; mi++)
        #pragma unroll
        for (int ni = 0; ni < NI; ni++)
            #pragma unroll
            for (int r = 0; r < 4; r++) acc[mi][ni][r] = 0.f;

    float4 av[4];
    auto ldgA = [&](int iter) {
        int k0 = iter * BK;
        #pragma unroll
        for (int i = 0; i < 4; i++) {
            int f4 = tid + i * 256;
            int r = f4 >> 3, c4 = f4 & 7;
            av[i] = *reinterpret_cast<const float4*>(
                &X[(size_t)(row0 + r) * K + k0 + c4 * 4]);
        }
    };
    auto stsA = [&](int st) {
        #pragma unroll
        for (int i = 0; i < 4; i++) {
            int f4 = tid + i * 256;
            int r = f4 >> 3, c4 = f4 & 7;
            union { __half h[4]; uint2 u; } H;
            H.h[0] = __float2half(av[i].x);
            H.h[1] = __float2half(av[i].y);
            H.h[2] = __float2half(av[i].z);
            H.h[3] = __float2half(av[i].w);
            *reinterpret_cast<uint2*>(&sA[st * ASZ + r * AP + c4 * 4]) = H.u;
        }
    };
    auto cpB = [&](int st, int iter) {
        if (iter < NITER) {
            int k0 = iter * BK;
            #pragma unroll
            for (int i = 0; i < 2; i++) {
                int c = tid + i * 256;
                int r = c >> 4, cc = c & 15;
                cp16(&sB[st * BSZ + r * BP + cc * 8],
                     Bh + (size_t)(k0 + r) * N + col0 + cc * 8);
            }
        }
        cp_commit();
    };

    ldgA(0);
    stsA(0);
    cpB(0, 0);
    ldgA(1);
    cpB(1, 1);

    for (int it = 0; it < NITER; it++) {
        cp_wait<1>();
        __syncthreads();

        const int st = it % ST;
        const __half* As  = &sA[st * ASZ];
        const __half* Bhs = &sB[st * BSZ];

        #pragma unroll
        for (int ks = 0; ks < 2; ks++) {
            const int k0 = ks * 16;
            uint32_t ah[MI][4], bh[NI][2];
            #pragma unroll
            for (int mi = 0; mi < MI; mi++) {
                int r = wm * 64 + mi * 16 + (lane & 15);
                int c = k0 + (lane >> 4) * 8;
                ldsm_x4(ah[mi], As + r * AP + c);
            }
            #pragma unroll
            for (int ni = 0; ni < NI; ni++) {
                int r = k0 + (lane & 15);
                int c = wn * 32 + ni * 8;
                ldsm_x2t(bh[ni], Bhs + r * BP + c);
            }
            #pragma unroll
            for (int mi = 0; mi < MI; mi++)
                #pragma unroll
                for (int ni = 0; ni < NI; ni++)
                    mma_f16(acc[mi][ni], ah[mi], bh[ni]);
        }

        if (it + 1 < NITER) stsA((it + 1) % ST);
        if (it + 2 < NITER) ldgA(it + 2);
        cpB((it + 2) % ST, it + 2);
    }

    #pragma unroll
    for (int mi = 0; mi < MI; mi++)
        #pragma unroll
        for (int ni = 0; ni < NI; ni++) {
            int r = row0 + wm * 64 + mi * 16 + lane / 4;
            int c = col0 + wn * 32 + ni * 8 + 2 * (lane % 4);
            *reinterpret_cast<float2*>(&C[(size_t)r * N + c]) =
                make_float2(acc[mi][ni][0] * RISCALE, acc[mi][ni][1] * RISCALE);
            *reinterpret_cast<float2*>(&C[(size_t)(r + 8) * N + c]) =
                make_float2(acc[mi][ni][2] * RISCALE, acc[mi][ni][3] * RISCALE);
        }
}

// ---------------- launch ----------------
extern "C" void kernel_launch(void* const* d_in, const int* in_sizes, int n_in,
                              void* d_out, int out_size)
{
    const float* x = (const float*)d_in[0];
    const float* W = (const float*)d_in[1];
    float* out = (float*)d_out;
    const int M = in_sizes[0] / DIM;   // 16384

    float *B, *B2, *Pt;
    cudaGetSymbolAddress((void**)&B,  g_B);
    cudaGetSymbolAddress((void**)&B2, g_B2);
    cudaGetSymbolAddress((void**)&Pt, g_part);
    bf16 *Bh,*Bl,*B2h,*B2l,*B3h,*B3l,*Qh,*Ql;
    __half *Rh16;
    cudaGetSymbolAddress((void**)&Bh,  s_Bh);  cudaGetSymbolAddress((void**)&Bl,  s_Bl);
    cudaGetSymbolAddress((void**)&B2h, s_B2h); cudaGetSymbolAddress((void**)&B2l, s_B2l);
    cudaGetSymbolAddress((void**)&B3h, s_B3h); cudaGetSymbolAddress((void**)&B3l, s_B3l);
    cudaGetSymbolAddress((void**)&Qh,  s_Qh);  cudaGetSymbolAddress((void**)&Ql,  s_Ql);
    cudaGetSymbolAddress((void**)&Rh16, s_Rh16);

    constexpr int SMEM_CHAIN = 2 * 2 * (64 * 40 + 32 * 72) * 2;                 // 38912
    constexpr int SMEM_MAIN  = (3 * 128 * 40 + 3 * 32 * 136) * 2;               // 56832
    cudaFuncSetAttribute(mma_gemm<64,64,32,32,128,2>,
                         cudaFuncAttributeMaxDynamicSharedMemorySize, SMEM_CHAIN);
    cudaFuncSetAttribute(xr_gemm,
                         cudaFuncAttributeMaxDynamicSharedMemorySize, SMEM_MAIN);

    const dim3 gS(DIM / 64, DIM / 64, SPLITK);    // (16, 16, 4) = 1024 CTAs
    const int  rb = DIM * DIM / 1024;

    // B = W - W^T (unscaled; degree-6 Taylor directly on A), fused split
    skew_split_kernel<<<dim3(DIM / 32, DIM / 32), dim3(32, 8)>>>(W, B, Bh, Bl);

    // G1: B2 = B@B -> fp32 B2 + split
    mma_gemm<64,64,32,32,128,2><<<gS, 128, SMEM_CHAIN>>>(Bh, Bl, Bh, Bl, Pt, DIM, DIM, DIM);
    reduce_split<SPLITK,false,true,false><<<rb, 256>>>(Pt, B2, B2h, B2l,
        nullptr, nullptr, 0.f, 0.f, 0.f, nullptr, nullptr, 0.f, 0.f, 0.f, 0.f);

    // G2: B3 = B2@B -> split, AND Q = I/6 + B/24 + B2/120 + B3/720 (comb2, split)
    mma_gemm<64,64,32,32,128,2><<<gS, 128, SMEM_CHAIN>>>(B2h, B2l, Bh, Bl, Pt, DIM, DIM, DIM);
    reduce_split<SPLITK,false,false,true><<<rb, 256>>>(Pt, nullptr, B3h, B3l,
        B, B2, 0.f, 0.f, 0.f, Qh, Ql, 1.f/6.f, 1.f/24.f, 1.f/120.f, 1.f/720.f);

    // G3: R = Q@B3 + I + B + B2/2  -> fp16(256*R)
    mma_gemm<64,64,32,32,128,2><<<gS, 128, SMEM_CHAIN>>>(Qh, Ql, B3h, B3l, Pt, DIM, DIM, DIM);
    reduce_h16_comb<<<rb, 256>>>(Pt, B, B2, Rh16);

    // main: out = x @ R  (fp16 single term, scale undone in epilogue)
    xr_gemm<<<dim3(DIM / 128, M / 128), 256, SMEM_MAIN>>>(x, Rh16, out, M, DIM, DIM);
}